// round 1
// baseline (speedup 1.0000x reference)
#include <cuda_runtime.h>
#include <math.h>
#include <stdint.h>

// ---------------- constants ----------------
#define BATCH   2
#define SEQLEN  4096
#define BL      (BATCH*SEQLEN)          // 8192 rows
#define DM      768
#define DI      1536
#define NH      24
#define HD      64
#define DS      64
#define DCONV   7
#define CONVD   (DI + 2*DS)             // 1664
#define DIP     (2*DI + 2*DS + 2*NH)    // 3248
#define CHUNK_T 256
#define NC      (SEQLEN/CHUNK_T)        // 16
#define NBB     (2*BATCH)               // 4 direction-batches
#define EPSV    1e-5f

// ---------------- scratch (device globals; no allocation allowed) ----------------
__device__ float g_u[(size_t)BL*DM];
__device__ float g_zx[(size_t)BL*DIP];
__device__ float g_xc[(size_t)BL*CONVD];
__device__ float g_dt[(size_t)NBB*SEQLEN*NH];
__device__ float g_acum[(size_t)NBB*NH*NC*CHUNK_T];
__device__ float g_csum[(size_t)NBB*NH*NC];
__device__ float g_states[(size_t)NBB*NC*NH*HD*DS];
__device__ float g_prev[(size_t)NBB*NC*NH*HD*DS];
__device__ float g_yssd[(size_t)NBB*SEQLEN*DI];
__device__ float g_dterm[(size_t)BL*NH];
__device__ float g_yn[(size_t)BL*DI];

// ---------------- helpers ----------------
__device__ __forceinline__ float softplusf(float x){
    return (x > 20.f) ? x : log1pf(expf(x));
}
__device__ __forceinline__ float siluf(float x){
    return x / (1.f + expf(-x));
}

// block reduce (256 threads)
__device__ __forceinline__ float blockReduce256(float v, float* red){
    int tid = threadIdx.x;
    red[tid] = v; __syncthreads();
    #pragma unroll
    for (int o = 128; o > 0; o >>= 1){
        if (tid < o) red[tid] += red[tid + o];
        __syncthreads();
    }
    float r = red[0];
    __syncthreads();
    return r;
}

// ---------------- 1) LayerNorm ----------------
__global__ void ln_kernel(const float* __restrict__ x,
                          const float* __restrict__ w,
                          const float* __restrict__ b){
    __shared__ float red[256];
    int row = blockIdx.x;
    const float* xr = x + (size_t)row*DM;
    int tid = threadIdx.x;
    float s = 0.f;
    for (int i = tid; i < DM; i += 256) s += xr[i];
    float mu = blockReduce256(s, red) / DM;
    float v = 0.f;
    for (int i = tid; i < DM; i += 256){ float d = xr[i]-mu; v += d*d; }
    float var = blockReduce256(v, red) / DM;
    float inv = rsqrtf(var + EPSV);
    for (int i = tid; i < DM; i += 256)
        g_u[(size_t)row*DM + i] = (xr[i]-mu)*inv*w[i] + b[i];
}

// ---------------- generic SGEMM: C[M,N] = A[M,K] @ B[N,K]^T (+R) ----------------
// 128x128 tile, BK=8, 256 threads, 8x8 per thread
__global__ void sgemm_nt(const float* __restrict__ A, int lda,
                         const float* __restrict__ B, int ldb,
                         const float* __restrict__ R,
                         float* __restrict__ C, int ldc,
                         int M, int N, int K){
    __shared__ float As[8][128];
    __shared__ float Bs[8][128];
    const int tid = threadIdx.x;
    const int m0 = blockIdx.y * 128;
    const int n0 = blockIdx.x * 128;
    const int ty = tid >> 4;        // 0..15
    const int tx = tid & 15;        // 0..15
    const int lr = tid >> 1;        // 0..127
    const int lc = (tid & 1) * 4;   // 0 or 4

    float acc[8][8];
    #pragma unroll
    for (int i = 0; i < 8; i++)
        #pragma unroll
        for (int j = 0; j < 8; j++) acc[i][j] = 0.f;

    const float* Aptr = A + (size_t)(m0 + lr)*lda + lc;
    const float* Bptr = B + (size_t)(n0 + lr)*ldb + lc;
    const bool bok = (n0 + lr) < N;

    for (int k0 = 0; k0 < K; k0 += 8){
        float4 av = *(const float4*)(Aptr + k0);
        float4 bv = make_float4(0.f, 0.f, 0.f, 0.f);
        if (bok) bv = *(const float4*)(Bptr + k0);
        As[lc+0][lr] = av.x; As[lc+1][lr] = av.y; As[lc+2][lr] = av.z; As[lc+3][lr] = av.w;
        Bs[lc+0][lr] = bv.x; Bs[lc+1][lr] = bv.y; Bs[lc+2][lr] = bv.z; Bs[lc+3][lr] = bv.w;
        __syncthreads();
        #pragma unroll
        for (int k = 0; k < 8; k++){
            float4 a0 = *(const float4*)&As[k][ty*8];
            float4 a1 = *(const float4*)&As[k][ty*8+4];
            float4 b0 = *(const float4*)&Bs[k][tx*8];
            float4 b1 = *(const float4*)&Bs[k][tx*8+4];
            float a[8] = {a0.x,a0.y,a0.z,a0.w,a1.x,a1.y,a1.z,a1.w};
            float b[8] = {b0.x,b0.y,b0.z,b0.w,b1.x,b1.y,b1.z,b1.w};
            #pragma unroll
            for (int i = 0; i < 8; i++)
                #pragma unroll
                for (int j = 0; j < 8; j++) acc[i][j] += a[i]*b[j];
        }
        __syncthreads();
    }
    #pragma unroll
    for (int i = 0; i < 8; i++){
        int m = m0 + ty*8 + i;
        #pragma unroll
        for (int j = 0; j < 8; j++){
            int n = n0 + tx*8 + j;
            if (n < N){
                float v = acc[i][j];
                if (R) v += R[(size_t)m*ldc + n];
                C[(size_t)m*ldc + n] = v;
            }
        }
    }
}

// ---------------- 3) dt prep (softplus, both directions) ----------------
__global__ void dt_kernel(const float* __restrict__ dt_bias){
    int idx = blockIdx.x*256 + threadIdx.x;
    if (idx >= NBB*SEQLEN*NH) return;
    int h = idx % NH;
    int l = (idx / NH) % SEQLEN;
    int bb = idx / (NH*SEQLEN);
    int b = bb & 1;
    bool rev = bb >= 2;
    int t = rev ? (SEQLEN-1-l) : l;
    int col = (DIP - 2*NH) + (rev ? NH + h : h);
    float v = g_zx[(size_t)(b*SEQLEN + t)*DIP + col] + dt_bias[h];
    g_dt[idx] = softplusf(v);
}

// ---------------- 4) depthwise causal conv + SiLU ----------------
__global__ void conv_kernel(const float* __restrict__ cw,
                            const float* __restrict__ cb){
    int bl = blockIdx.x;             // b*SEQLEN + t
    int t = bl % SEQLEN;
    size_t base = (size_t)(bl - t) * DIP;
    for (int ch = threadIdx.x; ch < CONVD; ch += 256){
        float acc = cb[ch];
        const float* wp = cw + ch*DCONV;
        #pragma unroll
        for (int j = 0; j < DCONV; j++){
            int tt = t - (DCONV-1) + j;
            if (tt >= 0)
                acc += wp[j] * g_zx[base + (size_t)tt*DIP + DI + ch];
        }
        g_xc[(size_t)bl*CONVD + ch] = siluf(acc);
    }
}

// ---------------- 5) per-chunk cumsum of dt*A ----------------
__global__ void cumsum_kernel(const float* __restrict__ A_log){
    int bid = blockIdx.x;            // ((bb*NH)+h)*NC + c
    int c = bid % NC;
    int h = (bid / NC) % NH;
    int bb = bid / (NC*NH);
    int tid = threadIdx.x;           // local l, 0..255
    float a = -expf(A_log[h]);
    int t = c*CHUNK_T + tid;
    float v = g_dt[(size_t)(bb*SEQLEN + t)*NH + h] * a;
    __shared__ float s[CHUNK_T];
    s[tid] = v; __syncthreads();
    for (int off = 1; off < CHUNK_T; off <<= 1){
        float add = (tid >= off) ? s[tid-off] : 0.f;
        __syncthreads();
        s[tid] += add;
        __syncthreads();
    }
    g_acum[(size_t)bid*CHUNK_T + tid] = s[tid];
    if (tid == CHUNK_T-1) g_csum[bid] = s[tid];
}

// ---------------- 6) chunk states: S[p,n] = sum_l Xd[l,p]*Bm[l,n]*decay[l] ----------------
__global__ void states_kernel(){
    int bid = blockIdx.x;            // (bb*NC+c)*NH + h
    int h = bid % NH;
    int c = (bid / NH) % NC;
    int bb = bid / (NH*NC);
    int b = bb & 1;
    bool rev = bb >= 2;
    int tid = threadIdx.x;
    int tp = tid >> 4, tn = tid & 15;

    __shared__ float Xs[64][65];
    __shared__ float Bs[64][65];
    __shared__ float dtl[64], decl[64];

    const float* ac = g_acum + ((size_t)(bb*NH + h)*NC + c)*CHUNK_T;
    float cs = g_csum[(bb*NH + h)*NC + c];

    float acc[4][4];
    #pragma unroll
    for (int i = 0; i < 4; i++)
        #pragma unroll
        for (int j = 0; j < 4; j++) acc[i][j] = 0.f;

    for (int lt = 0; lt < 4; lt++){
        if (tid < 64){
            int lc2 = lt*64 + tid;
            int tgl = c*CHUNK_T + lc2;
            dtl[tid] = g_dt[(size_t)(bb*SEQLEN + tgl)*NH + h];
            decl[tid] = expf(cs - ac[lc2]);
        }
        __syncthreads();
        for (int idx = tid; idx < 64*64; idx += 256){
            int l = idx >> 6, q = idx & 63;
            int tgl = c*CHUNK_T + lt*64 + l;
            int trow = rev ? (SEQLEN-1 - tgl) : tgl;
            size_t roff = (size_t)(b*SEQLEN + trow)*CONVD;
            Xs[l][q] = g_xc[roff + h*HD + q] * dtl[l];
            Bs[l][q] = g_xc[roff + DI + q] * decl[l];
        }
        __syncthreads();
        #pragma unroll
        for (int k = 0; k < 64; k++){
            float a0 = Xs[k][tp*4+0], a1 = Xs[k][tp*4+1], a2 = Xs[k][tp*4+2], a3 = Xs[k][tp*4+3];
            float b0 = Bs[k][tn*4+0], b1 = Bs[k][tn*4+1], b2 = Bs[k][tn*4+2], b3 = Bs[k][tn*4+3];
            acc[0][0]+=a0*b0; acc[0][1]+=a0*b1; acc[0][2]+=a0*b2; acc[0][3]+=a0*b3;
            acc[1][0]+=a1*b0; acc[1][1]+=a1*b1; acc[1][2]+=a1*b2; acc[1][3]+=a1*b3;
            acc[2][0]+=a2*b0; acc[2][1]+=a2*b1; acc[2][2]+=a2*b2; acc[2][3]+=a2*b3;
            acc[3][0]+=a3*b0; acc[3][1]+=a3*b1; acc[3][2]+=a3*b2; acc[3][3]+=a3*b3;
        }
        __syncthreads();
    }
    float* sp = g_states + (size_t)bid*(HD*DS);
    #pragma unroll
    for (int i = 0; i < 4; i++)
        #pragma unroll
        for (int j = 0; j < 4; j++)
            sp[(tp*4+i)*DS + tn*4+j] = acc[i][j];
}

// ---------------- 7) inter-chunk scan ----------------
__global__ void prevscan_kernel(){
    int bh = blockIdx.x;             // bb*NH + h
    int bb = bh / NH, h = bh % NH;
    int tid = threadIdx.x;
    float run[16];
    #pragma unroll
    for (int k = 0; k < 16; k++) run[k] = 0.f;
    for (int c = 0; c < NC; c++){
        size_t off = ((size_t)(bb*NC + c)*NH + h)*(HD*DS);
        float e = expf(g_csum[bh*NC + c]);
        #pragma unroll
        for (int k = 0; k < 16; k++){
            int idx = k*256 + tid;
            g_prev[off + idx] = run[k];
            run[k] = run[k]*e + g_states[off + idx];
        }
    }
}

// ---------------- 8) Y = Y_diag + Y_off per (bb,c,h,ltile) ----------------
__global__ void ydiag_kernel(){
    int bid = blockIdx.x;            // ((bb*NC+c)*NH+h)*4 + lt
    int lt = bid & 3;
    int h  = (bid >> 2) % NH;
    int c  = (bid / (4*NH)) % NC;
    int bb = bid / (4*NH*NC);
    int b = bb & 1;
    bool rev = bb >= 2;
    int tid = threadIdx.x;
    int tl = tid >> 4, tp = tid & 15;

    __shared__ float Abuf[64][65];
    __shared__ float Bbuf[64][65];
    __shared__ float acl[64], acs[64], eacl[64];

    const float* ac = g_acum + ((size_t)(bb*NH + h)*NC + c)*CHUNK_T;

    if (tid < 64){
        float v = ac[lt*64 + tid];
        acl[tid] = v;
        eacl[tid] = expf(v);
    }
    __syncthreads();

    float acc[4][4];
    #pragma unroll
    for (int i = 0; i < 4; i++)
        #pragma unroll
        for (int j = 0; j < 4; j++) acc[i][j] = 0.f;

    // --- Y_off:  acc[l,p] += sum_n (Cm[l,n]*exp(acl[l])) * prev[p,n]
    {
        size_t poff = ((size_t)(bb*NC + c)*NH + h)*(HD*DS);
        for (int idx = tid; idx < 64*64; idx += 256){
            int l = idx >> 6, n = idx & 63;
            int tgl = c*CHUNK_T + lt*64 + l;
            int trow = rev ? (SEQLEN-1 - tgl) : tgl;
            Abuf[l][n] = g_xc[(size_t)(b*SEQLEN + trow)*CONVD + DI + DS + n] * eacl[l];
            Bbuf[l][n] = g_prev[poff + idx];     // l plays role of p here
        }
        __syncthreads();
        #pragma unroll
        for (int k = 0; k < 64; k++){
            float a0 = Abuf[tl*4+0][k], a1 = Abuf[tl*4+1][k], a2 = Abuf[tl*4+2][k], a3 = Abuf[tl*4+3][k];
            float b0 = Bbuf[tp*4+0][k], b1 = Bbuf[tp*4+1][k], b2 = Bbuf[tp*4+2][k], b3 = Bbuf[tp*4+3][k];
            acc[0][0]+=a0*b0; acc[0][1]+=a0*b1; acc[0][2]+=a0*b2; acc[0][3]+=a0*b3;
            acc[1][0]+=a1*b0; acc[1][1]+=a1*b1; acc[1][2]+=a1*b2; acc[1][3]+=a1*b3;
            acc[2][0]+=a2*b0; acc[2][1]+=a2*b1; acc[2][2]+=a2*b2; acc[2][3]+=a2*b3;
            acc[3][0]+=a3*b0; acc[3][1]+=a3*b1; acc[3][2]+=a3*b2; acc[3][3]+=a3*b3;
        }
        __syncthreads();
    }

    // --- Y_diag over s-tiles <= lt
    for (int st = 0; st <= lt; st++){
        if (tid < 64) acs[tid] = ac[st*64 + tid];
        // load Cm tile (rows of l-tile) and Bm tile (rows of s-tile)
        for (int idx = tid; idx < 64*64; idx += 256){
            int r = idx >> 6, n = idx & 63;
            int tgl = c*CHUNK_T + lt*64 + r;
            int trl = rev ? (SEQLEN-1 - tgl) : tgl;
            Abuf[r][n] = g_xc[(size_t)(b*SEQLEN + trl)*CONVD + DI + DS + n];
            int tgs = c*CHUNK_T + st*64 + r;
            int trs = rev ? (SEQLEN-1 - tgs) : tgs;
            Bbuf[r][n] = g_xc[(size_t)(b*SEQLEN + trs)*CONVD + DI + n];
        }
        __syncthreads();
        // G[l,s] = sum_n C[l,n]*B[s,n]
        float g[4][4];
        #pragma unroll
        for (int i = 0; i < 4; i++)
            #pragma unroll
            for (int j = 0; j < 4; j++) g[i][j] = 0.f;
        #pragma unroll
        for (int k = 0; k < 64; k++){
            float a0 = Abuf[tl*4+0][k], a1 = Abuf[tl*4+1][k], a2 = Abuf[tl*4+2][k], a3 = Abuf[tl*4+3][k];
            float b0 = Bbuf[tp*4+0][k], b1 = Bbuf[tp*4+1][k], b2 = Bbuf[tp*4+2][k], b3 = Bbuf[tp*4+3][k];
            g[0][0]+=a0*b0; g[0][1]+=a0*b1; g[0][2]+=a0*b2; g[0][3]+=a0*b3;
            g[1][0]+=a1*b0; g[1][1]+=a1*b1; g[1][2]+=a1*b2; g[1][3]+=a1*b3;
            g[2][0]+=a2*b0; g[2][1]+=a2*b1; g[2][2]+=a2*b2; g[2][3]+=a2*b3;
            g[3][0]+=a3*b0; g[3][1]+=a3*b1; g[3][2]+=a3*b2; g[3][3]+=a3*b3;
        }
        __syncthreads();
        // masked/decayed G -> Abuf
        #pragma unroll
        for (int i = 0; i < 4; i++){
            int l = tl*4 + i;
            #pragma unroll
            for (int j = 0; j < 4; j++){
                int s = tp*4 + j;
                float w;
                if (st == lt && s > l) w = 0.f;
                else w = expf(acl[l] - acs[s]);
                Abuf[l][s] = g[i][j] * w;
            }
        }
        __syncthreads();
        // Xd tile -> Bbuf[s][p]
        for (int idx = tid; idx < 64*64; idx += 256){
            int s = idx >> 6, p = idx & 63;
            int tgs = c*CHUNK_T + st*64 + s;
            int trs = rev ? (SEQLEN-1 - tgs) : tgs;
            float dtv = g_dt[(size_t)(bb*SEQLEN + tgs)*NH + h];
            Bbuf[s][p] = g_xc[(size_t)(b*SEQLEN + trs)*CONVD + h*HD + p] * dtv;
        }
        __syncthreads();
        // acc[l,p] += sum_s GW[l,s]*Xd[s,p]
        #pragma unroll
        for (int k = 0; k < 64; k++){
            float a0 = Abuf[tl*4+0][k], a1 = Abuf[tl*4+1][k], a2 = Abuf[tl*4+2][k], a3 = Abuf[tl*4+3][k];
            float b0 = Bbuf[k][tp*4+0], b1 = Bbuf[k][tp*4+1], b2 = Bbuf[k][tp*4+2], b3 = Bbuf[k][tp*4+3];
            acc[0][0]+=a0*b0; acc[0][1]+=a0*b1; acc[0][2]+=a0*b2; acc[0][3]+=a0*b3;
            acc[1][0]+=a1*b0; acc[1][1]+=a1*b1; acc[1][2]+=a1*b2; acc[1][3]+=a1*b3;
            acc[2][0]+=a2*b0; acc[2][1]+=a2*b1; acc[2][2]+=a2*b2; acc[2][3]+=a2*b3;
            acc[3][0]+=a3*b0; acc[3][1]+=a3*b1; acc[3][2]+=a3*b2; acc[3][3]+=a3*b3;
        }
        __syncthreads();
    }

    // store
    #pragma unroll
    for (int i = 0; i < 4; i++){
        int tgl = c*CHUNK_T + lt*64 + tl*4 + i;
        #pragma unroll
        for (int j = 0; j < 4; j++){
            g_yssd[(size_t)(bb*SEQLEN + tgl)*DI + h*HD + tp*4 + j] = acc[i][j];
        }
    }
}

// ---------------- 9) combine dirs + skip + gate + RMSNorm ----------------
__global__ void combine_kernel(const float* __restrict__ Dv,
                               const float* __restrict__ rms_w){
    __shared__ float ybuf[DI];
    __shared__ float red[256];
    int bl = blockIdx.x;
    int b = bl / SEQLEN, t = bl % SEQLEN;
    int tid = threadIdx.x;
    float ss = 0.f;
    for (int d = tid; d < DI; d += 256){
        float yf = (t > 0) ? g_yssd[(size_t)(b*SEQLEN + t - 1)*DI + d] : 0.f;
        float yb = (t <= SEQLEN-2) ? g_yssd[(size_t)((2+b)*SEQLEN + (SEQLEN-2 - t))*DI + d] : 0.f;
        float xo = g_xc[(size_t)bl*CONVD + d];
        int h = d >> 6;
        float dterm = g_dterm[(size_t)bl*NH + h] + Dv[h];
        float z = g_zx[(size_t)bl*DIP + d];
        float y = (yf + yb + xo*dterm) * siluf(z);
        ybuf[d] = y;
        ss += y*y;
    }
    float tot = blockReduce256(ss, red);
    float inv = rsqrtf(tot/DI + EPSV);
    for (int d = tid; d < DI; d += 256)
        g_yn[(size_t)bl*DI + d] = ybuf[d]*inv*rms_w[d];
}

// ---------------- launch ----------------
extern "C" void kernel_launch(void* const* d_in, const int* in_sizes, int n_in,
                              void* d_out, int out_size){
    const float* x          = (const float*)d_in[0];
    const float* ln_w       = (const float*)d_in[1];
    const float* ln_b       = (const float*)d_in[2];
    const float* in_proj_w  = (const float*)d_in[3];
    const float* conv_w     = (const float*)d_in[4];
    const float* conv_b     = (const float*)d_in[5];
    const float* dt_bias    = (const float*)d_in[6];
    const float* A_log      = (const float*)d_in[7];
    const float* Dv         = (const float*)d_in[8];
    const float* fc_D_w     = (const float*)d_in[9];
    const float* rms_w      = (const float*)d_in[10];
    const float* out_proj_w = (const float*)d_in[11];
    float* out = (float*)d_out;

    float *u, *zx, *xc, *dterm, *yn;
    cudaGetSymbolAddress((void**)&u,     g_u);
    cudaGetSymbolAddress((void**)&zx,    g_zx);
    cudaGetSymbolAddress((void**)&xc,    g_xc);
    cudaGetSymbolAddress((void**)&dterm, g_dterm);
    cudaGetSymbolAddress((void**)&yn,    g_yn);

    // 1) LayerNorm
    ln_kernel<<<BL, 256>>>(x, ln_w, ln_b);

    // 2) in_proj: (8192x768) @ (3248x768)^T -> (8192x3248)
    sgemm_nt<<<dim3((DIP+127)/128, BL/128), 256>>>(u, DM, in_proj_w, DM, nullptr, zx, DIP, BL, DIP, DM);

    // 3) dt softplus (both directions)
    dt_kernel<<<(NBB*SEQLEN*NH + 255)/256, 256>>>(dt_bias);

    // 4) depthwise causal conv + SiLU
    conv_kernel<<<BL, 256>>>(conv_w, conv_b);

    // 5) per-chunk cumsum of dt*A
    cumsum_kernel<<<NBB*NH*NC, 256>>>(A_log);

    // 6) chunk states
    states_kernel<<<NBB*NC*NH, 256>>>();

    // 7) inter-chunk scan
    prevscan_kernel<<<NBB*NH, 256>>>();

    // 8) intra-chunk Y + carry-in
    ydiag_kernel<<<NBB*NC*NH*4, 256>>>();

    // 9) fc_D: (8192x1536 view of xc) @ (24x1536)^T -> (8192x24)
    sgemm_nt<<<dim3(1, BL/128), 256>>>(xc, CONVD, fc_D_w, DI, nullptr, dterm, NH, BL, NH, DI);

    // 10) combine + gate + RMSNorm
    combine_kernel<<<BL, 256>>>(Dv, rms_w);

    // 11) out_proj + residual: (8192x1536) @ (768x1536)^T + x -> out
    sgemm_nt<<<dim3(DM/128, BL/128), 256>>>(yn, DI, out_proj_w, DI, x, out, DM, BL, DM, DI);
}

// round 2
// speedup vs baseline: 1.6532x; 1.6532x over previous
#include <cuda_runtime.h>
#include <math.h>
#include <stdint.h>

// ---------------- constants ----------------
#define BATCH   2
#define SEQLEN  4096
#define BL      (BATCH*SEQLEN)          // 8192 rows
#define DM      768
#define DI      1536
#define NH      24
#define HD      64
#define DS      64
#define DCONV   7
#define CONVD   (DI + 2*DS)             // 1664
#define DIP     (2*DI + 2*DS + 2*NH)    // 3248
#define CHUNK_T 256
#define NC      (SEQLEN/CHUNK_T)        // 16
#define NBB     (2*BATCH)               // 4 direction-batches
#define EPSV    1e-5f

// ---------------- scratch (device globals; no allocation allowed) ----------------
__device__ float g_u[(size_t)BL*DM];
__device__ float g_zx[(size_t)BL*DIP];
__device__ float g_xc[(size_t)BL*CONVD];
__device__ float g_dt[(size_t)NBB*SEQLEN*NH];
__device__ float g_acum[(size_t)NBB*NH*NC*CHUNK_T];
__device__ float g_csum[(size_t)NBB*NH*NC];
__device__ float g_states[(size_t)NBB*NC*NH*HD*DS];
__device__ float g_prev[(size_t)NBB*NC*NH*HD*DS];
__device__ float g_yssd[(size_t)NBB*SEQLEN*DI];
__device__ float g_dterm[(size_t)BL*NH];
__device__ float g_yn[(size_t)BL*DI];

// ---------------- helpers ----------------
__device__ __forceinline__ float softplusf(float x){
    return (x > 20.f) ? x : log1pf(expf(x));
}
__device__ __forceinline__ float siluf(float x){
    return x / (1.f + expf(-x));
}
__device__ __forceinline__ float f2tf32(float f){
    unsigned r; asm("cvt.rna.tf32.f32 %0, %1;" : "=r"(r) : "f"(f));
    return __uint_as_float(r);
}

// block reduce (256 threads)
__device__ __forceinline__ float blockReduce256(float v, float* red){
    int tid = threadIdx.x;
    red[tid] = v; __syncthreads();
    #pragma unroll
    for (int o = 128; o > 0; o >>= 1){
        if (tid < o) red[tid] += red[tid + o];
        __syncthreads();
    }
    float r = red[0];
    __syncthreads();
    return r;
}

// ---------------- 1) LayerNorm ----------------
__global__ void ln_kernel(const float* __restrict__ x,
                          const float* __restrict__ w,
                          const float* __restrict__ b){
    __shared__ float red[256];
    int row = blockIdx.x;
    const float* xr = x + (size_t)row*DM;
    int tid = threadIdx.x;
    float s = 0.f;
    for (int i = tid; i < DM; i += 256) s += xr[i];
    float mu = blockReduce256(s, red) / DM;
    float v = 0.f;
    for (int i = tid; i < DM; i += 256){ float d = xr[i]-mu; v += d*d; }
    float var = blockReduce256(v, red) / DM;
    float inv = rsqrtf(var + EPSV);
    for (int i = tid; i < DM; i += 256)
        g_u[(size_t)row*DM + i] = (xr[i]-mu)*inv*w[i] + b[i];
}

// ---------------- TF32 tensor-core GEMM: C[M,N] = A[M,K] @ B[N,K]^T (+R) ----------
// 128x128 tile, BK=16, 256 threads (8 warps, 2x4), warp tile 64x32 (4x4 m16n8k8)
#define SMS 20   // smem row stride (floats) — conflict-free for fragment reads
__global__ void gemm_tf32(const float* __restrict__ A, int lda,
                          const float* __restrict__ B, int ldb,
                          const float* __restrict__ R,
                          float* __restrict__ C, int ldc,
                          int M, int N, int K){
    __shared__ float As[128*SMS];
    __shared__ float Bs[128*SMS];
    const int tid  = threadIdx.x;
    const int lane = tid & 31;
    const int warp = tid >> 5;
    const int wm = warp >> 2;       // 0..1
    const int wn = warp & 3;        // 0..3
    const int m0 = blockIdx.y * 128;
    const int n0 = blockIdx.x * 128;
    const int grow = tid >> 2;      // 0..63
    const int gq   = tid & 3;       // 0..3

    const float* Ap0 = A + (size_t)(m0 + grow)*lda + gq*4;
    const float* Ap1 = Ap0 + (size_t)64*lda;
    const int br0 = n0 + grow, br1 = br0 + 64;
    const float* Bp0 = B + (size_t)br0*ldb + gq*4;
    const float* Bp1 = Bp0 + (size_t)64*ldb;
    const bool bok0 = br0 < N, bok1 = br1 < N;

    float acc[4][4][4];
    #pragma unroll
    for (int i=0;i<4;i++)
        #pragma unroll
        for (int j=0;j<4;j++)
            #pragma unroll
            for (int r=0;r<4;r++) acc[i][j][r]=0.f;

    float4 ra0, ra1, rb0, rb1;
    ra0 = *(const float4*)(Ap0);
    ra1 = *(const float4*)(Ap1);
    rb0 = bok0 ? *(const float4*)(Bp0) : make_float4(0.f,0.f,0.f,0.f);
    rb1 = bok1 ? *(const float4*)(Bp1) : make_float4(0.f,0.f,0.f,0.f);

    const int nk = K >> 4;
    for (int kt = 0; kt < nk; kt++){
        float* as0 = &As[grow*SMS + gq*4];
        as0[0]=f2tf32(ra0.x); as0[1]=f2tf32(ra0.y); as0[2]=f2tf32(ra0.z); as0[3]=f2tf32(ra0.w);
        float* as1 = &As[(grow+64)*SMS + gq*4];
        as1[0]=f2tf32(ra1.x); as1[1]=f2tf32(ra1.y); as1[2]=f2tf32(ra1.z); as1[3]=f2tf32(ra1.w);
        float* bs0 = &Bs[grow*SMS + gq*4];
        bs0[0]=f2tf32(rb0.x); bs0[1]=f2tf32(rb0.y); bs0[2]=f2tf32(rb0.z); bs0[3]=f2tf32(rb0.w);
        float* bs1 = &Bs[(grow+64)*SMS + gq*4];
        bs1[0]=f2tf32(rb1.x); bs1[1]=f2tf32(rb1.y); bs1[2]=f2tf32(rb1.z); bs1[3]=f2tf32(rb1.w);
        __syncthreads();

        if (kt+1 < nk){
            int ko = (kt+1) << 4;
            ra0 = *(const float4*)(Ap0 + ko);
            ra1 = *(const float4*)(Ap1 + ko);
            rb0 = bok0 ? *(const float4*)(Bp0 + ko) : make_float4(0.f,0.f,0.f,0.f);
            rb1 = bok1 ? *(const float4*)(Bp1 + ko) : make_float4(0.f,0.f,0.f,0.f);
        }

        #pragma unroll
        for (int ks = 0; ks < 16; ks += 8){
            const int kb = ks + (lane & 3);
            unsigned a[4][4], bfr[4][2];
            #pragma unroll
            for (int i=0;i<4;i++){
                int r = wm*64 + i*16 + (lane>>2);
                a[i][0] = __float_as_uint(As[r*SMS + kb]);
                a[i][1] = __float_as_uint(As[(r+8)*SMS + kb]);
                a[i][2] = __float_as_uint(As[r*SMS + kb + 4]);
                a[i][3] = __float_as_uint(As[(r+8)*SMS + kb + 4]);
            }
            #pragma unroll
            for (int j=0;j<4;j++){
                int cb = wn*32 + j*8 + (lane>>2);
                bfr[j][0] = __float_as_uint(Bs[cb*SMS + kb]);
                bfr[j][1] = __float_as_uint(Bs[cb*SMS + kb + 4]);
            }
            #pragma unroll
            for (int i=0;i<4;i++)
                #pragma unroll
                for (int j=0;j<4;j++){
                    asm volatile("mma.sync.aligned.m16n8k8.row.col.f32.tf32.tf32.f32 "
                        "{%0,%1,%2,%3},{%4,%5,%6,%7},{%8,%9},{%0,%1,%2,%3};"
                        : "+f"(acc[i][j][0]),"+f"(acc[i][j][1]),
                          "+f"(acc[i][j][2]),"+f"(acc[i][j][3])
                        : "r"(a[i][0]),"r"(a[i][1]),"r"(a[i][2]),"r"(a[i][3]),
                          "r"(bfr[j][0]),"r"(bfr[j][1]));
                }
        }
        __syncthreads();
    }

    #pragma unroll
    for (int i=0;i<4;i++){
        int r0 = m0 + wm*64 + i*16 + (lane>>2);
        #pragma unroll
        for (int j=0;j<4;j++){
            int cb = n0 + wn*32 + j*8;
            if (cb < N){
                int cc = cb + 2*(lane & 3);
                size_t o0 = (size_t)r0*ldc + cc;
                size_t o1 = (size_t)(r0+8)*ldc + cc;
                float v0 = acc[i][j][0], v1 = acc[i][j][1];
                float v2 = acc[i][j][2], v3 = acc[i][j][3];
                if (R){ v0 += R[o0]; v1 += R[o0+1]; v2 += R[o1]; v3 += R[o1+1]; }
                C[o0] = v0; C[o0+1] = v1; C[o1] = v2; C[o1+1] = v3;
            }
        }
    }
}

// ---------------- 3) dt prep (softplus, both directions) ----------------
__global__ void dt_kernel(const float* __restrict__ dt_bias){
    int idx = blockIdx.x*256 + threadIdx.x;
    if (idx >= NBB*SEQLEN*NH) return;
    int h = idx % NH;
    int l = (idx / NH) % SEQLEN;
    int bb = idx / (NH*SEQLEN);
    int b = bb & 1;
    bool rev = bb >= 2;
    int t = rev ? (SEQLEN-1-l) : l;
    int col = (DIP - 2*NH) + (rev ? NH + h : h);
    float v = g_zx[(size_t)(b*SEQLEN + t)*DIP + col] + dt_bias[h];
    g_dt[idx] = softplusf(v);
}

// ---------------- 4) depthwise causal conv + SiLU ----------------
__global__ void conv_kernel(const float* __restrict__ cw,
                            const float* __restrict__ cb){
    int bl = blockIdx.x;             // b*SEQLEN + t
    int t = bl % SEQLEN;
    size_t base = (size_t)(bl - t) * DIP;
    for (int ch = threadIdx.x; ch < CONVD; ch += 256){
        float acc = cb[ch];
        const float* wp = cw + ch*DCONV;
        #pragma unroll
        for (int j = 0; j < DCONV; j++){
            int tt = t - (DCONV-1) + j;
            if (tt >= 0)
                acc += wp[j] * g_zx[base + (size_t)tt*DIP + DI + ch];
        }
        g_xc[(size_t)bl*CONVD + ch] = siluf(acc);
    }
}

// ---------------- 5) per-chunk cumsum of dt*A ----------------
__global__ void cumsum_kernel(const float* __restrict__ A_log){
    int bid = blockIdx.x;            // ((bb*NH)+h)*NC + c
    int c = bid % NC;
    int h = (bid / NC) % NH;
    int bb = bid / (NC*NH);
    int tid = threadIdx.x;           // local l, 0..255
    float a = -expf(A_log[h]);
    int t = c*CHUNK_T + tid;
    float v = g_dt[(size_t)(bb*SEQLEN + t)*NH + h] * a;
    __shared__ float s[CHUNK_T];
    s[tid] = v; __syncthreads();
    for (int off = 1; off < CHUNK_T; off <<= 1){
        float add = (tid >= off) ? s[tid-off] : 0.f;
        __syncthreads();
        s[tid] += add;
        __syncthreads();
    }
    g_acum[(size_t)bid*CHUNK_T + tid] = s[tid];
    if (tid == CHUNK_T-1) g_csum[bid] = s[tid];
}

// ---------------- 6) chunk states: S[p,n] = sum_l Xd[l,p]*Bm[l,n]*decay[l] ----------------
__global__ void states_kernel(){
    int bid = blockIdx.x;            // (bb*NC+c)*NH + h
    int h = bid % NH;
    int c = (bid / NH) % NC;
    int bb = bid / (NH*NC);
    int b = bb & 1;
    bool rev = bb >= 2;
    int tid = threadIdx.x;
    int tp = tid >> 4, tn = tid & 15;

    __shared__ float Xs[64][65];
    __shared__ float Bs[64][65];
    __shared__ float dtl[64], decl[64];

    const float* ac = g_acum + ((size_t)(bb*NH + h)*NC + c)*CHUNK_T;
    float cs = g_csum[(bb*NH + h)*NC + c];

    float acc[4][4];
    #pragma unroll
    for (int i = 0; i < 4; i++)
        #pragma unroll
        for (int j = 0; j < 4; j++) acc[i][j] = 0.f;

    for (int lt = 0; lt < 4; lt++){
        if (tid < 64){
            int lc2 = lt*64 + tid;
            int tgl = c*CHUNK_T + lc2;
            dtl[tid] = g_dt[(size_t)(bb*SEQLEN + tgl)*NH + h];
            decl[tid] = expf(cs - ac[lc2]);
        }
        __syncthreads();
        for (int idx = tid; idx < 64*64; idx += 256){
            int l = idx >> 6, q = idx & 63;
            int tgl = c*CHUNK_T + lt*64 + l;
            int trow = rev ? (SEQLEN-1 - tgl) : tgl;
            size_t roff = (size_t)(b*SEQLEN + trow)*CONVD;
            Xs[l][q] = g_xc[roff + h*HD + q] * dtl[l];
            Bs[l][q] = g_xc[roff + DI + q] * decl[l];
        }
        __syncthreads();
        #pragma unroll
        for (int k = 0; k < 64; k++){
            float a0 = Xs[k][tp*4+0], a1 = Xs[k][tp*4+1], a2 = Xs[k][tp*4+2], a3 = Xs[k][tp*4+3];
            float b0 = Bs[k][tn*4+0], b1 = Bs[k][tn*4+1], b2 = Bs[k][tn*4+2], b3 = Bs[k][tn*4+3];
            acc[0][0]+=a0*b0; acc[0][1]+=a0*b1; acc[0][2]+=a0*b2; acc[0][3]+=a0*b3;
            acc[1][0]+=a1*b0; acc[1][1]+=a1*b1; acc[1][2]+=a1*b2; acc[1][3]+=a1*b3;
            acc[2][0]+=a2*b0; acc[2][1]+=a2*b1; acc[2][2]+=a2*b2; acc[2][3]+=a2*b3;
            acc[3][0]+=a3*b0; acc[3][1]+=a3*b1; acc[3][2]+=a3*b2; acc[3][3]+=a3*b3;
        }
        __syncthreads();
    }
    float* sp = g_states + (size_t)bid*(HD*DS);
    #pragma unroll
    for (int i = 0; i < 4; i++)
        #pragma unroll
        for (int j = 0; j < 4; j++)
            sp[(tp*4+i)*DS + tn*4+j] = acc[i][j];
}

// ---------------- 7) inter-chunk scan ----------------
__global__ void prevscan_kernel(){
    int bh = blockIdx.x;             // bb*NH + h
    int bb = bh / NH, h = bh % NH;
    int tid = threadIdx.x;
    float run[16];
    #pragma unroll
    for (int k = 0; k < 16; k++) run[k] = 0.f;
    for (int c = 0; c < NC; c++){
        size_t off = ((size_t)(bb*NC + c)*NH + h)*(HD*DS);
        float e = expf(g_csum[bh*NC + c]);
        #pragma unroll
        for (int k = 0; k < 16; k++){
            int idx = k*256 + tid;
            g_prev[off + idx] = run[k];
            run[k] = run[k]*e + g_states[off + idx];
        }
    }
}

// ---------------- 8) Y = Y_diag + Y_off per (bb,c,h,ltile) ----------------
__global__ void ydiag_kernel(){
    int bid = blockIdx.x;            // ((bb*NC+c)*NH+h)*4 + lt
    int lt = bid & 3;
    int h  = (bid >> 2) % NH;
    int c  = (bid / (4*NH)) % NC;
    int bb = bid / (4*NH*NC);
    int b = bb & 1;
    bool rev = bb >= 2;
    int tid = threadIdx.x;
    int tl = tid >> 4, tp = tid & 15;

    __shared__ float Abuf[64][65];
    __shared__ float Bbuf[64][65];
    __shared__ float acl[64], acs[64], eacl[64];

    const float* ac = g_acum + ((size_t)(bb*NH + h)*NC + c)*CHUNK_T;

    if (tid < 64){
        float v = ac[lt*64 + tid];
        acl[tid] = v;
        eacl[tid] = expf(v);
    }
    __syncthreads();

    float acc[4][4];
    #pragma unroll
    for (int i = 0; i < 4; i++)
        #pragma unroll
        for (int j = 0; j < 4; j++) acc[i][j] = 0.f;

    // --- Y_off:  acc[l,p] += sum_n (Cm[l,n]*exp(acl[l])) * prev[p,n]
    {
        size_t poff = ((size_t)(bb*NC + c)*NH + h)*(HD*DS);
        for (int idx = tid; idx < 64*64; idx += 256){
            int l = idx >> 6, n = idx & 63;
            int tgl = c*CHUNK_T + lt*64 + l;
            int trow = rev ? (SEQLEN-1 - tgl) : tgl;
            Abuf[l][n] = g_xc[(size_t)(b*SEQLEN + trow)*CONVD + DI + DS + n] * eacl[l];
            Bbuf[l][n] = g_prev[poff + idx];     // l plays role of p here
        }
        __syncthreads();
        #pragma unroll
        for (int k = 0; k < 64; k++){
            float a0 = Abuf[tl*4+0][k], a1 = Abuf[tl*4+1][k], a2 = Abuf[tl*4+2][k], a3 = Abuf[tl*4+3][k];
            float b0 = Bbuf[tp*4+0][k], b1 = Bbuf[tp*4+1][k], b2 = Bbuf[tp*4+2][k], b3 = Bbuf[tp*4+3][k];
            acc[0][0]+=a0*b0; acc[0][1]+=a0*b1; acc[0][2]+=a0*b2; acc[0][3]+=a0*b3;
            acc[1][0]+=a1*b0; acc[1][1]+=a1*b1; acc[1][2]+=a1*b2; acc[1][3]+=a1*b3;
            acc[2][0]+=a2*b0; acc[2][1]+=a2*b1; acc[2][2]+=a2*b2; acc[2][3]+=a2*b3;
            acc[3][0]+=a3*b0; acc[3][1]+=a3*b1; acc[3][2]+=a3*b2; acc[3][3]+=a3*b3;
        }
        __syncthreads();
    }

    // --- Y_diag over s-tiles <= lt
    for (int st = 0; st <= lt; st++){
        if (tid < 64) acs[tid] = ac[st*64 + tid];
        for (int idx = tid; idx < 64*64; idx += 256){
            int r = idx >> 6, n = idx & 63;
            int tgl = c*CHUNK_T + lt*64 + r;
            int trl = rev ? (SEQLEN-1 - tgl) : tgl;
            Abuf[r][n] = g_xc[(size_t)(b*SEQLEN + trl)*CONVD + DI + DS + n];
            int tgs = c*CHUNK_T + st*64 + r;
            int trs = rev ? (SEQLEN-1 - tgs) : tgs;
            Bbuf[r][n] = g_xc[(size_t)(b*SEQLEN + trs)*CONVD + DI + n];
        }
        __syncthreads();
        float g[4][4];
        #pragma unroll
        for (int i = 0; i < 4; i++)
            #pragma unroll
            for (int j = 0; j < 4; j++) g[i][j] = 0.f;
        #pragma unroll
        for (int k = 0; k < 64; k++){
            float a0 = Abuf[tl*4+0][k], a1 = Abuf[tl*4+1][k], a2 = Abuf[tl*4+2][k], a3 = Abuf[tl*4+3][k];
            float b0 = Bbuf[tp*4+0][k], b1 = Bbuf[tp*4+1][k], b2 = Bbuf[tp*4+2][k], b3 = Bbuf[tp*4+3][k];
            g[0][0]+=a0*b0; g[0][1]+=a0*b1; g[0][2]+=a0*b2; g[0][3]+=a0*b3;
            g[1][0]+=a1*b0; g[1][1]+=a1*b1; g[1][2]+=a1*b2; g[1][3]+=a1*b3;
            g[2][0]+=a2*b0; g[2][1]+=a2*b1; g[2][2]+=a2*b2; g[2][3]+=a2*b3;
            g[3][0]+=a3*b0; g[3][1]+=a3*b1; g[3][2]+=a3*b2; g[3][3]+=a3*b3;
        }
        __syncthreads();
        #pragma unroll
        for (int i = 0; i < 4; i++){
            int l = tl*4 + i;
            #pragma unroll
            for (int j = 0; j < 4; j++){
                int s = tp*4 + j;
                float w;
                if (st == lt && s > l) w = 0.f;
                else w = expf(acl[l] - acs[s]);
                Abuf[l][s] = g[i][j] * w;
            }
        }
        __syncthreads();
        for (int idx = tid; idx < 64*64; idx += 256){
            int s = idx >> 6, p = idx & 63;
            int tgs = c*CHUNK_T + st*64 + s;
            int trs = rev ? (SEQLEN-1 - tgs) : tgs;
            float dtv = g_dt[(size_t)(bb*SEQLEN + tgs)*NH + h];
            Bbuf[s][p] = g_xc[(size_t)(b*SEQLEN + trs)*CONVD + h*HD + p] * dtv;
        }
        __syncthreads();
        #pragma unroll
        for (int k = 0; k < 64; k++){
            float a0 = Abuf[tl*4+0][k], a1 = Abuf[tl*4+1][k], a2 = Abuf[tl*4+2][k], a3 = Abuf[tl*4+3][k];
            float b0 = Bbuf[k][tp*4+0], b1 = Bbuf[k][tp*4+1], b2 = Bbuf[k][tp*4+2], b3 = Bbuf[k][tp*4+3];
            acc[0][0]+=a0*b0; acc[0][1]+=a0*b1; acc[0][2]+=a0*b2; acc[0][3]+=a0*b3;
            acc[1][0]+=a1*b0; acc[1][1]+=a1*b1; acc[1][2]+=a1*b2; acc[1][3]+=a1*b3;
            acc[2][0]+=a2*b0; acc[2][1]+=a2*b1; acc[2][2]+=a2*b2; acc[2][3]+=a2*b3;
            acc[3][0]+=a3*b0; acc[3][1]+=a3*b1; acc[3][2]+=a3*b2; acc[3][3]+=a3*b3;
        }
        __syncthreads();
    }

    #pragma unroll
    for (int i = 0; i < 4; i++){
        int tgl = c*CHUNK_T + lt*64 + tl*4 + i;
        #pragma unroll
        for (int j = 0; j < 4; j++){
            g_yssd[(size_t)(bb*SEQLEN + tgl)*DI + h*HD + tp*4 + j] = acc[i][j];
        }
    }
}

// ---------------- 9) combine dirs + skip + gate + RMSNorm ----------------
__global__ void combine_kernel(const float* __restrict__ Dv,
                               const float* __restrict__ rms_w){
    __shared__ float ybuf[DI];
    __shared__ float red[256];
    int bl = blockIdx.x;
    int b = bl / SEQLEN, t = bl % SEQLEN;
    int tid = threadIdx.x;
    float ss = 0.f;
    for (int d = tid; d < DI; d += 256){
        float yf = (t > 0) ? g_yssd[(size_t)(b*SEQLEN + t - 1)*DI + d] : 0.f;
        float yb = (t <= SEQLEN-2) ? g_yssd[(size_t)((2+b)*SEQLEN + (SEQLEN-2 - t))*DI + d] : 0.f;
        float xo = g_xc[(size_t)bl*CONVD + d];
        int h = d >> 6;
        float dterm = g_dterm[(size_t)bl*NH + h] + Dv[h];
        float z = g_zx[(size_t)bl*DIP + d];
        float y = (yf + yb + xo*dterm) * siluf(z);
        ybuf[d] = y;
        ss += y*y;
    }
    float tot = blockReduce256(ss, red);
    float inv = rsqrtf(tot/DI + EPSV);
    for (int d = tid; d < DI; d += 256)
        g_yn[(size_t)bl*DI + d] = ybuf[d]*inv*rms_w[d];
}

// ---------------- launch ----------------
extern "C" void kernel_launch(void* const* d_in, const int* in_sizes, int n_in,
                              void* d_out, int out_size){
    const float* x          = (const float*)d_in[0];
    const float* ln_w       = (const float*)d_in[1];
    const float* ln_b       = (const float*)d_in[2];
    const float* in_proj_w  = (const float*)d_in[3];
    const float* conv_w     = (const float*)d_in[4];
    const float* conv_b     = (const float*)d_in[5];
    const float* dt_bias    = (const float*)d_in[6];
    const float* A_log      = (const float*)d_in[7];
    const float* Dv         = (const float*)d_in[8];
    const float* fc_D_w     = (const float*)d_in[9];
    const float* rms_w      = (const float*)d_in[10];
    const float* out_proj_w = (const float*)d_in[11];
    float* out = (float*)d_out;

    float *u, *zx, *xc, *dterm, *yn;
    cudaGetSymbolAddress((void**)&u,     g_u);
    cudaGetSymbolAddress((void**)&zx,    g_zx);
    cudaGetSymbolAddress((void**)&xc,    g_xc);
    cudaGetSymbolAddress((void**)&dterm, g_dterm);
    cudaGetSymbolAddress((void**)&yn,    g_yn);

    // 1) LayerNorm
    ln_kernel<<<BL, 256>>>(x, ln_w, ln_b);

    // 2) in_proj: (8192x768) @ (3248x768)^T -> (8192x3248)   [TF32 tensor cores]
    gemm_tf32<<<dim3((DIP+127)/128, BL/128), 256>>>(u, DM, in_proj_w, DM, nullptr, zx, DIP, BL, DIP, DM);

    // 3) dt softplus (both directions)
    dt_kernel<<<(NBB*SEQLEN*NH + 255)/256, 256>>>(dt_bias);

    // 4) depthwise causal conv + SiLU
    conv_kernel<<<BL, 256>>>(conv_w, conv_b);

    // 5) per-chunk cumsum of dt*A
    cumsum_kernel<<<NBB*NH*NC, 256>>>(A_log);

    // 6) chunk states
    states_kernel<<<NBB*NC*NH, 256>>>();

    // 7) inter-chunk scan
    prevscan_kernel<<<NBB*NH, 256>>>();

    // 8) intra-chunk Y + carry-in
    ydiag_kernel<<<NBB*NC*NH*4, 256>>>();

    // 9) fc_D: (8192x1536 view of xc) @ (24x1536)^T -> (8192x24)  [TF32]
    gemm_tf32<<<dim3(1, BL/128), 256>>>(xc, CONVD, fc_D_w, DI, nullptr, dterm, NH, BL, NH, DI);

    // 10) combine + gate + RMSNorm
    combine_kernel<<<BL, 256>>>(Dv, rms_w);

    // 11) out_proj + residual: (8192x1536) @ (768x1536)^T + x -> out  [TF32]
    gemm_tf32<<<dim3(DM/128, BL/128), 256>>>(yn, DI, out_proj_w, DI, x, out, DM, BL, DM, DI);
}

// round 3
// speedup vs baseline: 2.5808x; 1.5611x over previous
#include <cuda_runtime.h>
#include <math.h>
#include <stdint.h>

// ---------------- constants ----------------
#define BATCH   2
#define SEQLEN  4096
#define BL      (BATCH*SEQLEN)          // 8192 rows
#define DM      768
#define DI      1536
#define NH      24
#define HD      64
#define DS      64
#define DCONV   7
#define CONVD   (DI + 2*DS)             // 1664
#define DIP     (2*DI + 2*DS + 2*NH)    // 3248
#define CHUNK_T 256
#define NC      (SEQLEN/CHUNK_T)        // 16
#define NBB     (2*BATCH)               // 4 direction-batches
#define EPSV    1e-5f

// ---------------- scratch ----------------
__device__ float g_u[(size_t)BL*DM];
__device__ float g_zx[(size_t)BL*DIP];
__device__ float g_xc[(size_t)BL*CONVD];
__device__ float g_dt[(size_t)NBB*SEQLEN*NH];
__device__ float g_acum[(size_t)NBB*NH*NC*CHUNK_T];
__device__ float g_csum[(size_t)NBB*NH*NC];
__device__ float g_states[(size_t)NBB*NC*NH*HD*DS];
__device__ float g_prev[(size_t)NBB*NC*NH*HD*DS];
__device__ float g_yssd[(size_t)NBB*SEQLEN*DI];
__device__ float g_dterm[(size_t)BL*NH];
__device__ float g_yn[(size_t)BL*DI];

// ---------------- helpers ----------------
__device__ __forceinline__ float softplusf(float x){
    return (x > 20.f) ? x : log1pf(expf(x));
}
__device__ __forceinline__ float siluf(float x){
    return x / (1.f + expf(-x));
}
__device__ __forceinline__ float f2tf32(float f){
    unsigned r; asm("cvt.rna.tf32.f32 %0, %1;" : "=r"(r) : "f"(f));
    return __uint_as_float(r);
}
#define MMA_TF32(acc, a, b) \
    asm volatile("mma.sync.aligned.m16n8k8.row.col.f32.tf32.tf32.f32 " \
        "{%0,%1,%2,%3},{%4,%5,%6,%7},{%8,%9},{%0,%1,%2,%3};" \
        : "+f"(acc[0]),"+f"(acc[1]),"+f"(acc[2]),"+f"(acc[3]) \
        : "r"(a[0]),"r"(a[1]),"r"(a[2]),"r"(a[3]),"r"(b[0]),"r"(b[1]))

__device__ __forceinline__ float blockReduce256(float v, float* red){
    int tid = threadIdx.x;
    red[tid] = v; __syncthreads();
    #pragma unroll
    for (int o = 128; o > 0; o >>= 1){
        if (tid < o) red[tid] += red[tid + o];
        __syncthreads();
    }
    float r = red[0];
    __syncthreads();
    return r;
}

// ---------------- 1) LayerNorm ----------------
__global__ void ln_kernel(const float* __restrict__ x,
                          const float* __restrict__ w,
                          const float* __restrict__ b){
    __shared__ float red[256];
    int row = blockIdx.x;
    const float* xr = x + (size_t)row*DM;
    int tid = threadIdx.x;
    float s = 0.f;
    for (int i = tid; i < DM; i += 256) s += xr[i];
    float mu = blockReduce256(s, red) / DM;
    float v = 0.f;
    for (int i = tid; i < DM; i += 256){ float d = xr[i]-mu; v += d*d; }
    float var = blockReduce256(v, red) / DM;
    float inv = rsqrtf(var + EPSV);
    for (int i = tid; i < DM; i += 256)
        g_u[(size_t)row*DM + i] = (xr[i]-mu)*inv*w[i] + b[i];
}

// ---------------- TF32 GEMM: C[M,N] = A[M,K] @ B[N,K]^T (+R) ----------------
#define SMS 20
__global__ void gemm_tf32(const float* __restrict__ A, int lda,
                          const float* __restrict__ B, int ldb,
                          const float* __restrict__ R,
                          float* __restrict__ C, int ldc,
                          int M, int N, int K){
    __shared__ float As[128*SMS];
    __shared__ float Bs[128*SMS];
    const int tid  = threadIdx.x;
    const int lane = tid & 31;
    const int warp = tid >> 5;
    const int wm = warp >> 2;
    const int wn = warp & 3;
    const int m0 = blockIdx.y * 128;
    const int n0 = blockIdx.x * 128;
    const int grow = tid >> 2;
    const int gq   = tid & 3;

    const float* Ap0 = A + (size_t)(m0 + grow)*lda + gq*4;
    const float* Ap1 = Ap0 + (size_t)64*lda;
    const int br0 = n0 + grow, br1 = br0 + 64;
    const float* Bp0 = B + (size_t)br0*ldb + gq*4;
    const float* Bp1 = Bp0 + (size_t)64*ldb;
    const bool bok0 = br0 < N, bok1 = br1 < N;

    float acc[4][4][4];
    #pragma unroll
    for (int i=0;i<4;i++)
        #pragma unroll
        for (int j=0;j<4;j++)
            #pragma unroll
            for (int r=0;r<4;r++) acc[i][j][r]=0.f;

    float4 ra0, ra1, rb0, rb1;
    ra0 = *(const float4*)(Ap0);
    ra1 = *(const float4*)(Ap1);
    rb0 = bok0 ? *(const float4*)(Bp0) : make_float4(0.f,0.f,0.f,0.f);
    rb1 = bok1 ? *(const float4*)(Bp1) : make_float4(0.f,0.f,0.f,0.f);

    const int nk = K >> 4;
    for (int kt = 0; kt < nk; kt++){
        float* as0 = &As[grow*SMS + gq*4];
        as0[0]=f2tf32(ra0.x); as0[1]=f2tf32(ra0.y); as0[2]=f2tf32(ra0.z); as0[3]=f2tf32(ra0.w);
        float* as1 = &As[(grow+64)*SMS + gq*4];
        as1[0]=f2tf32(ra1.x); as1[1]=f2tf32(ra1.y); as1[2]=f2tf32(ra1.z); as1[3]=f2tf32(ra1.w);
        float* bs0 = &Bs[grow*SMS + gq*4];
        bs0[0]=f2tf32(rb0.x); bs0[1]=f2tf32(rb0.y); bs0[2]=f2tf32(rb0.z); bs0[3]=f2tf32(rb0.w);
        float* bs1 = &Bs[(grow+64)*SMS + gq*4];
        bs1[0]=f2tf32(rb1.x); bs1[1]=f2tf32(rb1.y); bs1[2]=f2tf32(rb1.z); bs1[3]=f2tf32(rb1.w);
        __syncthreads();

        if (kt+1 < nk){
            int ko = (kt+1) << 4;
            ra0 = *(const float4*)(Ap0 + ko);
            ra1 = *(const float4*)(Ap1 + ko);
            rb0 = bok0 ? *(const float4*)(Bp0 + ko) : make_float4(0.f,0.f,0.f,0.f);
            rb1 = bok1 ? *(const float4*)(Bp1 + ko) : make_float4(0.f,0.f,0.f,0.f);
        }

        #pragma unroll
        for (int ks = 0; ks < 16; ks += 8){
            const int kb = ks + (lane & 3);
            unsigned a[4][4], bfr[4][2];
            #pragma unroll
            for (int i=0;i<4;i++){
                int r = wm*64 + i*16 + (lane>>2);
                a[i][0] = __float_as_uint(As[r*SMS + kb]);
                a[i][1] = __float_as_uint(As[(r+8)*SMS + kb]);
                a[i][2] = __float_as_uint(As[r*SMS + kb + 4]);
                a[i][3] = __float_as_uint(As[(r+8)*SMS + kb + 4]);
            }
            #pragma unroll
            for (int j=0;j<4;j++){
                int cb = wn*32 + j*8 + (lane>>2);
                bfr[j][0] = __float_as_uint(Bs[cb*SMS + kb]);
                bfr[j][1] = __float_as_uint(Bs[cb*SMS + kb + 4]);
            }
            #pragma unroll
            for (int i=0;i<4;i++)
                #pragma unroll
                for (int j=0;j<4;j++) MMA_TF32(acc[i][j], a[i], bfr[j]);
        }
        __syncthreads();
    }

    #pragma unroll
    for (int i=0;i<4;i++){
        int r0 = m0 + wm*64 + i*16 + (lane>>2);
        #pragma unroll
        for (int j=0;j<4;j++){
            int cb = n0 + wn*32 + j*8;
            if (cb < N){
                int cc = cb + 2*(lane & 3);
                size_t o0 = (size_t)r0*ldc + cc;
                size_t o1 = (size_t)(r0+8)*ldc + cc;
                float v0 = acc[i][j][0], v1 = acc[i][j][1];
                float v2 = acc[i][j][2], v3 = acc[i][j][3];
                if (R){ v0 += R[o0]; v1 += R[o0+1]; v2 += R[o1]; v3 += R[o1+1]; }
                C[o0] = v0; C[o0+1] = v1; C[o1] = v2; C[o1+1] = v3;
            }
        }
    }
}

// ---------------- 3) dt prep ----------------
__global__ void dt_kernel(const float* __restrict__ dt_bias){
    int idx = blockIdx.x*256 + threadIdx.x;
    if (idx >= NBB*SEQLEN*NH) return;
    int h = idx % NH;
    int l = (idx / NH) % SEQLEN;
    int bb = idx / (NH*SEQLEN);
    int b = bb & 1;
    bool rev = bb >= 2;
    int t = rev ? (SEQLEN-1-l) : l;
    int col = (DIP - 2*NH) + (rev ? NH + h : h);
    float v = g_zx[(size_t)(b*SEQLEN + t)*DIP + col] + dt_bias[h];
    g_dt[idx] = softplusf(v);
}

// ---------------- 4) depthwise causal conv + SiLU ----------------
__global__ void conv_kernel(const float* __restrict__ cw,
                            const float* __restrict__ cb){
    int bl = blockIdx.x;
    int t = bl % SEQLEN;
    size_t base = (size_t)(bl - t) * DIP;
    for (int ch = threadIdx.x; ch < CONVD; ch += 256){
        float acc = cb[ch];
        const float* wp = cw + ch*DCONV;
        #pragma unroll
        for (int j = 0; j < DCONV; j++){
            int tt = t - (DCONV-1) + j;
            if (tt >= 0)
                acc += wp[j] * g_zx[base + (size_t)tt*DIP + DI + ch];
        }
        g_xc[(size_t)bl*CONVD + ch] = siluf(acc);
    }
}

// ---------------- 5) per-chunk cumsum of dt*A ----------------
__global__ void cumsum_kernel(const float* __restrict__ A_log){
    int bid = blockIdx.x;
    int c = bid % NC;
    int h = (bid / NC) % NH;
    int bb = bid / (NC*NH);
    int tid = threadIdx.x;
    float a = -expf(A_log[h]);
    int t = c*CHUNK_T + tid;
    float v = g_dt[(size_t)(bb*SEQLEN + t)*NH + h] * a;
    __shared__ float s[CHUNK_T];
    s[tid] = v; __syncthreads();
    for (int off = 1; off < CHUNK_T; off <<= 1){
        float add = (tid >= off) ? s[tid-off] : 0.f;
        __syncthreads();
        s[tid] += add;
        __syncthreads();
    }
    g_acum[(size_t)bid*CHUNK_T + tid] = s[tid];
    if (tid == CHUNK_T-1) g_csum[bid] = s[tid];
}

// ---------------- 6) chunk states (tensor cores) ----------------
// S[p,n] = sum_l (X[l,p]*dt[l]) * (B[l,n]*dec[l]),  K=256
#define SMT 68
__global__ void states_kernel(){
    int bid = blockIdx.x;            // (bb*NC+c)*NH + h
    int h = bid % NH;
    int c = (bid / NH) % NC;
    int bb = bid / (NH*NC);
    int b = bb & 1;
    bool rev = bb >= 2;
    int tid = threadIdx.x;
    int lane = tid & 31, warp = tid >> 5;
    int wm = warp >> 2, wn = warp & 3;
    int gid = lane >> 2, qid = lane & 3;

    __shared__ float Ab[64*SMT];     // Xt[p][l]
    __shared__ float Bb[64*SMT];     // Bt[n][l]
    __shared__ float dtl[64], decl[64];

    const float* ac = g_acum + ((size_t)(bb*NH + h)*NC + c)*CHUNK_T;
    float cs = g_csum[(bb*NH + h)*NC + c];

    float acc[2][2][4];
    #pragma unroll
    for (int i=0;i<2;i++)
        #pragma unroll
        for (int j=0;j<2;j++)
            #pragma unroll
            for (int r=0;r<4;r++) acc[i][j][r]=0.f;

    for (int ltile = 0; ltile < 4; ltile++){
        if (tid < 64){
            int lc2 = ltile*64 + tid;
            int tgl = c*CHUNK_T + lc2;
            dtl[tid] = g_dt[(size_t)(bb*SEQLEN + tgl)*NH + h];
            decl[tid] = expf(cs - ac[lc2]);
        }
        __syncthreads();
        for (int idx = tid; idx < 64*64; idx += 256){
            int l = idx >> 6, q = idx & 63;
            int tgl = c*CHUNK_T + ltile*64 + l;
            int trow = rev ? (SEQLEN-1 - tgl) : tgl;
            size_t roff = (size_t)(b*SEQLEN + trow)*CONVD;
            Ab[q*SMT + l] = f2tf32(g_xc[roff + h*HD + q] * dtl[l]);
            Bb[q*SMT + l] = f2tf32(g_xc[roff + DI + q] * decl[l]);
        }
        __syncthreads();
        #pragma unroll
        for (int ks = 0; ks < 8; ks++){
            int kb = ks*8 + qid;
            unsigned a[2][4], bf[2][2];
            #pragma unroll
            for (int i=0;i<2;i++){
                int r = wm*32 + i*16 + gid;
                a[i][0] = __float_as_uint(Ab[r*SMT + kb]);
                a[i][1] = __float_as_uint(Ab[(r+8)*SMT + kb]);
                a[i][2] = __float_as_uint(Ab[r*SMT + kb + 4]);
                a[i][3] = __float_as_uint(Ab[(r+8)*SMT + kb + 4]);
            }
            #pragma unroll
            for (int j=0;j<2;j++){
                int cb = wn*16 + j*8 + gid;
                bf[j][0] = __float_as_uint(Bb[cb*SMT + kb]);
                bf[j][1] = __float_as_uint(Bb[cb*SMT + kb + 4]);
            }
            #pragma unroll
            for (int i=0;i<2;i++)
                #pragma unroll
                for (int j=0;j<2;j++) MMA_TF32(acc[i][j], a[i], bf[j]);
        }
        __syncthreads();
    }
    float* sp = g_states + (size_t)bid*(HD*DS);
    #pragma unroll
    for (int i=0;i<2;i++){
        int p = wm*32 + i*16 + gid;
        #pragma unroll
        for (int j=0;j<2;j++){
            int n = wn*16 + j*8 + 2*qid;
            sp[p*DS + n]     = acc[i][j][0];
            sp[p*DS + n + 1] = acc[i][j][1];
            sp[(p+8)*DS + n]     = acc[i][j][2];
            sp[(p+8)*DS + n + 1] = acc[i][j][3];
        }
    }
}

// ---------------- 7) inter-chunk scan ----------------
__global__ void prevscan_kernel(){
    int bh = blockIdx.x;
    int bb = bh / NH, h = bh % NH;
    int tid = threadIdx.x;
    float run[16];
    #pragma unroll
    for (int k = 0; k < 16; k++) run[k] = 0.f;
    for (int c = 0; c < NC; c++){
        size_t off = ((size_t)(bb*NC + c)*NH + h)*(HD*DS);
        float e = expf(g_csum[bh*NC + c]);
        #pragma unroll
        for (int k = 0; k < 16; k++){
            int idx = k*256 + tid;
            g_prev[off + idx] = run[k];
            run[k] = run[k]*e + g_states[off + idx];
        }
    }
}

// ---------------- 8) Y = Y_diag + Y_off (tensor cores) ----------------
__global__ void ydiag_kernel(){
    int bid = blockIdx.x;            // ((bb*NC+c)*NH+h)*4 + lt
    int lt = bid & 3;
    int h  = (bid >> 2) % NH;
    int c  = (bid / (4*NH)) % NC;
    int bb = bid / (4*NH*NC);
    int b = bb & 1;
    bool rev = bb >= 2;
    int tid = threadIdx.x;
    int lane = tid & 31, warp = tid >> 5;
    int wm = warp >> 2, wn = warp & 3;
    int gid = lane >> 2, qid = lane & 3;

    __shared__ float Ab[64*SMT];
    __shared__ float Bb[64*SMT];
    __shared__ float acl[64], eacl[64], acs[64], dts[64];

    const float* ac = g_acum + ((size_t)(bb*NH + h)*NC + c)*CHUNK_T;

    if (tid < 64){
        float v = ac[lt*64 + tid];
        acl[tid] = v;
        eacl[tid] = expf(v);
    }
    __syncthreads();

    float acc[2][2][4];
    #pragma unroll
    for (int i=0;i<2;i++)
        #pragma unroll
        for (int j=0;j<2;j++)
            #pragma unroll
            for (int r=0;r<4;r++) acc[i][j][r]=0.f;

    // ---- Y_off: acc[l,p] += sum_n (C[l,n]*eacl[l]) * prev[p,n]
    {
        size_t poff = ((size_t)(bb*NC + c)*NH + h)*(HD*DS);
        for (int i4 = tid; i4 < 1024; i4 += 256){
            int l = i4 >> 4, c4 = (i4 & 15) * 4;
            int tgl = c*CHUNK_T + lt*64 + l;
            int trl = rev ? (SEQLEN-1 - tgl) : tgl;
            float4 cv = *(const float4*)&g_xc[(size_t)(b*SEQLEN + trl)*CONVD + DI + DS + c4];
            float e = eacl[l];
            float* d = &Ab[l*SMT + c4];
            d[0]=f2tf32(cv.x*e); d[1]=f2tf32(cv.y*e); d[2]=f2tf32(cv.z*e); d[3]=f2tf32(cv.w*e);
            float4 pv = *(const float4*)&g_prev[poff + l*64 + c4];
            float* d2 = &Bb[l*SMT + c4];
            d2[0]=f2tf32(pv.x); d2[1]=f2tf32(pv.y); d2[2]=f2tf32(pv.z); d2[3]=f2tf32(pv.w);
        }
        __syncthreads();
        #pragma unroll
        for (int ks = 0; ks < 8; ks++){
            int kb = ks*8 + qid;
            unsigned a[2][4], bf[2][2];
            #pragma unroll
            for (int i=0;i<2;i++){
                int r = wm*32 + i*16 + gid;
                a[i][0] = __float_as_uint(Ab[r*SMT + kb]);
                a[i][1] = __float_as_uint(Ab[(r+8)*SMT + kb]);
                a[i][2] = __float_as_uint(Ab[r*SMT + kb + 4]);
                a[i][3] = __float_as_uint(Ab[(r+8)*SMT + kb + 4]);
            }
            #pragma unroll
            for (int j=0;j<2;j++){
                int cb = wn*16 + j*8 + gid;
                bf[j][0] = __float_as_uint(Bb[cb*SMT + kb]);
                bf[j][1] = __float_as_uint(Bb[cb*SMT + kb + 4]);
            }
            #pragma unroll
            for (int i=0;i<2;i++)
                #pragma unroll
                for (int j=0;j<2;j++) MMA_TF32(acc[i][j], a[i], bf[j]);
        }
        __syncthreads();
    }

    // ---- Y_diag over s-tiles <= lt
    for (int st = 0; st <= lt; st++){
        if (tid < 64){
            acs[tid] = ac[st*64 + tid];
            dts[tid] = g_dt[(size_t)(bb*SEQLEN + c*CHUNK_T + st*64 + tid)*NH + h];
        }
        // load C (unscaled) -> Ab, Bm(st) -> Bb
        for (int i4 = tid; i4 < 1024; i4 += 256){
            int r = i4 >> 4, c4 = (i4 & 15) * 4;
            int tgl = c*CHUNK_T + lt*64 + r;
            int trl = rev ? (SEQLEN-1 - tgl) : tgl;
            float4 cv = *(const float4*)&g_xc[(size_t)(b*SEQLEN + trl)*CONVD + DI + DS + c4];
            float* d = &Ab[r*SMT + c4];
            d[0]=f2tf32(cv.x); d[1]=f2tf32(cv.y); d[2]=f2tf32(cv.z); d[3]=f2tf32(cv.w);
            int tgs = c*CHUNK_T + st*64 + r;
            int trs = rev ? (SEQLEN-1 - tgs) : tgs;
            float4 bv = *(const float4*)&g_xc[(size_t)(b*SEQLEN + trs)*CONVD + DI + c4];
            float* d2 = &Bb[r*SMT + c4];
            d2[0]=f2tf32(bv.x); d2[1]=f2tf32(bv.y); d2[2]=f2tf32(bv.z); d2[3]=f2tf32(bv.w);
        }
        __syncthreads();
        // G[l,s] = C . Bm^T
        float g[2][2][4];
        #pragma unroll
        for (int i=0;i<2;i++)
            #pragma unroll
            for (int j=0;j<2;j++)
                #pragma unroll
                for (int r=0;r<4;r++) g[i][j][r]=0.f;
        #pragma unroll
        for (int ks = 0; ks < 8; ks++){
            int kb = ks*8 + qid;
            unsigned a[2][4], bf[2][2];
            #pragma unroll
            for (int i=0;i<2;i++){
                int r = wm*32 + i*16 + gid;
                a[i][0] = __float_as_uint(Ab[r*SMT + kb]);
                a[i][1] = __float_as_uint(Ab[(r+8)*SMT + kb]);
                a[i][2] = __float_as_uint(Ab[r*SMT + kb + 4]);
                a[i][3] = __float_as_uint(Ab[(r+8)*SMT + kb + 4]);
            }
            #pragma unroll
            for (int j=0;j<2;j++){
                int cb = wn*16 + j*8 + gid;
                bf[j][0] = __float_as_uint(Bb[cb*SMT + kb]);
                bf[j][1] = __float_as_uint(Bb[cb*SMT + kb + 4]);
            }
            #pragma unroll
            for (int i=0;i<2;i++)
                #pragma unroll
                for (int j=0;j<2;j++) MMA_TF32(g[i][j], a[i], bf[j]);
        }
        __syncthreads();
        // mask+decay G -> Ab ;  Xd^T -> Bb
        bool diag = (st == lt);
        #pragma unroll
        for (int i=0;i<2;i++){
            int l0 = wm*32 + i*16 + gid;
            #pragma unroll
            for (int j=0;j<2;j++){
                int s0 = wn*16 + j*8 + 2*qid;
                float al0 = acl[l0], al1 = acl[l0+8];
                float w00 = (diag && s0   > l0) ? 0.f : expf(al0 - acs[s0]);
                float w01 = (diag && s0+1 > l0) ? 0.f : expf(al0 - acs[s0+1]);
                float w10 = (diag && s0   > l0+8) ? 0.f : expf(al1 - acs[s0]);
                float w11 = (diag && s0+1 > l0+8) ? 0.f : expf(al1 - acs[s0+1]);
                Ab[l0*SMT + s0]       = f2tf32(g[i][j][0]*w00);
                Ab[l0*SMT + s0+1]     = f2tf32(g[i][j][1]*w01);
                Ab[(l0+8)*SMT + s0]   = f2tf32(g[i][j][2]*w10);
                Ab[(l0+8)*SMT + s0+1] = f2tf32(g[i][j][3]*w11);
            }
        }
        for (int idx = tid; idx < 64*64; idx += 256){
            int s = idx >> 6, p = idx & 63;
            int tgs = c*CHUNK_T + st*64 + s;
            int trs = rev ? (SEQLEN-1 - tgs) : tgs;
            Bb[p*SMT + s] = f2tf32(g_xc[(size_t)(b*SEQLEN + trs)*CONVD + h*HD + p] * dts[s]);
        }
        __syncthreads();
        // acc[l,p] += GW . XdT^T
        #pragma unroll
        for (int ks = 0; ks < 8; ks++){
            int kb = ks*8 + qid;
            unsigned a[2][4], bf[2][2];
            #pragma unroll
            for (int i=0;i<2;i++){
                int r = wm*32 + i*16 + gid;
                a[i][0] = __float_as_uint(Ab[r*SMT + kb]);
                a[i][1] = __float_as_uint(Ab[(r+8)*SMT + kb]);
                a[i][2] = __float_as_uint(Ab[r*SMT + kb + 4]);
                a[i][3] = __float_as_uint(Ab[(r+8)*SMT + kb + 4]);
            }
            #pragma unroll
            for (int j=0;j<2;j++){
                int cb = wn*16 + j*8 + gid;
                bf[j][0] = __float_as_uint(Bb[cb*SMT + kb]);
                bf[j][1] = __float_as_uint(Bb[cb*SMT + kb + 4]);
            }
            #pragma unroll
            for (int i=0;i<2;i++)
                #pragma unroll
                for (int j=0;j<2;j++) MMA_TF32(acc[i][j], a[i], bf[j]);
        }
        __syncthreads();
    }

    // ---- store
    #pragma unroll
    for (int i=0;i<2;i++){
        int l = wm*32 + i*16 + gid;
        int tg0 = c*CHUNK_T + lt*64 + l;
        #pragma unroll
        for (int j=0;j<2;j++){
            int pc = h*HD + wn*16 + j*8 + 2*qid;
            size_t o0 = (size_t)(bb*SEQLEN + tg0)*DI + pc;
            size_t o1 = (size_t)(bb*SEQLEN + tg0 + 8)*DI + pc;
            g_yssd[o0]   = acc[i][j][0];
            g_yssd[o0+1] = acc[i][j][1];
            g_yssd[o1]   = acc[i][j][2];
            g_yssd[o1+1] = acc[i][j][3];
        }
    }
}

// ---------------- 9) combine dirs + skip + gate + RMSNorm ----------------
__global__ void combine_kernel(const float* __restrict__ Dv,
                               const float* __restrict__ rms_w){
    __shared__ float ybuf[DI];
    __shared__ float red[256];
    int bl = blockIdx.x;
    int b = bl / SEQLEN, t = bl % SEQLEN;
    int tid = threadIdx.x;
    float ss = 0.f;
    for (int d = tid; d < DI; d += 256){
        float yf = (t > 0) ? g_yssd[(size_t)(b*SEQLEN + t - 1)*DI + d] : 0.f;
        float yb = (t <= SEQLEN-2) ? g_yssd[(size_t)((2+b)*SEQLEN + (SEQLEN-2 - t))*DI + d] : 0.f;
        float xo = g_xc[(size_t)bl*CONVD + d];
        int h = d >> 6;
        float dterm = g_dterm[(size_t)bl*NH + h] + Dv[h];
        float z = g_zx[(size_t)bl*DIP + d];
        float y = (yf + yb + xo*dterm) * siluf(z);
        ybuf[d] = y;
        ss += y*y;
    }
    float tot = blockReduce256(ss, red);
    float inv = rsqrtf(tot/DI + EPSV);
    for (int d = tid; d < DI; d += 256)
        g_yn[(size_t)bl*DI + d] = ybuf[d]*inv*rms_w[d];
}

// ---------------- launch ----------------
extern "C" void kernel_launch(void* const* d_in, const int* in_sizes, int n_in,
                              void* d_out, int out_size){
    const float* x          = (const float*)d_in[0];
    const float* ln_w       = (const float*)d_in[1];
    const float* ln_b       = (const float*)d_in[2];
    const float* in_proj_w  = (const float*)d_in[3];
    const float* conv_w     = (const float*)d_in[4];
    const float* conv_b     = (const float*)d_in[5];
    const float* dt_bias    = (const float*)d_in[6];
    const float* A_log      = (const float*)d_in[7];
    const float* Dv         = (const float*)d_in[8];
    const float* fc_D_w     = (const float*)d_in[9];
    const float* rms_w      = (const float*)d_in[10];
    const float* out_proj_w = (const float*)d_in[11];
    float* out = (float*)d_out;

    float *u, *zx, *xc, *dterm, *yn;
    cudaGetSymbolAddress((void**)&u,     g_u);
    cudaGetSymbolAddress((void**)&zx,    g_zx);
    cudaGetSymbolAddress((void**)&xc,    g_xc);
    cudaGetSymbolAddress((void**)&dterm, g_dterm);
    cudaGetSymbolAddress((void**)&yn,    g_yn);

    ln_kernel<<<BL, 256>>>(x, ln_w, ln_b);
    gemm_tf32<<<dim3((DIP+127)/128, BL/128), 256>>>(u, DM, in_proj_w, DM, nullptr, zx, DIP, BL, DIP, DM);
    dt_kernel<<<(NBB*SEQLEN*NH + 255)/256, 256>>>(dt_bias);
    conv_kernel<<<BL, 256>>>(conv_w, conv_b);
    cumsum_kernel<<<NBB*NH*NC, 256>>>(A_log);
    states_kernel<<<NBB*NC*NH, 256>>>();
    prevscan_kernel<<<NBB*NH, 256>>>();
    ydiag_kernel<<<NBB*NC*NH*4, 256>>>();
    gemm_tf32<<<dim3(1, BL/128), 256>>>(xc, CONVD, fc_D_w, DI, nullptr, dterm, NH, BL, NH, DI);
    combine_kernel<<<BL, 256>>>(Dv, rms_w);
    gemm_tf32<<<dim3(DM/128, BL/128), 256>>>(yn, DI, out_proj_w, DI, x, out, DM, BL, DM, DI);
}

// round 4
// speedup vs baseline: 2.7387x; 1.0612x over previous
#include <cuda_runtime.h>
#include <math.h>
#include <stdint.h>

// ---------------- constants ----------------
#define BATCH   2
#define SEQLEN  4096
#define BL      (BATCH*SEQLEN)          // 8192 rows
#define DM      768
#define DI      1536
#define NH      24
#define HD      64
#define DS      64
#define DCONV   7
#define CONVD   (DI + 2*DS)             // 1664
#define DIP     (2*DI + 2*DS + 2*NH)    // 3248
#define CHUNK_T 256
#define NC      (SEQLEN/CHUNK_T)        // 16
#define NBB     (2*BATCH)               // 4 direction-batches
#define EPSV    1e-5f

// ---------------- scratch ----------------
__device__ float g_u[(size_t)BL*DM];
__device__ float g_zx[(size_t)BL*DIP];
__device__ float g_xc[(size_t)BL*CONVD];
__device__ float g_dt[(size_t)NBB*SEQLEN*NH];
__device__ float g_acum[(size_t)NBB*NH*NC*CHUNK_T];
__device__ float g_csum[(size_t)NBB*NH*NC];
__device__ float g_states[(size_t)NBB*NC*NH*HD*DS];
__device__ float g_prev[(size_t)NBB*NC*NH*HD*DS];
__device__ float g_yssd[(size_t)NBB*SEQLEN*DI];
__device__ float g_dterm[(size_t)BL*NH];
__device__ float g_yn[(size_t)BL*DI];
__device__ float g_wa[(size_t)DIP*DM];   // tf32-rounded in_proj_w
__device__ float g_wo[(size_t)DM*DI];    // tf32-rounded out_proj_w

// ---------------- helpers ----------------
__device__ __forceinline__ float softplusf(float x){
    return (x > 20.f) ? x : log1pf(expf(x));
}
__device__ __forceinline__ float siluf(float x){
    return x / (1.f + expf(-x));
}
__device__ __forceinline__ float f2tf32(float f){
    unsigned r; asm("cvt.rna.tf32.f32 %0, %1;" : "=r"(r) : "f"(f));
    return __uint_as_float(r);
}
#define MMA_TF32(acc, a, b) \
    asm volatile("mma.sync.aligned.m16n8k8.row.col.f32.tf32.tf32.f32 " \
        "{%0,%1,%2,%3},{%4,%5,%6,%7},{%8,%9},{%0,%1,%2,%3};" \
        : "+f"(acc[0]),"+f"(acc[1]),"+f"(acc[2]),"+f"(acc[3]) \
        : "r"(a[0]),"r"(a[1]),"r"(a[2]),"r"(a[3]),"r"(b[0]),"r"(b[1]))

__device__ __forceinline__ void cp16(float* dst, const float* src, bool p){
    unsigned d = (unsigned)__cvta_generic_to_shared(dst);
    int sz = p ? 16 : 0;
    asm volatile("cp.async.cg.shared.global [%0], [%1], 16, %2;\n"
                 :: "r"(d), "l"(src), "r"(sz));
}
__device__ __forceinline__ void cp_commit(){ asm volatile("cp.async.commit_group;\n"); }
__device__ __forceinline__ void cp_wait1(){ asm volatile("cp.async.wait_group 1;\n"); }

__device__ __forceinline__ float blockReduce256(float v, float* red){
    int tid = threadIdx.x;
    red[tid] = v; __syncthreads();
    #pragma unroll
    for (int o = 128; o > 0; o >>= 1){
        if (tid < o) red[tid] += red[tid + o];
        __syncthreads();
    }
    float r = red[0];
    __syncthreads();
    return r;
}

// ---------------- 0) weight pre-round to tf32 ----------------
__global__ void wconv_kernel(const float* __restrict__ wi,
                             const float* __restrict__ wo){
    int i = blockIdx.x*256 + threadIdx.x;
    if (i < DIP*DM) g_wa[i] = f2tf32(wi[i]);
    if (i < DM*DI)  g_wo[i] = f2tf32(wo[i]);
}

// ---------------- 1) LayerNorm (emits tf32-rounded) ----------------
__global__ void ln_kernel(const float* __restrict__ x,
                          const float* __restrict__ w,
                          const float* __restrict__ b){
    __shared__ float red[256];
    int row = blockIdx.x;
    const float* xr = x + (size_t)row*DM;
    int tid = threadIdx.x;
    float s = 0.f;
    for (int i = tid; i < DM; i += 256) s += xr[i];
    float mu = blockReduce256(s, red) / DM;
    float v = 0.f;
    for (int i = tid; i < DM; i += 256){ float d = xr[i]-mu; v += d*d; }
    float var = blockReduce256(v, red) / DM;
    float inv = rsqrtf(var + EPSV);
    for (int i = tid; i < DM; i += 256)
        g_u[(size_t)row*DM + i] = f2tf32((xr[i]-mu)*inv*w[i] + b[i]);
}

// ---------------- TF32 GEMM, 3-stage cp.async ----------------
// C[M,N] = A[M,K] @ B[N,K]^T (+R).  A,B already tf32-valued.
#define SMS 20
#define GST 3
__global__ __launch_bounds__(256, 2)
void gemm_db(const float* __restrict__ A, int lda,
             const float* __restrict__ B, int ldb,
             const float* __restrict__ R,
             float* __restrict__ C, int ldc,
             int M, int N, int K){
    extern __shared__ float sm[];
    float* AsB = sm;                    // GST * 128*SMS
    float* BsB = sm + GST*128*SMS;
    const int tid  = threadIdx.x;
    const int lane = tid & 31;
    const int warp = tid >> 5;
    const int wm = warp >> 2;
    const int wn = warp & 3;
    const int m0 = blockIdx.y * 128;
    const int n0 = blockIdx.x * 128;
    const int grow = tid >> 2;
    const int gq   = tid & 3;

    const float* Ap0 = A + (size_t)(m0 + grow)*lda + gq*4;
    const float* Ap1 = Ap0 + (size_t)64*lda;
    const int br0 = n0 + grow, br1 = br0 + 64;
    const float* Bp0 = B + (size_t)br0*ldb + gq*4;
    const float* Bp1 = Bp0 + (size_t)64*ldb;
    const bool bok0 = br0 < N, bok1 = br1 < N;

    float acc[4][4][4];
    #pragma unroll
    for (int i=0;i<4;i++)
        #pragma unroll
        for (int j=0;j<4;j++)
            #pragma unroll
            for (int r=0;r<4;r++) acc[i][j][r]=0.f;

    const int nk = K >> 4;

    #pragma unroll
    for (int s = 0; s < GST-1; s++){
        int ko = s << 4;
        float* as = AsB + s*(128*SMS);
        float* bs = BsB + s*(128*SMS);
        cp16(as + grow*SMS + gq*4,        Ap0 + ko, true);
        cp16(as + (grow+64)*SMS + gq*4,   Ap1 + ko, true);
        cp16(bs + grow*SMS + gq*4,        Bp0 + ko, bok0);
        cp16(bs + (grow+64)*SMS + gq*4,   Bp1 + ko, bok1);
        cp_commit();
    }

    for (int kt = 0; kt < nk; kt++){
        cp_wait1();
        __syncthreads();
        int kn = kt + GST - 1;
        if (kn < nk){
            int ko = kn << 4;
            int stg = kn % GST;
            float* as = AsB + stg*(128*SMS);
            float* bs = BsB + stg*(128*SMS);
            cp16(as + grow*SMS + gq*4,        Ap0 + ko, true);
            cp16(as + (grow+64)*SMS + gq*4,   Ap1 + ko, true);
            cp16(bs + grow*SMS + gq*4,        Bp0 + ko, bok0);
            cp16(bs + (grow+64)*SMS + gq*4,   Bp1 + ko, bok1);
        }
        cp_commit();

        const float* As = AsB + (kt % GST)*(128*SMS);
        const float* Bs = BsB + (kt % GST)*(128*SMS);
        #pragma unroll
        for (int ks = 0; ks < 16; ks += 8){
            const int kb = ks + (lane & 3);
            unsigned a[4][4], bfr[4][2];
            #pragma unroll
            for (int i=0;i<4;i++){
                int r = wm*64 + i*16 + (lane>>2);
                a[i][0] = __float_as_uint(As[r*SMS + kb]);
                a[i][1] = __float_as_uint(As[(r+8)*SMS + kb]);
                a[i][2] = __float_as_uint(As[r*SMS + kb + 4]);
                a[i][3] = __float_as_uint(As[(r+8)*SMS + kb + 4]);
            }
            #pragma unroll
            for (int j=0;j<4;j++){
                int cb = wn*32 + j*8 + (lane>>2);
                bfr[j][0] = __float_as_uint(Bs[cb*SMS + kb]);
                bfr[j][1] = __float_as_uint(Bs[cb*SMS + kb + 4]);
            }
            #pragma unroll
            for (int i=0;i<4;i++)
                #pragma unroll
                for (int j=0;j<4;j++) MMA_TF32(acc[i][j], a[i], bfr[j]);
        }
    }

    #pragma unroll
    for (int i=0;i<4;i++){
        int r0 = m0 + wm*64 + i*16 + (lane>>2);
        #pragma unroll
        for (int j=0;j<4;j++){
            int cb = n0 + wn*32 + j*8;
            if (cb < N){
                int cc = cb + 2*(lane & 3);
                size_t o0 = (size_t)r0*ldc + cc;
                size_t o1 = (size_t)(r0+8)*ldc + cc;
                float v0 = acc[i][j][0], v1 = acc[i][j][1];
                float v2 = acc[i][j][2], v3 = acc[i][j][3];
                if (R){ v0 += R[o0]; v1 += R[o0+1]; v2 += R[o1]; v3 += R[o1+1]; }
                C[o0] = v0; C[o0+1] = v1; C[o1] = v2; C[o1+1] = v3;
            }
        }
    }
}

// ---------------- 4) depthwise causal conv + SiLU ----------------
__global__ void conv_kernel(const float* __restrict__ cw,
                            const float* __restrict__ cb){
    int bl = blockIdx.x;
    int t = bl % SEQLEN;
    size_t base = (size_t)(bl - t) * DIP;
    for (int ch = threadIdx.x; ch < CONVD; ch += 256){
        float acc = cb[ch];
        const float* wp = cw + ch*DCONV;
        #pragma unroll
        for (int j = 0; j < DCONV; j++){
            int tt = t - (DCONV-1) + j;
            if (tt >= 0)
                acc += wp[j] * g_zx[base + (size_t)tt*DIP + DI + ch];
        }
        g_xc[(size_t)bl*CONVD + ch] = siluf(acc);
    }
}

// ---------------- 5) dt softplus + per-chunk cumsum fused ----------------
__global__ void cumsum_kernel(const float* __restrict__ A_log,
                              const float* __restrict__ dt_bias){
    int bid = blockIdx.x;            // ((bb*NH)+h)*NC + c
    int c = bid % NC;
    int h = (bid / NC) % NH;
    int bb = bid / (NC*NH);
    int b = bb & 1;
    bool rev = bb >= 2;
    int tid = threadIdx.x;
    float a = -expf(A_log[h]);
    int t = c*CHUNK_T + tid;
    int tg = rev ? (SEQLEN-1-t) : t;
    int col = (DIP - 2*NH) + (rev ? NH + h : h);
    float dtv = softplusf(g_zx[(size_t)(b*SEQLEN + tg)*DIP + col] + dt_bias[h]);
    g_dt[(size_t)(bb*SEQLEN + t)*NH + h] = dtv;
    float v = dtv * a;
    __shared__ float s[CHUNK_T];
    s[tid] = v; __syncthreads();
    for (int off = 1; off < CHUNK_T; off <<= 1){
        float add = (tid >= off) ? s[tid-off] : 0.f;
        __syncthreads();
        s[tid] += add;
        __syncthreads();
    }
    g_acum[(size_t)bid*CHUNK_T + tid] = s[tid];
    if (tid == CHUNK_T-1) g_csum[bid] = s[tid];
}

// ---------------- 6) chunk states (tensor cores) ----------------
#define SMT 68
__global__ void states_kernel(){
    int bid = blockIdx.x;            // (bb*NC+c)*NH + h
    int h = bid % NH;
    int c = (bid / NH) % NC;
    int bb = bid / (NH*NC);
    int b = bb & 1;
    bool rev = bb >= 2;
    int tid = threadIdx.x;
    int lane = tid & 31, warp = tid >> 5;
    int wm = warp >> 2, wn = warp & 3;
    int gid = lane >> 2, qid = lane & 3;

    __shared__ float Ab[64*SMT];
    __shared__ float Bb[64*SMT];
    __shared__ float dtl[64], decl[64];

    const float* ac = g_acum + ((size_t)(bb*NH + h)*NC + c)*CHUNK_T;
    float cs = g_csum[(bb*NH + h)*NC + c];

    float acc[2][2][4];
    #pragma unroll
    for (int i=0;i<2;i++)
        #pragma unroll
        for (int j=0;j<2;j++)
            #pragma unroll
            for (int r=0;r<4;r++) acc[i][j][r]=0.f;

    for (int ltile = 0; ltile < 4; ltile++){
        if (tid < 64){
            int lc2 = ltile*64 + tid;
            int tgl = c*CHUNK_T + lc2;
            dtl[tid] = g_dt[(size_t)(bb*SEQLEN + tgl)*NH + h];
            decl[tid] = expf(cs - ac[lc2]);
        }
        __syncthreads();
        for (int idx = tid; idx < 64*64; idx += 256){
            int l = idx >> 6, q = idx & 63;
            int tgl = c*CHUNK_T + ltile*64 + l;
            int trow = rev ? (SEQLEN-1 - tgl) : tgl;
            size_t roff = (size_t)(b*SEQLEN + trow)*CONVD;
            Ab[q*SMT + l] = f2tf32(g_xc[roff + h*HD + q] * dtl[l]);
            Bb[q*SMT + l] = f2tf32(g_xc[roff + DI + q] * decl[l]);
        }
        __syncthreads();
        #pragma unroll
        for (int ks = 0; ks < 8; ks++){
            int kb = ks*8 + qid;
            unsigned a[2][4], bf[2][2];
            #pragma unroll
            for (int i=0;i<2;i++){
                int r = wm*32 + i*16 + gid;
                a[i][0] = __float_as_uint(Ab[r*SMT + kb]);
                a[i][1] = __float_as_uint(Ab[(r+8)*SMT + kb]);
                a[i][2] = __float_as_uint(Ab[r*SMT + kb + 4]);
                a[i][3] = __float_as_uint(Ab[(r+8)*SMT + kb + 4]);
            }
            #pragma unroll
            for (int j=0;j<2;j++){
                int cb = wn*16 + j*8 + gid;
                bf[j][0] = __float_as_uint(Bb[cb*SMT + kb]);
                bf[j][1] = __float_as_uint(Bb[cb*SMT + kb + 4]);
            }
            #pragma unroll
            for (int i=0;i<2;i++)
                #pragma unroll
                for (int j=0;j<2;j++) MMA_TF32(acc[i][j], a[i], bf[j]);
        }
        __syncthreads();
    }
    float* sp = g_states + (size_t)bid*(HD*DS);
    #pragma unroll
    for (int i=0;i<2;i++){
        int p = wm*32 + i*16 + gid;
        #pragma unroll
        for (int j=0;j<2;j++){
            int n = wn*16 + j*8 + 2*qid;
            sp[p*DS + n]     = acc[i][j][0];
            sp[p*DS + n + 1] = acc[i][j][1];
            sp[(p+8)*DS + n]     = acc[i][j][2];
            sp[(p+8)*DS + n + 1] = acc[i][j][3];
        }
    }
}

// ---------------- 7) inter-chunk scan ----------------
__global__ void prevscan_kernel(){
    int bh = blockIdx.x;
    int bb = bh / NH, h = bh % NH;
    int tid = threadIdx.x;
    float run[16];
    #pragma unroll
    for (int k = 0; k < 16; k++) run[k] = 0.f;
    for (int c = 0; c < NC; c++){
        size_t off = ((size_t)(bb*NC + c)*NH + h)*(HD*DS);
        float e = expf(g_csum[bh*NC + c]);
        #pragma unroll
        for (int k = 0; k < 16; k++){
            int idx = k*256 + tid;
            g_prev[off + idx] = run[k];
            run[k] = run[k]*e + g_states[off + idx];
        }
    }
}

// ---------------- 8) Y = Y_diag + Y_off (tensor cores) ----------------
__global__ void ydiag_kernel(){
    int bid = blockIdx.x;            // ((bb*NC+c)*NH+h)*4 + lt
    int lt = bid & 3;
    int h  = (bid >> 2) % NH;
    int c  = (bid / (4*NH)) % NC;
    int bb = bid / (4*NH*NC);
    int b = bb & 1;
    bool rev = bb >= 2;
    int tid = threadIdx.x;
    int lane = tid & 31, warp = tid >> 5;
    int wm = warp >> 2, wn = warp & 3;
    int gid = lane >> 2, qid = lane & 3;

    __shared__ float Ab[64*SMT];
    __shared__ float Bb[64*SMT];
    __shared__ float acl[64], eacl[64], acs[64], dts[64];

    const float* ac = g_acum + ((size_t)(bb*NH + h)*NC + c)*CHUNK_T;

    if (tid < 64){
        float v = ac[lt*64 + tid];
        acl[tid] = v;
        eacl[tid] = expf(v);
    }
    __syncthreads();

    float acc[2][2][4];
    #pragma unroll
    for (int i=0;i<2;i++)
        #pragma unroll
        for (int j=0;j<2;j++)
            #pragma unroll
            for (int r=0;r<4;r++) acc[i][j][r]=0.f;

    // ---- Y_off
    {
        size_t poff = ((size_t)(bb*NC + c)*NH + h)*(HD*DS);
        for (int i4 = tid; i4 < 1024; i4 += 256){
            int l = i4 >> 4, c4 = (i4 & 15) * 4;
            int tgl = c*CHUNK_T + lt*64 + l;
            int trl = rev ? (SEQLEN-1 - tgl) : tgl;
            float4 cv = *(const float4*)&g_xc[(size_t)(b*SEQLEN + trl)*CONVD + DI + DS + c4];
            float e = eacl[l];
            float* d = &Ab[l*SMT + c4];
            d[0]=f2tf32(cv.x*e); d[1]=f2tf32(cv.y*e); d[2]=f2tf32(cv.z*e); d[3]=f2tf32(cv.w*e);
            float4 pv = *(const float4*)&g_prev[poff + l*64 + c4];
            float* d2 = &Bb[l*SMT + c4];
            d2[0]=f2tf32(pv.x); d2[1]=f2tf32(pv.y); d2[2]=f2tf32(pv.z); d2[3]=f2tf32(pv.w);
        }
        __syncthreads();
        #pragma unroll
        for (int ks = 0; ks < 8; ks++){
            int kb = ks*8 + qid;
            unsigned a[2][4], bf[2][2];
            #pragma unroll
            for (int i=0;i<2;i++){
                int r = wm*32 + i*16 + gid;
                a[i][0] = __float_as_uint(Ab[r*SMT + kb]);
                a[i][1] = __float_as_uint(Ab[(r+8)*SMT + kb]);
                a[i][2] = __float_as_uint(Ab[r*SMT + kb + 4]);
                a[i][3] = __float_as_uint(Ab[(r+8)*SMT + kb + 4]);
            }
            #pragma unroll
            for (int j=0;j<2;j++){
                int cb = wn*16 + j*8 + gid;
                bf[j][0] = __float_as_uint(Bb[cb*SMT + kb]);
                bf[j][1] = __float_as_uint(Bb[cb*SMT + kb + 4]);
            }
            #pragma unroll
            for (int i=0;i<2;i++)
                #pragma unroll
                for (int j=0;j<2;j++) MMA_TF32(acc[i][j], a[i], bf[j]);
        }
        __syncthreads();
    }

    // ---- Y_diag over s-tiles <= lt
    for (int st = 0; st <= lt; st++){
        if (tid < 64){
            acs[tid] = ac[st*64 + tid];
            dts[tid] = g_dt[(size_t)(bb*SEQLEN + c*CHUNK_T + st*64 + tid)*NH + h];
        }
        for (int i4 = tid; i4 < 1024; i4 += 256){
            int r = i4 >> 4, c4 = (i4 & 15) * 4;
            int tgl = c*CHUNK_T + lt*64 + r;
            int trl = rev ? (SEQLEN-1 - tgl) : tgl;
            float4 cv = *(const float4*)&g_xc[(size_t)(b*SEQLEN + trl)*CONVD + DI + DS + c4];
            float* d = &Ab[r*SMT + c4];
            d[0]=f2tf32(cv.x); d[1]=f2tf32(cv.y); d[2]=f2tf32(cv.z); d[3]=f2tf32(cv.w);
            int tgs = c*CHUNK_T + st*64 + r;
            int trs = rev ? (SEQLEN-1 - tgs) : tgs;
            float4 bv = *(const float4*)&g_xc[(size_t)(b*SEQLEN + trs)*CONVD + DI + c4];
            float* d2 = &Bb[r*SMT + c4];
            d2[0]=f2tf32(bv.x); d2[1]=f2tf32(bv.y); d2[2]=f2tf32(bv.z); d2[3]=f2tf32(bv.w);
        }
        __syncthreads();
        float g[2][2][4];
        #pragma unroll
        for (int i=0;i<2;i++)
            #pragma unroll
            for (int j=0;j<2;j++)
                #pragma unroll
                for (int r=0;r<4;r++) g[i][j][r]=0.f;
        #pragma unroll
        for (int ks = 0; ks < 8; ks++){
            int kb = ks*8 + qid;
            unsigned a[2][4], bf[2][2];
            #pragma unroll
            for (int i=0;i<2;i++){
                int r = wm*32 + i*16 + gid;
                a[i][0] = __float_as_uint(Ab[r*SMT + kb]);
                a[i][1] = __float_as_uint(Ab[(r+8)*SMT + kb]);
                a[i][2] = __float_as_uint(Ab[r*SMT + kb + 4]);
                a[i][3] = __float_as_uint(Ab[(r+8)*SMT + kb + 4]);
            }
            #pragma unroll
            for (int j=0;j<2;j++){
                int cb = wn*16 + j*8 + gid;
                bf[j][0] = __float_as_uint(Bb[cb*SMT + kb]);
                bf[j][1] = __float_as_uint(Bb[cb*SMT + kb + 4]);
            }
            #pragma unroll
            for (int i=0;i<2;i++)
                #pragma unroll
                for (int j=0;j<2;j++) MMA_TF32(g[i][j], a[i], bf[j]);
        }
        __syncthreads();
        bool diag = (st == lt);
        #pragma unroll
        for (int i=0;i<2;i++){
            int l0 = wm*32 + i*16 + gid;
            #pragma unroll
            for (int j=0;j<2;j++){
                int s0 = wn*16 + j*8 + 2*qid;
                float al0 = acl[l0], al1 = acl[l0+8];
                float w00 = (diag && s0   > l0) ? 0.f : expf(al0 - acs[s0]);
                float w01 = (diag && s0+1 > l0) ? 0.f : expf(al0 - acs[s0+1]);
                float w10 = (diag && s0   > l0+8) ? 0.f : expf(al1 - acs[s0]);
                float w11 = (diag && s0+1 > l0+8) ? 0.f : expf(al1 - acs[s0+1]);
                Ab[l0*SMT + s0]       = f2tf32(g[i][j][0]*w00);
                Ab[l0*SMT + s0+1]     = f2tf32(g[i][j][1]*w01);
                Ab[(l0+8)*SMT + s0]   = f2tf32(g[i][j][2]*w10);
                Ab[(l0+8)*SMT + s0+1] = f2tf32(g[i][j][3]*w11);
            }
        }
        for (int idx = tid; idx < 64*64; idx += 256){
            int s = idx >> 6, p = idx & 63;
            int tgs = c*CHUNK_T + st*64 + s;
            int trs = rev ? (SEQLEN-1 - tgs) : tgs;
            Bb[p*SMT + s] = f2tf32(g_xc[(size_t)(b*SEQLEN + trs)*CONVD + h*HD + p] * dts[s]);
        }
        __syncthreads();
        #pragma unroll
        for (int ks = 0; ks < 8; ks++){
            int kb = ks*8 + qid;
            unsigned a[2][4], bf[2][2];
            #pragma unroll
            for (int i=0;i<2;i++){
                int r = wm*32 + i*16 + gid;
                a[i][0] = __float_as_uint(Ab[r*SMT + kb]);
                a[i][1] = __float_as_uint(Ab[(r+8)*SMT + kb]);
                a[i][2] = __float_as_uint(Ab[r*SMT + kb + 4]);
                a[i][3] = __float_as_uint(Ab[(r+8)*SMT + kb + 4]);
            }
            #pragma unroll
            for (int j=0;j<2;j++){
                int cb = wn*16 + j*8 + gid;
                bf[j][0] = __float_as_uint(Bb[cb*SMT + kb]);
                bf[j][1] = __float_as_uint(Bb[cb*SMT + kb + 4]);
            }
            #pragma unroll
            for (int i=0;i<2;i++)
                #pragma unroll
                for (int j=0;j<2;j++) MMA_TF32(acc[i][j], a[i], bf[j]);
        }
        __syncthreads();
    }

    #pragma unroll
    for (int i=0;i<2;i++){
        int l = wm*32 + i*16 + gid;
        int tg0 = c*CHUNK_T + lt*64 + l;
        #pragma unroll
        for (int j=0;j<2;j++){
            int pc = h*HD + wn*16 + j*8 + 2*qid;
            size_t o0 = (size_t)(bb*SEQLEN + tg0)*DI + pc;
            size_t o1 = (size_t)(bb*SEQLEN + tg0 + 8)*DI + pc;
            g_yssd[o0]   = acc[i][j][0];
            g_yssd[o0+1] = acc[i][j][1];
            g_yssd[o1]   = acc[i][j][2];
            g_yssd[o1+1] = acc[i][j][3];
        }
    }
}

// ---------------- 9) fc_D: dterm[r,h] = xs[r,:] . fc_D_w[h,:] ----------------
__global__ void fcd_kernel(const float* __restrict__ fw){
    __shared__ float ws[NH][132];
    int r0 = blockIdx.x * 64;
    int tid = threadIdx.x;
    int rl = tid >> 2;            // 0..63
    int lj = tid & 3;             // 0..3 (6 heads each)
    float acc[6] = {0.f,0.f,0.f,0.f,0.f,0.f};
    for (int k0 = 0; k0 < DI; k0 += 128){
        for (int i = tid; i < NH*128; i += 256)
            ws[i>>7][i&127] = fw[(size_t)(i>>7)*DI + k0 + (i&127)];
        __syncthreads();
        const float* xr = &g_xc[(size_t)(r0+rl)*CONVD + k0];
        #pragma unroll 8
        for (int kk = 0; kk < 128; kk += 4){
            float4 xv = *(const float4*)(xr + kk);
            #pragma unroll
            for (int hh = 0; hh < 6; hh++){
                int h = lj*6 + hh;
                acc[hh] += xv.x*ws[h][kk] + xv.y*ws[h][kk+1]
                         + xv.z*ws[h][kk+2] + xv.w*ws[h][kk+3];
            }
        }
        __syncthreads();
    }
    #pragma unroll
    for (int hh = 0; hh < 6; hh++)
        g_dterm[(size_t)(r0+rl)*NH + lj*6 + hh] = acc[hh];
}

// ---------------- 10) combine dirs + skip + gate + RMSNorm (emits tf32) ----------------
__global__ void combine_kernel(const float* __restrict__ Dv,
                               const float* __restrict__ rms_w){
    __shared__ float ybuf[DI];
    __shared__ float red[256];
    int bl = blockIdx.x;
    int b = bl / SEQLEN, t = bl % SEQLEN;
    int tid = threadIdx.x;
    float ss = 0.f;
    for (int d = tid; d < DI; d += 256){
        float yf = (t > 0) ? g_yssd[(size_t)(b*SEQLEN + t - 1)*DI + d] : 0.f;
        float yb = (t <= SEQLEN-2) ? g_yssd[(size_t)((2+b)*SEQLEN + (SEQLEN-2 - t))*DI + d] : 0.f;
        float xo = g_xc[(size_t)bl*CONVD + d];
        int h = d >> 6;
        float dterm = g_dterm[(size_t)bl*NH + h] + Dv[h];
        float z = g_zx[(size_t)bl*DIP + d];
        float y = (yf + yb + xo*dterm) * siluf(z);
        ybuf[d] = y;
        ss += y*y;
    }
    float tot = blockReduce256(ss, red);
    float inv = rsqrtf(tot/DI + EPSV);
    for (int d = tid; d < DI; d += 256)
        g_yn[(size_t)bl*DI + d] = f2tf32(ybuf[d]*inv*rms_w[d]);
}

// ---------------- launch ----------------
extern "C" void kernel_launch(void* const* d_in, const int* in_sizes, int n_in,
                              void* d_out, int out_size){
    const float* x          = (const float*)d_in[0];
    const float* ln_w       = (const float*)d_in[1];
    const float* ln_b       = (const float*)d_in[2];
    const float* in_proj_w  = (const float*)d_in[3];
    const float* conv_w     = (const float*)d_in[4];
    const float* conv_b     = (const float*)d_in[5];
    const float* dt_bias    = (const float*)d_in[6];
    const float* A_log      = (const float*)d_in[7];
    const float* Dv         = (const float*)d_in[8];
    const float* fc_D_w     = (const float*)d_in[9];
    const float* rms_w      = (const float*)d_in[10];
    const float* out_proj_w = (const float*)d_in[11];
    float* out = (float*)d_out;

    float *u, *zx, *yn, *wa, *wo;
    cudaGetSymbolAddress((void**)&u,  g_u);
    cudaGetSymbolAddress((void**)&zx, g_zx);
    cudaGetSymbolAddress((void**)&yn, g_yn);
    cudaGetSymbolAddress((void**)&wa, g_wa);
    cudaGetSymbolAddress((void**)&wo, g_wo);

    static bool attr_set = false;
    const int gsmem = GST*2*128*SMS*sizeof(float);   // 61440 B
    if (!attr_set){
        cudaFuncSetAttribute(gemm_db, cudaFuncAttributeMaxDynamicSharedMemorySize, gsmem);
        attr_set = true;
    }

    wconv_kernel<<<(DIP*DM + 255)/256, 256>>>(in_proj_w, out_proj_w);
    ln_kernel<<<BL, 256>>>(x, ln_w, ln_b);

    // in_proj
    gemm_db<<<dim3((DIP+127)/128, BL/128), 256, gsmem>>>(u, DM, wa, DM, nullptr, zx, DIP, BL, DIP, DM);

    conv_kernel<<<BL, 256>>>(conv_w, conv_b);
    cumsum_kernel<<<NBB*NH*NC, 256>>>(A_log, dt_bias);
    states_kernel<<<NBB*NC*NH, 256>>>();
    prevscan_kernel<<<NBB*NH, 256>>>();
    ydiag_kernel<<<NBB*NC*NH*4, 256>>>();
    fcd_kernel<<<BL/64, 256>>>(fc_D_w);
    combine_kernel<<<BL, 256>>>(Dv, rms_w);

    // out_proj + residual
    gemm_db<<<dim3(DM/128, BL/128), 256, gsmem>>>(yn, DI, wo, DI, x, out, DM, BL, DM, DI);
}

// round 5
// speedup vs baseline: 3.3470x; 1.2221x over previous
#include <cuda_runtime.h>
#include <cuda_fp16.h>
#include <math.h>
#include <stdint.h>

// ---------------- constants ----------------
#define BATCH   2
#define SEQLEN  4096
#define BL      (BATCH*SEQLEN)          // 8192 rows
#define DM      768
#define DI      1536
#define NH      24
#define HD      64
#define DS      64
#define DCONV   7
#define CONVD   (DI + 2*DS)             // 1664
#define DIP     (2*DI + 2*DS + 2*NH)    // 3248
#define CHUNK_T 256
#define NC      (SEQLEN/CHUNK_T)        // 16
#define NBB     (2*BATCH)               // 4 direction-batches
#define EPSV    1e-5f

// ---------------- scratch ----------------
__device__ float g_zx[(size_t)BL*DIP];
__device__ float g_xc[(size_t)BL*CONVD];
__device__ float g_dt[(size_t)NBB*SEQLEN*NH];
__device__ float g_acum[(size_t)NBB*NH*NC*CHUNK_T];
__device__ float g_csum[(size_t)NBB*NH*NC];
__device__ float g_states[(size_t)NBB*NC*NH*HD*DS];
__device__ float g_prev[(size_t)NBB*NC*NH*HD*DS];
__device__ float g_yssd[(size_t)NBB*SEQLEN*DI];
__device__ float g_dterm[(size_t)BL*NH];
__device__ __half g_uh[(size_t)BL*DM];
__device__ __half g_ynh[(size_t)BL*DI];
__device__ __half g_wah[(size_t)DIP*DM];
__device__ __half g_woh[(size_t)DM*DI];

// ---------------- helpers ----------------
__device__ __forceinline__ float softplusf(float x){
    return (x > 20.f) ? x : log1pf(expf(x));
}
__device__ __forceinline__ float siluf(float x){
    return x / (1.f + expf(-x));
}
__device__ __forceinline__ float f2tf32(float f){
    unsigned r; asm("cvt.rna.tf32.f32 %0, %1;" : "=r"(r) : "f"(f));
    return __uint_as_float(r);
}
#define MMA_TF32(acc, a, b) \
    asm volatile("mma.sync.aligned.m16n8k8.row.col.f32.tf32.tf32.f32 " \
        "{%0,%1,%2,%3},{%4,%5,%6,%7},{%8,%9},{%0,%1,%2,%3};" \
        : "+f"(acc[0]),"+f"(acc[1]),"+f"(acc[2]),"+f"(acc[3]) \
        : "r"(a[0]),"r"(a[1]),"r"(a[2]),"r"(a[3]),"r"(b[0]),"r"(b[1]))
#define MMA_F16(acc, a, b) \
    asm volatile("mma.sync.aligned.m16n8k16.row.col.f32.f16.f16.f32 " \
        "{%0,%1,%2,%3},{%4,%5,%6,%7},{%8,%9},{%0,%1,%2,%3};" \
        : "+f"(acc[0]),"+f"(acc[1]),"+f"(acc[2]),"+f"(acc[3]) \
        : "r"(a[0]),"r"(a[1]),"r"(a[2]),"r"(a[3]),"r"(b[0]),"r"(b[1]))

__device__ __forceinline__ void cp16(void* dst, const void* src, bool p){
    unsigned d = (unsigned)__cvta_generic_to_shared(dst);
    int sz = p ? 16 : 0;
    asm volatile("cp.async.cg.shared.global [%0], [%1], 16, %2;\n"
                 :: "r"(d), "l"(src), "r"(sz));
}
__device__ __forceinline__ void cp_commit(){ asm volatile("cp.async.commit_group;\n"); }
__device__ __forceinline__ void cp_wait1(){ asm volatile("cp.async.wait_group 1;\n"); }

__device__ __forceinline__ float blockReduce256(float v, float* red){
    int tid = threadIdx.x;
    red[tid] = v; __syncthreads();
    #pragma unroll
    for (int o = 128; o > 0; o >>= 1){
        if (tid < o) red[tid] += red[tid + o];
        __syncthreads();
    }
    float r = red[0];
    __syncthreads();
    return r;
}

// ---------------- 0) weight convert to fp16 ----------------
__global__ void wconv_kernel(const float* __restrict__ wi,
                             const float* __restrict__ wo){
    int i = blockIdx.x*256 + threadIdx.x;
    if (i < DIP*DM) g_wah[i] = __float2half(wi[i]);
    if (i < DM*DI)  g_woh[i] = __float2half(wo[i]);
}

// ---------------- 1) LayerNorm (emits fp16) ----------------
__global__ void ln_kernel(const float* __restrict__ x,
                          const float* __restrict__ w,
                          const float* __restrict__ b){
    __shared__ float red[256];
    int row = blockIdx.x;
    const float* xr = x + (size_t)row*DM;
    int tid = threadIdx.x;
    float s = 0.f;
    for (int i = tid; i < DM; i += 256) s += xr[i];
    float mu = blockReduce256(s, red) / DM;
    float v = 0.f;
    for (int i = tid; i < DM; i += 256){ float d = xr[i]-mu; v += d*d; }
    float var = blockReduce256(v, red) / DM;
    float inv = rsqrtf(var + EPSV);
    for (int i = tid; i < DM; i += 256)
        g_uh[(size_t)row*DM + i] = __float2half((xr[i]-mu)*inv*w[i] + b[i]);
}

// ---------------- fp16 GEMM, 3-stage cp.async, m16n8k16 ----------------
// C[M,N] = A[M,K] @ B[N,K]^T (+R), fp32 accumulate
#define SMSH 40       // halfs per smem row (32 data + 8 pad)
#define GSTH 3
__global__ __launch_bounds__(256, 2)
void gemm_h(const __half* __restrict__ A, int lda,
            const __half* __restrict__ B, int ldb,
            const float* __restrict__ R,
            float* __restrict__ C, int ldc,
            int M, int N, int K){
    extern __shared__ __half smh[];
    __half* AsB = smh;
    __half* BsB = smh + GSTH*128*SMSH;
    const int tid  = threadIdx.x;
    const int lane = tid & 31;
    const int warp = tid >> 5;
    const int wm = warp >> 2;
    const int wn = warp & 3;
    const int m0 = blockIdx.y * 128;
    const int n0 = blockIdx.x * 128;
    // loader: 512 chunks of 8 halfs per matrix; thread does chunks tid, tid+256
    const int r_a = tid >> 1;            // rows 0..127 (chunk pair trick below)
    (void)r_a;

    float acc[4][4][4];
    #pragma unroll
    for (int i=0;i<4;i++)
        #pragma unroll
        for (int j=0;j<4;j++)
            #pragma unroll
            for (int r=0;r<4;r++) acc[i][j][r]=0.f;

    const int nk = K >> 5;               // BK=32

    // chunk mapping: c in {tid, tid+256}: row=c>>2, q=c&3
    const int c0r = tid >> 2,  c0q = tid & 3;
    const int c1r = (tid+256) >> 2, c1q = tid & 3;  // (tid+256)&3 == tid&3

    const __half* ApA = A + (size_t)(m0 + c0r)*lda + c0q*8;
    const __half* ApB = A + (size_t)(m0 + c1r)*lda + c1q*8;
    const int bn0 = n0 + c0r, bn1 = n0 + c1r;
    const __half* BpA = B + (size_t)bn0*ldb + c0q*8;
    const __half* BpB = B + (size_t)bn1*ldb + c1q*8;
    const bool bokA = bn0 < N, bokB = bn1 < N;

    #pragma unroll
    for (int s = 0; s < GSTH-1; s++){
        int ko = s << 5;
        __half* as = AsB + s*(128*SMSH);
        __half* bs = BsB + s*(128*SMSH);
        cp16(as + c0r*SMSH + c0q*8, ApA + ko, true);
        cp16(as + c1r*SMSH + c1q*8, ApB + ko, true);
        cp16(bs + c0r*SMSH + c0q*8, BpA + ko, bokA);
        cp16(bs + c1r*SMSH + c1q*8, BpB + ko, bokB);
        cp_commit();
    }

    for (int kt = 0; kt < nk; kt++){
        cp_wait1();
        __syncthreads();
        int kn = kt + GSTH - 1;
        if (kn < nk){
            int ko = kn << 5;
            int stg = kn % GSTH;
            __half* as = AsB + stg*(128*SMSH);
            __half* bs = BsB + stg*(128*SMSH);
            cp16(as + c0r*SMSH + c0q*8, ApA + ko, true);
            cp16(as + c1r*SMSH + c1q*8, ApB + ko, true);
            cp16(bs + c0r*SMSH + c0q*8, BpA + ko, bokA);
            cp16(bs + c1r*SMSH + c1q*8, BpB + ko, bokB);
        }
        cp_commit();

        const __half* As = AsB + (kt % GSTH)*(128*SMSH);
        const __half* Bs = BsB + (kt % GSTH)*(128*SMSH);
        #pragma unroll
        for (int ks = 0; ks < 32; ks += 16){
            const int kq = ks + 2*(lane & 3);
            unsigned a[4][4], bfr[4][2];
            #pragma unroll
            for (int i=0;i<4;i++){
                int r = wm*64 + i*16 + (lane>>2);
                a[i][0] = *(const unsigned*)&As[r*SMSH + kq];
                a[i][1] = *(const unsigned*)&As[(r+8)*SMSH + kq];
                a[i][2] = *(const unsigned*)&As[r*SMSH + kq + 8];
                a[i][3] = *(const unsigned*)&As[(r+8)*SMSH + kq + 8];
            }
            #pragma unroll
            for (int j=0;j<4;j++){
                int cb = wn*32 + j*8 + (lane>>2);
                bfr[j][0] = *(const unsigned*)&Bs[cb*SMSH + kq];
                bfr[j][1] = *(const unsigned*)&Bs[cb*SMSH + kq + 8];
            }
            #pragma unroll
            for (int i=0;i<4;i++)
                #pragma unroll
                for (int j=0;j<4;j++) MMA_F16(acc[i][j], a[i], bfr[j]);
        }
    }

    #pragma unroll
    for (int i=0;i<4;i++){
        int r0 = m0 + wm*64 + i*16 + (lane>>2);
        #pragma unroll
        for (int j=0;j<4;j++){
            int cb = n0 + wn*32 + j*8;
            if (cb < N){
                int cc = cb + 2*(lane & 3);
                size_t o0 = (size_t)r0*ldc + cc;
                size_t o1 = (size_t)(r0+8)*ldc + cc;
                float v0 = acc[i][j][0], v1 = acc[i][j][1];
                float v2 = acc[i][j][2], v3 = acc[i][j][3];
                if (R){ v0 += R[o0]; v1 += R[o0+1]; v2 += R[o1]; v3 += R[o1+1]; }
                C[o0] = v0; C[o0+1] = v1; C[o1] = v2; C[o1+1] = v3;
            }
        }
    }
}

// ---------------- 4) tiled depthwise causal conv + SiLU ----------------
#define CTS 16
__global__ void conv_kernel(const float* __restrict__ cw,
                            const float* __restrict__ cb){
    __shared__ float s[CTS+6][128];
    __shared__ float w[7][128];
    __shared__ float bias[128];
    int ch0 = blockIdx.x * 128;
    int t0  = blockIdx.y * CTS;
    int b   = blockIdx.z;
    int tid = threadIdx.x;
    for (int i = tid; i < 7*128; i += 256){
        int j = i >> 7, ch = i & 127;
        w[j][ch] = cw[(size_t)(ch0+ch)*DCONV + j];
    }
    if (tid < 128) bias[tid] = cb[ch0 + tid];
    for (int i = tid; i < (CTS+6)*128; i += 256){
        int tt = t0 - 6 + (i >> 7);
        int ch = i & 127;
        s[i>>7][ch] = (tt >= 0) ? g_zx[(size_t)(b*SEQLEN + tt)*DIP + DI + ch0 + ch] : 0.f;
    }
    __syncthreads();
    #pragma unroll
    for (int k = 0; k < 8; k++){
        int o = tid + k*256;
        int tl = o >> 7, ch = o & 127;
        float acc = bias[ch];
        #pragma unroll
        for (int j = 0; j < 7; j++) acc += w[j][ch] * s[tl+j][ch];
        g_xc[(size_t)(b*SEQLEN + t0 + tl)*CONVD + ch0 + ch] = siluf(acc);
    }
}

// ---------------- 5) dt softplus + per-chunk cumsum fused ----------------
__global__ void cumsum_kernel(const float* __restrict__ A_log,
                              const float* __restrict__ dt_bias){
    int bid = blockIdx.x;            // ((bb*NH)+h)*NC + c
    int c = bid % NC;
    int h = (bid / NC) % NH;
    int bb = bid / (NC*NH);
    int b = bb & 1;
    bool rev = bb >= 2;
    int tid = threadIdx.x;
    float a = -expf(A_log[h]);
    int t = c*CHUNK_T + tid;
    int tg = rev ? (SEQLEN-1-t) : t;
    int col = (DIP - 2*NH) + (rev ? NH + h : h);
    float dtv = softplusf(g_zx[(size_t)(b*SEQLEN + tg)*DIP + col] + dt_bias[h]);
    g_dt[(size_t)(bb*SEQLEN + t)*NH + h] = dtv;
    float v = dtv * a;
    __shared__ float s[CHUNK_T];
    s[tid] = v; __syncthreads();
    for (int off = 1; off < CHUNK_T; off <<= 1){
        float add = (tid >= off) ? s[tid-off] : 0.f;
        __syncthreads();
        s[tid] += add;
        __syncthreads();
    }
    g_acum[(size_t)bid*CHUNK_T + tid] = s[tid];
    if (tid == CHUNK_T-1) g_csum[bid] = s[tid];
}

// ---------------- 6) chunk states (tensor cores, tf32) ----------------
#define SMT 68
__global__ void states_kernel(){
    int bid = blockIdx.x;            // (bb*NC+c)*NH + h
    int h = bid % NH;
    int c = (bid / NH) % NC;
    int bb = bid / (NH*NC);
    int b = bb & 1;
    bool rev = bb >= 2;
    int tid = threadIdx.x;
    int lane = tid & 31, warp = tid >> 5;
    int wm = warp >> 2, wn = warp & 3;
    int gid = lane >> 2, qid = lane & 3;

    __shared__ float Ab[64*SMT];
    __shared__ float Bb[64*SMT];
    __shared__ float dtl[64], decl[64];

    const float* ac = g_acum + ((size_t)(bb*NH + h)*NC + c)*CHUNK_T;
    float cs = g_csum[(bb*NH + h)*NC + c];

    float acc[2][2][4];
    #pragma unroll
    for (int i=0;i<2;i++)
        #pragma unroll
        for (int j=0;j<2;j++)
            #pragma unroll
            for (int r=0;r<4;r++) acc[i][j][r]=0.f;

    for (int ltile = 0; ltile < 4; ltile++){
        if (tid < 64){
            int lc2 = ltile*64 + tid;
            int tgl = c*CHUNK_T + lc2;
            dtl[tid] = g_dt[(size_t)(bb*SEQLEN + tgl)*NH + h];
            decl[tid] = expf(cs - ac[lc2]);
        }
        __syncthreads();
        for (int idx = tid; idx < 64*64; idx += 256){
            int l = idx >> 6, q = idx & 63;
            int tgl = c*CHUNK_T + ltile*64 + l;
            int trow = rev ? (SEQLEN-1 - tgl) : tgl;
            size_t roff = (size_t)(b*SEQLEN + trow)*CONVD;
            Ab[q*SMT + l] = f2tf32(g_xc[roff + h*HD + q] * dtl[l]);
            Bb[q*SMT + l] = f2tf32(g_xc[roff + DI + q] * decl[l]);
        }
        __syncthreads();
        #pragma unroll
        for (int ks = 0; ks < 8; ks++){
            int kb = ks*8 + qid;
            unsigned a[2][4], bf[2][2];
            #pragma unroll
            for (int i=0;i<2;i++){
                int r = wm*32 + i*16 + gid;
                a[i][0] = __float_as_uint(Ab[r*SMT + kb]);
                a[i][1] = __float_as_uint(Ab[(r+8)*SMT + kb]);
                a[i][2] = __float_as_uint(Ab[r*SMT + kb + 4]);
                a[i][3] = __float_as_uint(Ab[(r+8)*SMT + kb + 4]);
            }
            #pragma unroll
            for (int j=0;j<2;j++){
                int cb = wn*16 + j*8 + gid;
                bf[j][0] = __float_as_uint(Bb[cb*SMT + kb]);
                bf[j][1] = __float_as_uint(Bb[cb*SMT + kb + 4]);
            }
            #pragma unroll
            for (int i=0;i<2;i++)
                #pragma unroll
                for (int j=0;j<2;j++) MMA_TF32(acc[i][j], a[i], bf[j]);
        }
        __syncthreads();
    }
    float* sp = g_states + (size_t)bid*(HD*DS);
    #pragma unroll
    for (int i=0;i<2;i++){
        int p = wm*32 + i*16 + gid;
        #pragma unroll
        for (int j=0;j<2;j++){
            int n = wn*16 + j*8 + 2*qid;
            sp[p*DS + n]     = acc[i][j][0];
            sp[p*DS + n + 1] = acc[i][j][1];
            sp[(p+8)*DS + n]     = acc[i][j][2];
            sp[(p+8)*DS + n + 1] = acc[i][j][3];
        }
    }
}

// ---------------- 7) inter-chunk scan ----------------
__global__ void prevscan_kernel(){
    int bh = blockIdx.x;
    int bb = bh / NH, h = bh % NH;
    int tid = threadIdx.x;
    float run[16];
    #pragma unroll
    for (int k = 0; k < 16; k++) run[k] = 0.f;
    for (int c = 0; c < NC; c++){
        size_t off = ((size_t)(bb*NC + c)*NH + h)*(HD*DS);
        float e = expf(g_csum[bh*NC + c]);
        #pragma unroll
        for (int k = 0; k < 16; k++){
            int idx = k*256 + tid;
            g_prev[off + idx] = run[k];
            run[k] = run[k]*e + g_states[off + idx];
        }
    }
}

// ---------------- 8) Y = Y_diag + Y_off (tensor cores, tf32) ----------------
__global__ void ydiag_kernel(){
    int bid = blockIdx.x;            // ((bb*NC+c)*NH+h)*4 + lt
    int lt = bid & 3;
    int h  = (bid >> 2) % NH;
    int c  = (bid / (4*NH)) % NC;
    int bb = bid / (4*NH*NC);
    int b = bb & 1;
    bool rev = bb >= 2;
    int tid = threadIdx.x;
    int lane = tid & 31, warp = tid >> 5;
    int wm = warp >> 2, wn = warp & 3;
    int gid = lane >> 2, qid = lane & 3;

    __shared__ float Ab[64*SMT];
    __shared__ float Bb[64*SMT];
    __shared__ float acl[64], eacl[64], acs[64], dts[64];

    const float* ac = g_acum + ((size_t)(bb*NH + h)*NC + c)*CHUNK_T;

    if (tid < 64){
        float v = ac[lt*64 + tid];
        acl[tid] = v;
        eacl[tid] = expf(v);
    }
    __syncthreads();

    float acc[2][2][4];
    #pragma unroll
    for (int i=0;i<2;i++)
        #pragma unroll
        for (int j=0;j<2;j++)
            #pragma unroll
            for (int r=0;r<4;r++) acc[i][j][r]=0.f;

    // ---- Y_off
    {
        size_t poff = ((size_t)(bb*NC + c)*NH + h)*(HD*DS);
        for (int i4 = tid; i4 < 1024; i4 += 256){
            int l = i4 >> 4, c4 = (i4 & 15) * 4;
            int tgl = c*CHUNK_T + lt*64 + l;
            int trl = rev ? (SEQLEN-1 - tgl) : tgl;
            float4 cv = *(const float4*)&g_xc[(size_t)(b*SEQLEN + trl)*CONVD + DI + DS + c4];
            float e = eacl[l];
            float* d = &Ab[l*SMT + c4];
            d[0]=f2tf32(cv.x*e); d[1]=f2tf32(cv.y*e); d[2]=f2tf32(cv.z*e); d[3]=f2tf32(cv.w*e);
            float4 pv = *(const float4*)&g_prev[poff + l*64 + c4];
            float* d2 = &Bb[l*SMT + c4];
            d2[0]=f2tf32(pv.x); d2[1]=f2tf32(pv.y); d2[2]=f2tf32(pv.z); d2[3]=f2tf32(pv.w);
        }
        __syncthreads();
        #pragma unroll
        for (int ks = 0; ks < 8; ks++){
            int kb = ks*8 + qid;
            unsigned a[2][4], bf[2][2];
            #pragma unroll
            for (int i=0;i<2;i++){
                int r = wm*32 + i*16 + gid;
                a[i][0] = __float_as_uint(Ab[r*SMT + kb]);
                a[i][1] = __float_as_uint(Ab[(r+8)*SMT + kb]);
                a[i][2] = __float_as_uint(Ab[r*SMT + kb + 4]);
                a[i][3] = __float_as_uint(Ab[(r+8)*SMT + kb + 4]);
            }
            #pragma unroll
            for (int j=0;j<2;j++){
                int cb = wn*16 + j*8 + gid;
                bf[j][0] = __float_as_uint(Bb[cb*SMT + kb]);
                bf[j][1] = __float_as_uint(Bb[cb*SMT + kb + 4]);
            }
            #pragma unroll
            for (int i=0;i<2;i++)
                #pragma unroll
                for (int j=0;j<2;j++) MMA_TF32(acc[i][j], a[i], bf[j]);
        }
        __syncthreads();
    }

    // ---- Y_diag over s-tiles <= lt
    for (int st = 0; st <= lt; st++){
        if (tid < 64){
            acs[tid] = ac[st*64 + tid];
            dts[tid] = g_dt[(size_t)(bb*SEQLEN + c*CHUNK_T + st*64 + tid)*NH + h];
        }
        for (int i4 = tid; i4 < 1024; i4 += 256){
            int r = i4 >> 4, c4 = (i4 & 15) * 4;
            int tgl = c*CHUNK_T + lt*64 + r;
            int trl = rev ? (SEQLEN-1 - tgl) : tgl;
            float4 cv = *(const float4*)&g_xc[(size_t)(b*SEQLEN + trl)*CONVD + DI + DS + c4];
            float* d = &Ab[r*SMT + c4];
            d[0]=f2tf32(cv.x); d[1]=f2tf32(cv.y); d[2]=f2tf32(cv.z); d[3]=f2tf32(cv.w);
            int tgs = c*CHUNK_T + st*64 + r;
            int trs = rev ? (SEQLEN-1 - tgs) : tgs;
            float4 bv = *(const float4*)&g_xc[(size_t)(b*SEQLEN + trs)*CONVD + DI + c4];
            float* d2 = &Bb[r*SMT + c4];
            d2[0]=f2tf32(bv.x); d2[1]=f2tf32(bv.y); d2[2]=f2tf32(bv.z); d2[3]=f2tf32(bv.w);
        }
        __syncthreads();
        float g[2][2][4];
        #pragma unroll
        for (int i=0;i<2;i++)
            #pragma unroll
            for (int j=0;j<2;j++)
                #pragma unroll
                for (int r=0;r<4;r++) g[i][j][r]=0.f;
        #pragma unroll
        for (int ks = 0; ks < 8; ks++){
            int kb = ks*8 + qid;
            unsigned a[2][4], bf[2][2];
            #pragma unroll
            for (int i=0;i<2;i++){
                int r = wm*32 + i*16 + gid;
                a[i][0] = __float_as_uint(Ab[r*SMT + kb]);
                a[i][1] = __float_as_uint(Ab[(r+8)*SMT + kb]);
                a[i][2] = __float_as_uint(Ab[r*SMT + kb + 4]);
                a[i][3] = __float_as_uint(Ab[(r+8)*SMT + kb + 4]);
            }
            #pragma unroll
            for (int j=0;j<2;j++){
                int cb = wn*16 + j*8 + gid;
                bf[j][0] = __float_as_uint(Bb[cb*SMT + kb]);
                bf[j][1] = __float_as_uint(Bb[cb*SMT + kb + 4]);
            }
            #pragma unroll
            for (int i=0;i<2;i++)
                #pragma unroll
                for (int j=0;j<2;j++) MMA_TF32(g[i][j], a[i], bf[j]);
        }
        __syncthreads();
        bool diag = (st == lt);
        #pragma unroll
        for (int i=0;i<2;i++){
            int l0 = wm*32 + i*16 + gid;
            #pragma unroll
            for (int j=0;j<2;j++){
                int s0 = wn*16 + j*8 + 2*qid;
                float al0 = acl[l0], al1 = acl[l0+8];
                float w00 = (diag && s0   > l0) ? 0.f : expf(al0 - acs[s0]);
                float w01 = (diag && s0+1 > l0) ? 0.f : expf(al0 - acs[s0+1]);
                float w10 = (diag && s0   > l0+8) ? 0.f : expf(al1 - acs[s0]);
                float w11 = (diag && s0+1 > l0+8) ? 0.f : expf(al1 - acs[s0+1]);
                Ab[l0*SMT + s0]       = f2tf32(g[i][j][0]*w00);
                Ab[l0*SMT + s0+1]     = f2tf32(g[i][j][1]*w01);
                Ab[(l0+8)*SMT + s0]   = f2tf32(g[i][j][2]*w10);
                Ab[(l0+8)*SMT + s0+1] = f2tf32(g[i][j][3]*w11);
            }
        }
        for (int idx = tid; idx < 64*64; idx += 256){
            int s = idx >> 6, p = idx & 63;
            int tgs = c*CHUNK_T + st*64 + s;
            int trs = rev ? (SEQLEN-1 - tgs) : tgs;
            Bb[p*SMT + s] = f2tf32(g_xc[(size_t)(b*SEQLEN + trs)*CONVD + h*HD + p] * dts[s]);
        }
        __syncthreads();
        #pragma unroll
        for (int ks = 0; ks < 8; ks++){
            int kb = ks*8 + qid;
            unsigned a[2][4], bf[2][2];
            #pragma unroll
            for (int i=0;i<2;i++){
                int r = wm*32 + i*16 + gid;
                a[i][0] = __float_as_uint(Ab[r*SMT + kb]);
                a[i][1] = __float_as_uint(Ab[(r+8)*SMT + kb]);
                a[i][2] = __float_as_uint(Ab[r*SMT + kb + 4]);
                a[i][3] = __float_as_uint(Ab[(r+8)*SMT + kb + 4]);
            }
            #pragma unroll
            for (int j=0;j<2;j++){
                int cb = wn*16 + j*8 + gid;
                bf[j][0] = __float_as_uint(Bb[cb*SMT + kb]);
                bf[j][1] = __float_as_uint(Bb[cb*SMT + kb + 4]);
            }
            #pragma unroll
            for (int i=0;i<2;i++)
                #pragma unroll
                for (int j=0;j<2;j++) MMA_TF32(acc[i][j], a[i], bf[j]);
        }
        __syncthreads();
    }

    #pragma unroll
    for (int i=0;i<2;i++){
        int l = wm*32 + i*16 + gid;
        int tg0 = c*CHUNK_T + lt*64 + l;
        #pragma unroll
        for (int j=0;j<2;j++){
            int pc = h*HD + wn*16 + j*8 + 2*qid;
            size_t o0 = (size_t)(bb*SEQLEN + tg0)*DI + pc;
            size_t o1 = (size_t)(bb*SEQLEN + tg0 + 8)*DI + pc;
            g_yssd[o0]   = acc[i][j][0];
            g_yssd[o0+1] = acc[i][j][1];
            g_yssd[o1]   = acc[i][j][2];
            g_yssd[o1+1] = acc[i][j][3];
        }
    }
}

// ---------------- 9) fc_D ----------------
__global__ void fcd_kernel(const float* __restrict__ fw){
    __shared__ float ws[NH][132];
    int r0 = blockIdx.x * 64;
    int tid = threadIdx.x;
    int rl = tid >> 2;
    int lj = tid & 3;
    float acc[6] = {0.f,0.f,0.f,0.f,0.f,0.f};
    for (int k0 = 0; k0 < DI; k0 += 128){
        for (int i = tid; i < NH*128; i += 256)
            ws[i>>7][i&127] = fw[(size_t)(i>>7)*DI + k0 + (i&127)];
        __syncthreads();
        const float* xr = &g_xc[(size_t)(r0+rl)*CONVD + k0];
        #pragma unroll 8
        for (int kk = 0; kk < 128; kk += 4){
            float4 xv = *(const float4*)(xr + kk);
            #pragma unroll
            for (int hh = 0; hh < 6; hh++){
                int h = lj*6 + hh;
                acc[hh] += xv.x*ws[h][kk] + xv.y*ws[h][kk+1]
                         + xv.z*ws[h][kk+2] + xv.w*ws[h][kk+3];
            }
        }
        __syncthreads();
    }
    #pragma unroll
    for (int hh = 0; hh < 6; hh++)
        g_dterm[(size_t)(r0+rl)*NH + lj*6 + hh] = acc[hh];
}

// ---------------- 10) combine + gate + RMSNorm (emits fp16) ----------------
__global__ void combine_kernel(const float* __restrict__ Dv,
                               const float* __restrict__ rms_w){
    __shared__ float ybuf[DI];
    __shared__ float red[256];
    int bl = blockIdx.x;
    int b = bl / SEQLEN, t = bl % SEQLEN;
    int tid = threadIdx.x;
    float ss = 0.f;
    for (int d = tid; d < DI; d += 256){
        float yf = (t > 0) ? g_yssd[(size_t)(b*SEQLEN + t - 1)*DI + d] : 0.f;
        float yb = (t <= SEQLEN-2) ? g_yssd[(size_t)((2+b)*SEQLEN + (SEQLEN-2 - t))*DI + d] : 0.f;
        float xo = g_xc[(size_t)bl*CONVD + d];
        int h = d >> 6;
        float dterm = g_dterm[(size_t)bl*NH + h] + Dv[h];
        float z = g_zx[(size_t)bl*DIP + d];
        float y = (yf + yb + xo*dterm) * siluf(z);
        ybuf[d] = y;
        ss += y*y;
    }
    float tot = blockReduce256(ss, red);
    float inv = rsqrtf(tot/DI + EPSV);
    for (int d = tid; d < DI; d += 256)
        g_ynh[(size_t)bl*DI + d] = __float2half(ybuf[d]*inv*rms_w[d]);
}

// ---------------- launch ----------------
extern "C" void kernel_launch(void* const* d_in, const int* in_sizes, int n_in,
                              void* d_out, int out_size){
    const float* x          = (const float*)d_in[0];
    const float* ln_w       = (const float*)d_in[1];
    const float* ln_b       = (const float*)d_in[2];
    const float* in_proj_w  = (const float*)d_in[3];
    const float* conv_w     = (const float*)d_in[4];
    const float* conv_b     = (const float*)d_in[5];
    const float* dt_bias    = (const float*)d_in[6];
    const float* A_log      = (const float*)d_in[7];
    const float* Dv         = (const float*)d_in[8];
    const float* fc_D_w     = (const float*)d_in[9];
    const float* rms_w      = (const float*)d_in[10];
    const float* out_proj_w = (const float*)d_in[11];
    float* out = (float*)d_out;

    float* zx;
    __half *uh, *ynh, *wah, *woh;
    cudaGetSymbolAddress((void**)&zx,  g_zx);
    cudaGetSymbolAddress((void**)&uh,  g_uh);
    cudaGetSymbolAddress((void**)&ynh, g_ynh);
    cudaGetSymbolAddress((void**)&wah, g_wah);
    cudaGetSymbolAddress((void**)&woh, g_woh);

    static bool attr_set = false;
    const int gsmem = GSTH*2*128*SMSH*(int)sizeof(__half);   // 61440 B
    if (!attr_set){
        cudaFuncSetAttribute(gemm_h, cudaFuncAttributeMaxDynamicSharedMemorySize, gsmem);
        attr_set = true;
    }

    wconv_kernel<<<(DIP*DM + 255)/256, 256>>>(in_proj_w, out_proj_w);
    ln_kernel<<<BL, 256>>>(x, ln_w, ln_b);

    // in_proj: fp16 tensor cores
    gemm_h<<<dim3((DIP+127)/128, BL/128), 256, gsmem>>>(uh, DM, wah, DM, nullptr, zx, DIP, BL, DIP, DM);

    conv_kernel<<<dim3(CONVD/128, SEQLEN/CTS, BATCH), 256>>>(conv_w, conv_b);
    cumsum_kernel<<<NBB*NH*NC, 256>>>(A_log, dt_bias);
    states_kernel<<<NBB*NC*NH, 256>>>();
    prevscan_kernel<<<NBB*NH, 256>>>();
    ydiag_kernel<<<NBB*NC*NH*4, 256>>>();
    fcd_kernel<<<BL/64, 256>>>(fc_D_w);
    combine_kernel<<<BL, 256>>>(Dv, rms_w);

    // out_proj + residual: fp16 tensor cores
    gemm_h<<<dim3(DM/128, BL/128), 256, gsmem>>>(ynh, DI, woh, DI, x, out, DM, BL, DM, DI);
}

// round 6
// speedup vs baseline: 3.5751x; 1.0681x over previous
#include <cuda_runtime.h>
#include <cuda_fp16.h>
#include <math.h>
#include <stdint.h>

// ---------------- constants ----------------
#define BATCH   2
#define SEQLEN  4096
#define BL      (BATCH*SEQLEN)          // 8192 rows
#define DM      768
#define DI      1536
#define NH      24
#define HD      64
#define DS      64
#define DCONV   7
#define CONVD   (DI + 2*DS)             // 1664
#define DIP     (2*DI + 2*DS + 2*NH)    // 3248
#define CHUNK_T 256
#define NC      (SEQLEN/CHUNK_T)        // 16
#define NBB     (2*BATCH)               // 4 direction-batches
#define EPSV    1e-5f

// ---------------- scratch ----------------
__device__ float g_zx[(size_t)BL*DIP];
__device__ float g_xc[(size_t)BL*CONVD];
__device__ __half g_xch[(size_t)BL*CONVD];
__device__ float g_dt[(size_t)NBB*SEQLEN*NH];
__device__ float g_acum[(size_t)NBB*NH*NC*CHUNK_T];
__device__ float g_csum[(size_t)NBB*NH*NC];
__device__ float g_states[(size_t)NBB*NC*NH*HD*DS];
__device__ __half g_prevh[(size_t)NBB*NC*NH*HD*DS];
__device__ float g_yssd[(size_t)NBB*SEQLEN*DI];
__device__ float g_dterm[(size_t)BL*NH];
__device__ __half g_uh[(size_t)BL*DM];
__device__ __half g_ynh[(size_t)BL*DI];
__device__ __half g_wah[(size_t)DIP*DM];
__device__ __half g_woh[(size_t)DM*DI];

// ---------------- helpers ----------------
__device__ __forceinline__ float softplusf(float x){
    return (x > 20.f) ? x : log1pf(expf(x));
}
__device__ __forceinline__ float siluf(float x){
    return x / (1.f + expf(-x));
}
#define MMA_F16(acc, a, b) \
    asm volatile("mma.sync.aligned.m16n8k16.row.col.f32.f16.f16.f32 " \
        "{%0,%1,%2,%3},{%4,%5,%6,%7},{%8,%9},{%0,%1,%2,%3};" \
        : "+f"(acc[0]),"+f"(acc[1]),"+f"(acc[2]),"+f"(acc[3]) \
        : "r"(a[0]),"r"(a[1]),"r"(a[2]),"r"(a[3]),"r"(b[0]),"r"(b[1]))

__device__ __forceinline__ void cp16(void* dst, const void* src, bool p){
    unsigned d = (unsigned)__cvta_generic_to_shared(dst);
    int sz = p ? 16 : 0;
    asm volatile("cp.async.cg.shared.global [%0], [%1], 16, %2;\n"
                 :: "r"(d), "l"(src), "r"(sz));
}
__device__ __forceinline__ void cp_commit(){ asm volatile("cp.async.commit_group;\n"); }
__device__ __forceinline__ void cp_wait1(){ asm volatile("cp.async.wait_group 1;\n"); }

__device__ __forceinline__ float blockReduce256(float v, float* red){
    int tid = threadIdx.x;
    red[tid] = v; __syncthreads();
    #pragma unroll
    for (int o = 128; o > 0; o >>= 1){
        if (tid < o) red[tid] += red[tid + o];
        __syncthreads();
    }
    float r = red[0];
    __syncthreads();
    return r;
}

// ---------------- 0) weight convert to fp16 ----------------
__global__ void wconv_kernel(const float* __restrict__ wi,
                             const float* __restrict__ wo){
    int i = blockIdx.x*256 + threadIdx.x;
    if (i < DIP*DM) g_wah[i] = __float2half(wi[i]);
    if (i < DM*DI)  g_woh[i] = __float2half(wo[i]);
}

// ---------------- 1) LayerNorm (emits fp16) ----------------
__global__ void ln_kernel(const float* __restrict__ x,
                          const float* __restrict__ w,
                          const float* __restrict__ b){
    __shared__ float red[256];
    int row = blockIdx.x;
    const float* xr = x + (size_t)row*DM;
    int tid = threadIdx.x;
    float s = 0.f;
    for (int i = tid; i < DM; i += 256) s += xr[i];
    float mu = blockReduce256(s, red) / DM;
    float v = 0.f;
    for (int i = tid; i < DM; i += 256){ float d = xr[i]-mu; v += d*d; }
    float var = blockReduce256(v, red) / DM;
    float inv = rsqrtf(var + EPSV);
    for (int i = tid; i < DM; i += 256)
        g_uh[(size_t)row*DM + i] = __float2half((xr[i]-mu)*inv*w[i] + b[i]);
}

// ---------------- fp16 GEMM, 3-stage cp.async, m16n8k16 ----------------
#define SMSH 40
#define GSTH 3
__global__ __launch_bounds__(256, 2)
void gemm_h(const __half* __restrict__ A, int lda,
            const __half* __restrict__ B, int ldb,
            const float* __restrict__ R,
            float* __restrict__ C, int ldc,
            int M, int N, int K){
    extern __shared__ __half smh[];
    __half* AsB = smh;
    __half* BsB = smh + GSTH*128*SMSH;
    const int tid  = threadIdx.x;
    const int lane = tid & 31;
    const int warp = tid >> 5;
    const int wm = warp >> 2;
    const int wn = warp & 3;
    const int m0 = blockIdx.y * 128;
    const int n0 = blockIdx.x * 128;

    float acc[4][4][4];
    #pragma unroll
    for (int i=0;i<4;i++)
        #pragma unroll
        for (int j=0;j<4;j++)
            #pragma unroll
            for (int r=0;r<4;r++) acc[i][j][r]=0.f;

    const int nk = K >> 5;
    const int c0r = tid >> 2,  c0q = tid & 3;
    const int c1r = (tid+256) >> 2, c1q = tid & 3;

    const __half* ApA = A + (size_t)(m0 + c0r)*lda + c0q*8;
    const __half* ApB = A + (size_t)(m0 + c1r)*lda + c1q*8;
    const int bn0 = n0 + c0r, bn1 = n0 + c1r;
    const __half* BpA = B + (size_t)bn0*ldb + c0q*8;
    const __half* BpB = B + (size_t)bn1*ldb + c1q*8;
    const bool bokA = bn0 < N, bokB = bn1 < N;

    #pragma unroll
    for (int s = 0; s < GSTH-1; s++){
        int ko = s << 5;
        __half* as = AsB + s*(128*SMSH);
        __half* bs = BsB + s*(128*SMSH);
        cp16(as + c0r*SMSH + c0q*8, ApA + ko, true);
        cp16(as + c1r*SMSH + c1q*8, ApB + ko, true);
        cp16(bs + c0r*SMSH + c0q*8, BpA + ko, bokA);
        cp16(bs + c1r*SMSH + c1q*8, BpB + ko, bokB);
        cp_commit();
    }

    for (int kt = 0; kt < nk; kt++){
        cp_wait1();
        __syncthreads();
        int kn = kt + GSTH - 1;
        if (kn < nk){
            int ko = kn << 5;
            int stg = kn % GSTH;
            __half* as = AsB + stg*(128*SMSH);
            __half* bs = BsB + stg*(128*SMSH);
            cp16(as + c0r*SMSH + c0q*8, ApA + ko, true);
            cp16(as + c1r*SMSH + c1q*8, ApB + ko, true);
            cp16(bs + c0r*SMSH + c0q*8, BpA + ko, bokA);
            cp16(bs + c1r*SMSH + c1q*8, BpB + ko, bokB);
        }
        cp_commit();

        const __half* As = AsB + (kt % GSTH)*(128*SMSH);
        const __half* Bs = BsB + (kt % GSTH)*(128*SMSH);
        #pragma unroll
        for (int ks = 0; ks < 32; ks += 16){
            const int kq = ks + 2*(lane & 3);
            unsigned a[4][4], bfr[4][2];
            #pragma unroll
            for (int i=0;i<4;i++){
                int r = wm*64 + i*16 + (lane>>2);
                a[i][0] = *(const unsigned*)&As[r*SMSH + kq];
                a[i][1] = *(const unsigned*)&As[(r+8)*SMSH + kq];
                a[i][2] = *(const unsigned*)&As[r*SMSH + kq + 8];
                a[i][3] = *(const unsigned*)&As[(r+8)*SMSH + kq + 8];
            }
            #pragma unroll
            for (int j=0;j<4;j++){
                int cb = wn*32 + j*8 + (lane>>2);
                bfr[j][0] = *(const unsigned*)&Bs[cb*SMSH + kq];
                bfr[j][1] = *(const unsigned*)&Bs[cb*SMSH + kq + 8];
            }
            #pragma unroll
            for (int i=0;i<4;i++)
                #pragma unroll
                for (int j=0;j<4;j++) MMA_F16(acc[i][j], a[i], bfr[j]);
        }
    }

    #pragma unroll
    for (int i=0;i<4;i++){
        int r0 = m0 + wm*64 + i*16 + (lane>>2);
        #pragma unroll
        for (int j=0;j<4;j++){
            int cb = n0 + wn*32 + j*8;
            if (cb < N){
                int cc = cb + 2*(lane & 3);
                size_t o0 = (size_t)r0*ldc + cc;
                size_t o1 = (size_t)(r0+8)*ldc + cc;
                float v0 = acc[i][j][0], v1 = acc[i][j][1];
                float v2 = acc[i][j][2], v3 = acc[i][j][3];
                if (R){ v0 += R[o0]; v1 += R[o0+1]; v2 += R[o1]; v3 += R[o1+1]; }
                C[o0] = v0; C[o0+1] = v1; C[o1] = v2; C[o1+1] = v3;
            }
        }
    }
}

// ---------------- 4) tiled depthwise causal conv + SiLU (emits f32 + f16) ----
#define CTS 16
__global__ void conv_kernel(const float* __restrict__ cw,
                            const float* __restrict__ cb){
    __shared__ float s[CTS+6][128];
    __shared__ float w[7][128];
    __shared__ float bias[128];
    int ch0 = blockIdx.x * 128;
    int t0  = blockIdx.y * CTS;
    int b   = blockIdx.z;
    int tid = threadIdx.x;
    for (int i = tid; i < 7*128; i += 256){
        int j = i >> 7, ch = i & 127;
        w[j][ch] = cw[(size_t)(ch0+ch)*DCONV + j];
    }
    if (tid < 128) bias[tid] = cb[ch0 + tid];
    for (int i = tid; i < (CTS+6)*128; i += 256){
        int tt = t0 - 6 + (i >> 7);
        int ch = i & 127;
        s[i>>7][ch] = (tt >= 0) ? g_zx[(size_t)(b*SEQLEN + tt)*DIP + DI + ch0 + ch] : 0.f;
    }
    __syncthreads();
    #pragma unroll
    for (int k = 0; k < 8; k++){
        int o = tid + k*256;
        int tl = o >> 7, ch = o & 127;
        float acc = bias[ch];
        #pragma unroll
        for (int j = 0; j < 7; j++) acc += w[j][ch] * s[tl+j][ch];
        float v = siluf(acc);
        size_t off = (size_t)(b*SEQLEN + t0 + tl)*CONVD + ch0 + ch;
        g_xc[off] = v;
        g_xch[off] = __float2half(v);
    }
}

// ---------------- 5) dt softplus + per-chunk cumsum fused ----------------
__global__ void cumsum_kernel(const float* __restrict__ A_log,
                              const float* __restrict__ dt_bias){
    int bid = blockIdx.x;            // ((bb*NH)+h)*NC + c
    int c = bid % NC;
    int h = (bid / NC) % NH;
    int bb = bid / (NC*NH);
    int b = bb & 1;
    bool rev = bb >= 2;
    int tid = threadIdx.x;
    float a = -expf(A_log[h]);
    int t = c*CHUNK_T + tid;
    int tg = rev ? (SEQLEN-1-t) : t;
    int col = (DIP - 2*NH) + (rev ? NH + h : h);
    float dtv = softplusf(g_zx[(size_t)(b*SEQLEN + tg)*DIP + col] + dt_bias[h]);
    g_dt[(size_t)(bb*SEQLEN + t)*NH + h] = dtv;
    float v = dtv * a;
    __shared__ float s[CHUNK_T];
    s[tid] = v; __syncthreads();
    for (int off = 1; off < CHUNK_T; off <<= 1){
        float add = (tid >= off) ? s[tid-off] : 0.f;
        __syncthreads();
        s[tid] += add;
        __syncthreads();
    }
    g_acum[(size_t)bid*CHUNK_T + tid] = s[tid];
    if (tid == CHUNK_T-1) g_csum[bid] = s[tid];
}

// ---------------- 6) chunk states (fp16 tensor cores) ----------------
// S[p,n] = sum_l (X[l,p]*dt[l]) * (B[l,n]*dec[l]),  K=256
#define SMH 72
__global__ void states_kernel(){
    int bid = blockIdx.x;            // (bb*NC+c)*NH + h
    int h = bid % NH;
    int c = (bid / NH) % NC;
    int bb = bid / (NH*NC);
    int b = bb & 1;
    bool rev = bb >= 2;
    int tid = threadIdx.x;
    int lane = tid & 31, warp = tid >> 5;
    int wm = warp >> 2, wn = warp & 3;
    int gid = lane >> 2, qid = lane & 3;

    __shared__ __half Ab[64*SMH];    // Xt[p][l]
    __shared__ __half Bb[64*SMH];    // Bt[n][l]
    __shared__ float dtl[64], decl[64];

    const float* ac = g_acum + ((size_t)(bb*NH + h)*NC + c)*CHUNK_T;
    float cs = g_csum[(bb*NH + h)*NC + c];

    float acc[2][2][4];
    #pragma unroll
    for (int i=0;i<2;i++)
        #pragma unroll
        for (int j=0;j<2;j++)
            #pragma unroll
            for (int r=0;r<4;r++) acc[i][j][r]=0.f;

    for (int ltile = 0; ltile < 4; ltile++){
        if (tid < 64){
            int lc2 = ltile*64 + tid;
            int tgl = c*CHUNK_T + lc2;
            dtl[tid] = g_dt[(size_t)(bb*SEQLEN + tgl)*NH + h];
            decl[tid] = expf(cs - ac[lc2]);
        }
        __syncthreads();
        for (int idx = tid; idx < 64*64; idx += 256){
            int l = idx >> 6, q = idx & 63;
            int tgl = c*CHUNK_T + ltile*64 + l;
            int trow = rev ? (SEQLEN-1 - tgl) : tgl;
            size_t roff = (size_t)(b*SEQLEN + trow)*CONVD;
            float xv = __half2float(g_xch[roff + h*HD + q]);
            float bv = __half2float(g_xch[roff + DI + q]);
            Ab[q*SMH + l] = __float2half(xv * dtl[l]);
            Bb[q*SMH + l] = __float2half(bv * decl[l]);
        }
        __syncthreads();
        #pragma unroll
        for (int ks = 0; ks < 64; ks += 16){
            int kq = ks + 2*qid;
            unsigned a[2][4], bf[2][2];
            #pragma unroll
            for (int i=0;i<2;i++){
                int r = wm*32 + i*16 + gid;
                a[i][0] = *(const unsigned*)&Ab[r*SMH + kq];
                a[i][1] = *(const unsigned*)&Ab[(r+8)*SMH + kq];
                a[i][2] = *(const unsigned*)&Ab[r*SMH + kq + 8];
                a[i][3] = *(const unsigned*)&Ab[(r+8)*SMH + kq + 8];
            }
            #pragma unroll
            for (int j=0;j<2;j++){
                int cb = wn*16 + j*8 + gid;
                bf[j][0] = *(const unsigned*)&Bb[cb*SMH + kq];
                bf[j][1] = *(const unsigned*)&Bb[cb*SMH + kq + 8];
            }
            #pragma unroll
            for (int i=0;i<2;i++)
                #pragma unroll
                for (int j=0;j<2;j++) MMA_F16(acc[i][j], a[i], bf[j]);
        }
        __syncthreads();
    }
    float* sp = g_states + (size_t)bid*(HD*DS);
    #pragma unroll
    for (int i=0;i<2;i++){
        int p = wm*32 + i*16 + gid;
        #pragma unroll
        for (int j=0;j<2;j++){
            int n = wn*16 + j*8 + 2*qid;
            sp[p*DS + n]     = acc[i][j][0];
            sp[p*DS + n + 1] = acc[i][j][1];
            sp[(p+8)*DS + n]     = acc[i][j][2];
            sp[(p+8)*DS + n + 1] = acc[i][j][3];
        }
    }
}

// ---------------- 7) inter-chunk scan (fp32 recurrence, fp16 output) --------
__global__ void prevscan_kernel(){
    int bh = blockIdx.x;
    int bb = bh / NH, h = bh % NH;
    int tid = threadIdx.x;
    float run[16];
    #pragma unroll
    for (int k = 0; k < 16; k++) run[k] = 0.f;
    for (int c = 0; c < NC; c++){
        size_t off = ((size_t)(bb*NC + c)*NH + h)*(HD*DS);
        float e = expf(g_csum[bh*NC + c]);
        #pragma unroll
        for (int k = 0; k < 16; k++){
            int idx = k*256 + tid;
            g_prevh[off + idx] = __float2half(run[k]);
            run[k] = run[k]*e + g_states[off + idx];
        }
    }
}

// ---------------- 8) Y = Y_diag + Y_off (fp16 tensor cores) ----------------
__global__ void ydiag_kernel(){
    int bid = blockIdx.x;            // ((bb*NC+c)*NH+h)*4 + lt
    int lt = bid & 3;
    int h  = (bid >> 2) % NH;
    int c  = (bid / (4*NH)) % NC;
    int bb = bid / (4*NH*NC);
    int b = bb & 1;
    bool rev = bb >= 2;
    int tid = threadIdx.x;
    int lane = tid & 31, warp = tid >> 5;
    int wm = warp >> 2, wn = warp & 3;
    int gid = lane >> 2, qid = lane & 3;

    __shared__ __half Ab[64*SMH];
    __shared__ __half Bb[64*SMH];
    __shared__ float acl[64], eacl[64], acs[64], dts[64];

    const float* ac = g_acum + ((size_t)(bb*NH + h)*NC + c)*CHUNK_T;

    if (tid < 64){
        float v = ac[lt*64 + tid];
        acl[tid] = v;
        eacl[tid] = expf(v);
    }
    __syncthreads();

    float acc[2][2][4];
    #pragma unroll
    for (int i=0;i<2;i++)
        #pragma unroll
        for (int j=0;j<2;j++)
            #pragma unroll
            for (int r=0;r<4;r++) acc[i][j][r]=0.f;

    // ---- Y_off: acc[l,p] += sum_n (C[l,n]*eacl[l]) * prev[p,n]
    {
        size_t poff = ((size_t)(bb*NC + c)*NH + h)*(HD*DS);
        for (int i2 = tid; i2 < 2048; i2 += 256){
            int l = i2 >> 5, c2 = (i2 & 31) * 2;
            int tgl = c*CHUNK_T + lt*64 + l;
            int trl = rev ? (SEQLEN-1 - tgl) : tgl;
            __half2 cv = *(const __half2*)&g_xch[(size_t)(b*SEQLEN + trl)*CONVD + DI + DS + c2];
            float2 cf = __half22float2(cv);
            float e = eacl[l];
            *(__half2*)&Ab[l*SMH + c2] = __floats2half2_rn(cf.x*e, cf.y*e);
            *(__half2*)&Bb[l*SMH + c2] = *(const __half2*)&g_prevh[poff + l*64 + c2];
        }
        __syncthreads();
        #pragma unroll
        for (int ks = 0; ks < 64; ks += 16){
            int kq = ks + 2*qid;
            unsigned a[2][4], bf[2][2];
            #pragma unroll
            for (int i=0;i<2;i++){
                int r = wm*32 + i*16 + gid;
                a[i][0] = *(const unsigned*)&Ab[r*SMH + kq];
                a[i][1] = *(const unsigned*)&Ab[(r+8)*SMH + kq];
                a[i][2] = *(const unsigned*)&Ab[r*SMH + kq + 8];
                a[i][3] = *(const unsigned*)&Ab[(r+8)*SMH + kq + 8];
            }
            #pragma unroll
            for (int j=0;j<2;j++){
                int cb = wn*16 + j*8 + gid;
                bf[j][0] = *(const unsigned*)&Bb[cb*SMH + kq];
                bf[j][1] = *(const unsigned*)&Bb[cb*SMH + kq + 8];
            }
            #pragma unroll
            for (int i=0;i<2;i++)
                #pragma unroll
                for (int j=0;j<2;j++) MMA_F16(acc[i][j], a[i], bf[j]);
        }
        __syncthreads();
    }

    // ---- Y_diag over s-tiles <= lt
    for (int st = 0; st <= lt; st++){
        if (tid < 64){
            acs[tid] = ac[st*64 + tid];
            dts[tid] = g_dt[(size_t)(bb*SEQLEN + c*CHUNK_T + st*64 + tid)*NH + h];
        }
        for (int i2 = tid; i2 < 2048; i2 += 256){
            int r = i2 >> 5, c2 = (i2 & 31) * 2;
            int tgl = c*CHUNK_T + lt*64 + r;
            int trl = rev ? (SEQLEN-1 - tgl) : tgl;
            *(__half2*)&Ab[r*SMH + c2] =
                *(const __half2*)&g_xch[(size_t)(b*SEQLEN + trl)*CONVD + DI + DS + c2];
            int tgs = c*CHUNK_T + st*64 + r;
            int trs = rev ? (SEQLEN-1 - tgs) : tgs;
            *(__half2*)&Bb[r*SMH + c2] =
                *(const __half2*)&g_xch[(size_t)(b*SEQLEN + trs)*CONVD + DI + c2];
        }
        __syncthreads();
        // G[l,s] = C . Bm^T
        float g[2][2][4];
        #pragma unroll
        for (int i=0;i<2;i++)
            #pragma unroll
            for (int j=0;j<2;j++)
                #pragma unroll
                for (int r=0;r<4;r++) g[i][j][r]=0.f;
        #pragma unroll
        for (int ks = 0; ks < 64; ks += 16){
            int kq = ks + 2*qid;
            unsigned a[2][4], bf[2][2];
            #pragma unroll
            for (int i=0;i<2;i++){
                int r = wm*32 + i*16 + gid;
                a[i][0] = *(const unsigned*)&Ab[r*SMH + kq];
                a[i][1] = *(const unsigned*)&Ab[(r+8)*SMH + kq];
                a[i][2] = *(const unsigned*)&Ab[r*SMH + kq + 8];
                a[i][3] = *(const unsigned*)&Ab[(r+8)*SMH + kq + 8];
            }
            #pragma unroll
            for (int j=0;j<2;j++){
                int cb = wn*16 + j*8 + gid;
                bf[j][0] = *(const unsigned*)&Bb[cb*SMH + kq];
                bf[j][1] = *(const unsigned*)&Bb[cb*SMH + kq + 8];
            }
            #pragma unroll
            for (int i=0;i<2;i++)
                #pragma unroll
                for (int j=0;j<2;j++) MMA_F16(g[i][j], a[i], bf[j]);
        }
        __syncthreads();
        bool diag = (st == lt);
        #pragma unroll
        for (int i=0;i<2;i++){
            int l0 = wm*32 + i*16 + gid;
            #pragma unroll
            for (int j=0;j<2;j++){
                int s0 = wn*16 + j*8 + 2*qid;
                float al0 = acl[l0], al1 = acl[l0+8];
                float w00 = (diag && s0   > l0) ? 0.f : expf(al0 - acs[s0]);
                float w01 = (diag && s0+1 > l0) ? 0.f : expf(al0 - acs[s0+1]);
                float w10 = (diag && s0   > l0+8) ? 0.f : expf(al1 - acs[s0]);
                float w11 = (diag && s0+1 > l0+8) ? 0.f : expf(al1 - acs[s0+1]);
                Ab[l0*SMH + s0]       = __float2half(g[i][j][0]*w00);
                Ab[l0*SMH + s0+1]     = __float2half(g[i][j][1]*w01);
                Ab[(l0+8)*SMH + s0]   = __float2half(g[i][j][2]*w10);
                Ab[(l0+8)*SMH + s0+1] = __float2half(g[i][j][3]*w11);
            }
        }
        for (int idx = tid; idx < 64*64; idx += 256){
            int s = idx >> 6, p = idx & 63;
            int tgs = c*CHUNK_T + st*64 + s;
            int trs = rev ? (SEQLEN-1 - tgs) : tgs;
            float xv = __half2float(g_xch[(size_t)(b*SEQLEN + trs)*CONVD + h*HD + p]);
            Bb[p*SMH + s] = __float2half(xv * dts[s]);
        }
        __syncthreads();
        #pragma unroll
        for (int ks = 0; ks < 64; ks += 16){
            int kq = ks + 2*qid;
            unsigned a[2][4], bf[2][2];
            #pragma unroll
            for (int i=0;i<2;i++){
                int r = wm*32 + i*16 + gid;
                a[i][0] = *(const unsigned*)&Ab[r*SMH + kq];
                a[i][1] = *(const unsigned*)&Ab[(r+8)*SMH + kq];
                a[i][2] = *(const unsigned*)&Ab[r*SMH + kq + 8];
                a[i][3] = *(const unsigned*)&Ab[(r+8)*SMH + kq + 8];
            }
            #pragma unroll
            for (int j=0;j<2;j++){
                int cb = wn*16 + j*8 + gid;
                bf[j][0] = *(const unsigned*)&Bb[cb*SMH + kq];
                bf[j][1] = *(const unsigned*)&Bb[cb*SMH + kq + 8];
            }
            #pragma unroll
            for (int i=0;i<2;i++)
                #pragma unroll
                for (int j=0;j<2;j++) MMA_F16(acc[i][j], a[i], bf[j]);
        }
        __syncthreads();
    }

    #pragma unroll
    for (int i=0;i<2;i++){
        int l = wm*32 + i*16 + gid;
        int tg0 = c*CHUNK_T + lt*64 + l;
        #pragma unroll
        for (int j=0;j<2;j++){
            int pc = h*HD + wn*16 + j*8 + 2*qid;
            size_t o0 = (size_t)(bb*SEQLEN + tg0)*DI + pc;
            size_t o1 = (size_t)(bb*SEQLEN + tg0 + 8)*DI + pc;
            g_yssd[o0]   = acc[i][j][0];
            g_yssd[o0+1] = acc[i][j][1];
            g_yssd[o1]   = acc[i][j][2];
            g_yssd[o1+1] = acc[i][j][3];
        }
    }
}

// ---------------- 9) fc_D ----------------
__global__ void fcd_kernel(const float* __restrict__ fw){
    __shared__ float ws[NH][132];
    int r0 = blockIdx.x * 64;
    int tid = threadIdx.x;
    int rl = tid >> 2;
    int lj = tid & 3;
    float acc[6] = {0.f,0.f,0.f,0.f,0.f,0.f};
    for (int k0 = 0; k0 < DI; k0 += 128){
        for (int i = tid; i < NH*128; i += 256)
            ws[i>>7][i&127] = fw[(size_t)(i>>7)*DI + k0 + (i&127)];
        __syncthreads();
        const float* xr = &g_xc[(size_t)(r0+rl)*CONVD + k0];
        #pragma unroll 8
        for (int kk = 0; kk < 128; kk += 4){
            float4 xv = *(const float4*)(xr + kk);
            #pragma unroll
            for (int hh = 0; hh < 6; hh++){
                int h = lj*6 + hh;
                acc[hh] += xv.x*ws[h][kk] + xv.y*ws[h][kk+1]
                         + xv.z*ws[h][kk+2] + xv.w*ws[h][kk+3];
            }
        }
        __syncthreads();
    }
    #pragma unroll
    for (int hh = 0; hh < 6; hh++)
        g_dterm[(size_t)(r0+rl)*NH + lj*6 + hh] = acc[hh];
}

// ---------------- 10) combine + gate + RMSNorm (emits fp16) ----------------
__global__ void combine_kernel(const float* __restrict__ Dv,
                               const float* __restrict__ rms_w){
    __shared__ float ybuf[DI];
    __shared__ float red[256];
    int bl = blockIdx.x;
    int b = bl / SEQLEN, t = bl % SEQLEN;
    int tid = threadIdx.x;
    float ss = 0.f;
    for (int d = tid; d < DI; d += 256){
        float yf = (t > 0) ? g_yssd[(size_t)(b*SEQLEN + t - 1)*DI + d] : 0.f;
        float yb = (t <= SEQLEN-2) ? g_yssd[(size_t)((2+b)*SEQLEN + (SEQLEN-2 - t))*DI + d] : 0.f;
        float xo = g_xc[(size_t)bl*CONVD + d];
        int h = d >> 6;
        float dterm = g_dterm[(size_t)bl*NH + h] + Dv[h];
        float z = g_zx[(size_t)bl*DIP + d];
        float y = (yf + yb + xo*dterm) * siluf(z);
        ybuf[d] = y;
        ss += y*y;
    }
    float tot = blockReduce256(ss, red);
    float inv = rsqrtf(tot/DI + EPSV);
    for (int d = tid; d < DI; d += 256)
        g_ynh[(size_t)bl*DI + d] = __float2half(ybuf[d]*inv*rms_w[d]);
}

// ---------------- launch ----------------
extern "C" void kernel_launch(void* const* d_in, const int* in_sizes, int n_in,
                              void* d_out, int out_size){
    const float* x          = (const float*)d_in[0];
    const float* ln_w       = (const float*)d_in[1];
    const float* ln_b       = (const float*)d_in[2];
    const float* in_proj_w  = (const float*)d_in[3];
    const float* conv_w     = (const float*)d_in[4];
    const float* conv_b     = (const float*)d_in[5];
    const float* dt_bias    = (const float*)d_in[6];
    const float* A_log      = (const float*)d_in[7];
    const float* Dv         = (const float*)d_in[8];
    const float* fc_D_w     = (const float*)d_in[9];
    const float* rms_w      = (const float*)d_in[10];
    const float* out_proj_w = (const float*)d_in[11];
    float* out = (float*)d_out;

    float* zx;
    __half *uh, *ynh, *wah, *woh;
    cudaGetSymbolAddress((void**)&zx,  g_zx);
    cudaGetSymbolAddress((void**)&uh,  g_uh);
    cudaGetSymbolAddress((void**)&ynh, g_ynh);
    cudaGetSymbolAddress((void**)&wah, g_wah);
    cudaGetSymbolAddress((void**)&woh, g_woh);

    static bool attr_set = false;
    const int gsmem = GSTH*2*128*SMSH*(int)sizeof(__half);   // 61440 B
    if (!attr_set){
        cudaFuncSetAttribute(gemm_h, cudaFuncAttributeMaxDynamicSharedMemorySize, gsmem);
        attr_set = true;
    }

    wconv_kernel<<<(DIP*DM + 255)/256, 256>>>(in_proj_w, out_proj_w);
    ln_kernel<<<BL, 256>>>(x, ln_w, ln_b);

    // in_proj
    gemm_h<<<dim3((DIP+127)/128, BL/128), 256, gsmem>>>(uh, DM, wah, DM, nullptr, zx, DIP, BL, DIP, DM);

    conv_kernel<<<dim3(CONVD/128, SEQLEN/CTS, BATCH), 256>>>(conv_w, conv_b);
    cumsum_kernel<<<NBB*NH*NC, 256>>>(A_log, dt_bias);
    states_kernel<<<NBB*NC*NH, 256>>>();
    prevscan_kernel<<<NBB*NH, 256>>>();
    ydiag_kernel<<<NBB*NC*NH*4, 256>>>();
    fcd_kernel<<<BL/64, 256>>>(fc_D_w);
    combine_kernel<<<BL, 256>>>(Dv, rms_w);

    // out_proj + residual
    gemm_h<<<dim3(DM/128, BL/128), 256, gsmem>>>(ynh, DI, woh, DI, x, out, DM, BL, DM, DI);
}

// round 7
// speedup vs baseline: 3.8917x; 1.0886x over previous
#include <cuda_runtime.h>
#include <cuda_fp16.h>
#include <math.h>
#include <stdint.h>

// ---------------- constants ----------------
#define BATCH   2
#define SEQLEN  4096
#define BL      (BATCH*SEQLEN)          // 8192 rows
#define DM      768
#define DI      1536
#define NH      24
#define HD      64
#define DS      64
#define DCONV   7
#define CONVD   (DI + 2*DS)             // 1664
#define DIP     (2*DI + 2*DS + 2*NH)    // 3248
#define CHUNK_T 256
#define NC      (SEQLEN/CHUNK_T)        // 16
#define NBB     (2*BATCH)               // 4 direction-batches
#define EPSV    1e-5f

// ---------------- scratch ----------------
__device__ __half g_zxh[(size_t)BL*DIP];
__device__ __half g_xch[(size_t)BL*CONVD];
__device__ float g_dt[(size_t)NBB*SEQLEN*NH];
__device__ float g_acum[(size_t)NBB*NH*NC*CHUNK_T];
__device__ float g_csum[(size_t)NBB*NH*NC];
__device__ float g_states[(size_t)NBB*NC*NH*HD*DS];
__device__ __half g_prevh[(size_t)NBB*NC*NH*HD*DS];
__device__ __half g_yssdh[(size_t)NBB*SEQLEN*DI];
__device__ float g_dterm[(size_t)BL*NH];
__device__ __half g_uh[(size_t)BL*DM];
__device__ __half g_ynh[(size_t)BL*DI];
__device__ __half g_wah[(size_t)DIP*DM];
__device__ __half g_woh[(size_t)DM*DI];

// ---------------- helpers ----------------
__device__ __forceinline__ float softplusf(float x){
    return (x > 20.f) ? x : log1pf(expf(x));
}
__device__ __forceinline__ float siluf(float x){
    return x / (1.f + expf(-x));
}
#define MMA_F16(acc, a, b) \
    asm volatile("mma.sync.aligned.m16n8k16.row.col.f32.f16.f16.f32 " \
        "{%0,%1,%2,%3},{%4,%5,%6,%7},{%8,%9},{%0,%1,%2,%3};" \
        : "+f"(acc[0]),"+f"(acc[1]),"+f"(acc[2]),"+f"(acc[3]) \
        : "r"(a[0]),"r"(a[1]),"r"(a[2]),"r"(a[3]),"r"(b[0]),"r"(b[1]))

__device__ __forceinline__ void ldsm4(unsigned* r, const __half* p){
    unsigned a = (unsigned)__cvta_generic_to_shared(p);
    asm volatile("ldmatrix.sync.aligned.m8n8.x4.shared.b16 {%0,%1,%2,%3}, [%4];"
        : "=r"(r[0]),"=r"(r[1]),"=r"(r[2]),"=r"(r[3]) : "r"(a));
}

__device__ __forceinline__ void cp16(void* dst, const void* src, bool p){
    unsigned d = (unsigned)__cvta_generic_to_shared(dst);
    int sz = p ? 16 : 0;
    asm volatile("cp.async.cg.shared.global [%0], [%1], 16, %2;\n"
                 :: "r"(d), "l"(src), "r"(sz));
}
__device__ __forceinline__ void cp_commit(){ asm volatile("cp.async.commit_group;\n"); }
__device__ __forceinline__ void cp_wait1(){ asm volatile("cp.async.wait_group 1;\n"); }

__device__ __forceinline__ float blockReduce256(float v, float* red){
    int tid = threadIdx.x;
    red[tid] = v; __syncthreads();
    #pragma unroll
    for (int o = 128; o > 0; o >>= 1){
        if (tid < o) red[tid] += red[tid + o];
        __syncthreads();
    }
    float r = red[0];
    __syncthreads();
    return r;
}

// ---------------- 0) weight convert to fp16 ----------------
__global__ void wconv_kernel(const float* __restrict__ wi,
                             const float* __restrict__ wo){
    int i = blockIdx.x*256 + threadIdx.x;
    if (i < DIP*DM) g_wah[i] = __float2half(wi[i]);
    if (i < DM*DI)  g_woh[i] = __float2half(wo[i]);
}

// ---------------- 1) LayerNorm (emits fp16) ----------------
__global__ void ln_kernel(const float* __restrict__ x,
                          const float* __restrict__ w,
                          const float* __restrict__ b){
    __shared__ float red[256];
    int row = blockIdx.x;
    const float* xr = x + (size_t)row*DM;
    int tid = threadIdx.x;
    float s = 0.f;
    for (int i = tid; i < DM; i += 256) s += xr[i];
    float mu = blockReduce256(s, red) / DM;
    float v = 0.f;
    for (int i = tid; i < DM; i += 256){ float d = xr[i]-mu; v += d*d; }
    float var = blockReduce256(v, red) / DM;
    float inv = rsqrtf(var + EPSV);
    for (int i = tid; i < DM; i += 256)
        g_uh[(size_t)row*DM + i] = __float2half((xr[i]-mu)*inv*w[i] + b[i]);
}

// ---------------- fp16 GEMM, 3-stage cp.async, m16n8k16, ldmatrix ----------
// C[M,N] = A[M,K] @ B[N,K]^T.  Output: Ch (half) if non-null else C (+R) fp32.
#define SMSH 40
#define GSTH 3
__global__ __launch_bounds__(256, 2)
void gemm_h(const __half* __restrict__ A, int lda,
            const __half* __restrict__ B, int ldb,
            const float* __restrict__ R,
            float* __restrict__ C, __half* __restrict__ Ch, int ldc,
            int M, int N, int K){
    extern __shared__ __half smh[];
    __half* AsB = smh;
    __half* BsB = smh + GSTH*128*SMSH;
    const int tid  = threadIdx.x;
    const int lane = tid & 31;
    const int warp = tid >> 5;
    const int wm = warp >> 2;
    const int wn = warp & 3;
    const int m0 = blockIdx.y * 128;
    const int n0 = blockIdx.x * 128;
    const int rowsel = lane & 15;
    const int koffA  = (lane >> 4) * 8;
    const int nsel   = (lane & 7) + ((lane >> 4) * 8);
    const int koffB  = ((lane >> 3) & 1) * 8;

    float acc[4][4][4];
    #pragma unroll
    for (int i=0;i<4;i++)
        #pragma unroll
        for (int j=0;j<4;j++)
            #pragma unroll
            for (int r=0;r<4;r++) acc[i][j][r]=0.f;

    const int nk = K >> 5;
    const int c0r = tid >> 2,  c0q = tid & 3;
    const int c1r = (tid+256) >> 2, c1q = tid & 3;

    const __half* ApA = A + (size_t)(m0 + c0r)*lda + c0q*8;
    const __half* ApB = A + (size_t)(m0 + c1r)*lda + c1q*8;
    const int bn0 = n0 + c0r, bn1 = n0 + c1r;
    const __half* BpA = B + (size_t)bn0*ldb + c0q*8;
    const __half* BpB = B + (size_t)bn1*ldb + c1q*8;
    const bool bokA = bn0 < N, bokB = bn1 < N;

    #pragma unroll
    for (int s = 0; s < GSTH-1; s++){
        int ko = s << 5;
        __half* as = AsB + s*(128*SMSH);
        __half* bs = BsB + s*(128*SMSH);
        cp16(as + c0r*SMSH + c0q*8, ApA + ko, true);
        cp16(as + c1r*SMSH + c1q*8, ApB + ko, true);
        cp16(bs + c0r*SMSH + c0q*8, BpA + ko, bokA);
        cp16(bs + c1r*SMSH + c1q*8, BpB + ko, bokB);
        cp_commit();
    }

    for (int kt = 0; kt < nk; kt++){
        cp_wait1();
        __syncthreads();
        int kn = kt + GSTH - 1;
        if (kn < nk){
            int ko = kn << 5;
            int stg = kn % GSTH;
            __half* as = AsB + stg*(128*SMSH);
            __half* bs = BsB + stg*(128*SMSH);
            cp16(as + c0r*SMSH + c0q*8, ApA + ko, true);
            cp16(as + c1r*SMSH + c1q*8, ApB + ko, true);
            cp16(bs + c0r*SMSH + c0q*8, BpA + ko, bokA);
            cp16(bs + c1r*SMSH + c1q*8, BpB + ko, bokB);
        }
        cp_commit();

        const __half* As = AsB + (kt % GSTH)*(128*SMSH);
        const __half* Bs = BsB + (kt % GSTH)*(128*SMSH);
        #pragma unroll
        for (int ks = 0; ks < 32; ks += 16){
            unsigned a[4][4], bfr[4][2];
            #pragma unroll
            for (int i=0;i<4;i++)
                ldsm4(a[i], As + (wm*64 + i*16 + rowsel)*SMSH + ks + koffA);
            {
                unsigned t0[4], t1[4];
                ldsm4(t0, Bs + (wn*32 + nsel)*SMSH + ks + koffB);
                ldsm4(t1, Bs + (wn*32 + 16 + nsel)*SMSH + ks + koffB);
                bfr[0][0]=t0[0]; bfr[0][1]=t0[1]; bfr[1][0]=t0[2]; bfr[1][1]=t0[3];
                bfr[2][0]=t1[0]; bfr[2][1]=t1[1]; bfr[3][0]=t1[2]; bfr[3][1]=t1[3];
            }
            #pragma unroll
            for (int i=0;i<4;i++)
                #pragma unroll
                for (int j=0;j<4;j++) MMA_F16(acc[i][j], a[i], bfr[j]);
        }
    }

    #pragma unroll
    for (int i=0;i<4;i++){
        int r0 = m0 + wm*64 + i*16 + (lane>>2);
        #pragma unroll
        for (int j=0;j<4;j++){
            int cb = n0 + wn*32 + j*8;
            if (cb < N){
                int cc = cb + 2*(lane & 3);
                size_t o0 = (size_t)r0*ldc + cc;
                size_t o1 = (size_t)(r0+8)*ldc + cc;
                if (Ch){
                    *(__half2*)&Ch[o0] = __floats2half2_rn(acc[i][j][0], acc[i][j][1]);
                    *(__half2*)&Ch[o1] = __floats2half2_rn(acc[i][j][2], acc[i][j][3]);
                } else {
                    float v0 = acc[i][j][0], v1 = acc[i][j][1];
                    float v2 = acc[i][j][2], v3 = acc[i][j][3];
                    if (R){ v0 += R[o0]; v1 += R[o0+1]; v2 += R[o1]; v3 += R[o1+1]; }
                    C[o0] = v0; C[o0+1] = v1; C[o1] = v2; C[o1+1] = v3;
                }
            }
        }
    }
}

// ---------------- 4) tiled depthwise causal conv + SiLU (fp16 out) ----------
#define CTS 16
__global__ void conv_kernel(const float* __restrict__ cw,
                            const float* __restrict__ cb){
    __shared__ float s[CTS+6][128];
    __shared__ float w[7][128];
    __shared__ float bias[128];
    int ch0 = blockIdx.x * 128;
    int t0  = blockIdx.y * CTS;
    int b   = blockIdx.z;
    int tid = threadIdx.x;
    for (int i = tid; i < 7*128; i += 256){
        int j = i >> 7, ch = i & 127;
        w[j][ch] = cw[(size_t)(ch0+ch)*DCONV + j];
    }
    if (tid < 128) bias[tid] = cb[ch0 + tid];
    for (int i = tid; i < (CTS+6)*128; i += 256){
        int tt = t0 - 6 + (i >> 7);
        int ch = i & 127;
        s[i>>7][ch] = (tt >= 0)
            ? __half2float(g_zxh[(size_t)(b*SEQLEN + tt)*DIP + DI + ch0 + ch]) : 0.f;
    }
    __syncthreads();
    #pragma unroll
    for (int k = 0; k < 8; k++){
        int o = tid + k*256;
        int tl = o >> 7, ch = o & 127;
        float acc = bias[ch];
        #pragma unroll
        for (int j = 0; j < 7; j++) acc += w[j][ch] * s[tl+j][ch];
        g_xch[(size_t)(b*SEQLEN + t0 + tl)*CONVD + ch0 + ch] = __float2half(siluf(acc));
    }
}

// ---------------- 5) dt softplus + per-chunk cumsum fused ----------------
__global__ void cumsum_kernel(const float* __restrict__ A_log,
                              const float* __restrict__ dt_bias){
    int bid = blockIdx.x;            // ((bb*NH)+h)*NC + c
    int c = bid % NC;
    int h = (bid / NC) % NH;
    int bb = bid / (NC*NH);
    int b = bb & 1;
    bool rev = bb >= 2;
    int tid = threadIdx.x;
    float a = -expf(A_log[h]);
    int t = c*CHUNK_T + tid;
    int tg = rev ? (SEQLEN-1-t) : t;
    int col = (DIP - 2*NH) + (rev ? NH + h : h);
    float raw = __half2float(g_zxh[(size_t)(b*SEQLEN + tg)*DIP + col]);
    float dtv = softplusf(raw + dt_bias[h]);
    g_dt[(size_t)(bb*SEQLEN + t)*NH + h] = dtv;
    float v = dtv * a;
    __shared__ float s[CHUNK_T];
    s[tid] = v; __syncthreads();
    for (int off = 1; off < CHUNK_T; off <<= 1){
        float add = (tid >= off) ? s[tid-off] : 0.f;
        __syncthreads();
        s[tid] += add;
        __syncthreads();
    }
    g_acum[(size_t)bid*CHUNK_T + tid] = s[tid];
    if (tid == CHUNK_T-1) g_csum[bid] = s[tid];
}

// ---------------- 6) chunk states (fp16 mma + ldmatrix) ----------------
#define SMH 72
__global__ void states_kernel(){
    int bid = blockIdx.x;            // (bb*NC+c)*NH + h
    int h = bid % NH;
    int c = (bid / NH) % NC;
    int bb = bid / (NH*NC);
    int b = bb & 1;
    bool rev = bb >= 2;
    int tid = threadIdx.x;
    int lane = tid & 31, warp = tid >> 5;
    int wm = warp >> 2, wn = warp & 3;
    int gid = lane >> 2, qid = lane & 3;
    const int rowsel = lane & 15;
    const int koffA  = (lane >> 4) * 8;
    const int nsel   = (lane & 7) + ((lane >> 4) * 8);
    const int koffB  = ((lane >> 3) & 1) * 8;

    __shared__ __half Ab[64*SMH];
    __shared__ __half Bb[64*SMH];
    __shared__ float dtl[64], decl[64];

    const float* ac = g_acum + ((size_t)(bb*NH + h)*NC + c)*CHUNK_T;
    float cs = g_csum[(bb*NH + h)*NC + c];

    float acc[2][2][4];
    #pragma unroll
    for (int i=0;i<2;i++)
        #pragma unroll
        for (int j=0;j<2;j++)
            #pragma unroll
            for (int r=0;r<4;r++) acc[i][j][r]=0.f;

    for (int ltile = 0; ltile < 4; ltile++){
        if (tid < 64){
            int lc2 = ltile*64 + tid;
            int tgl = c*CHUNK_T + lc2;
            dtl[tid] = g_dt[(size_t)(bb*SEQLEN + tgl)*NH + h];
            decl[tid] = expf(cs - ac[lc2]);
        }
        __syncthreads();
        for (int idx = tid; idx < 64*64; idx += 256){
            int l = idx >> 6, q = idx & 63;
            int tgl = c*CHUNK_T + ltile*64 + l;
            int trow = rev ? (SEQLEN-1 - tgl) : tgl;
            size_t roff = (size_t)(b*SEQLEN + trow)*CONVD;
            float xv = __half2float(g_xch[roff + h*HD + q]);
            float bv = __half2float(g_xch[roff + DI + q]);
            Ab[q*SMH + l] = __float2half(xv * dtl[l]);
            Bb[q*SMH + l] = __float2half(bv * decl[l]);
        }
        __syncthreads();
        #pragma unroll
        for (int ks = 0; ks < 64; ks += 16){
            unsigned a[2][4], bf[2][2];
            #pragma unroll
            for (int i=0;i<2;i++)
                ldsm4(a[i], Ab + (wm*32 + i*16 + rowsel)*SMH + ks + koffA);
            {
                unsigned t0[4];
                ldsm4(t0, Bb + (wn*16 + nsel)*SMH + ks + koffB);
                bf[0][0]=t0[0]; bf[0][1]=t0[1]; bf[1][0]=t0[2]; bf[1][1]=t0[3];
            }
            #pragma unroll
            for (int i=0;i<2;i++)
                #pragma unroll
                for (int j=0;j<2;j++) MMA_F16(acc[i][j], a[i], bf[j]);
        }
        __syncthreads();
    }
    float* sp = g_states + (size_t)bid*(HD*DS);
    #pragma unroll
    for (int i=0;i<2;i++){
        int p = wm*32 + i*16 + gid;
        #pragma unroll
        for (int j=0;j<2;j++){
            int n = wn*16 + j*8 + 2*qid;
            sp[p*DS + n]     = acc[i][j][0];
            sp[p*DS + n + 1] = acc[i][j][1];
            sp[(p+8)*DS + n]     = acc[i][j][2];
            sp[(p+8)*DS + n + 1] = acc[i][j][3];
        }
    }
}

// ---------------- 7) inter-chunk scan ----------------
__global__ void prevscan_kernel(){
    int bh = blockIdx.x;
    int bb = bh / NH, h = bh % NH;
    int tid = threadIdx.x;
    float run[16];
    #pragma unroll
    for (int k = 0; k < 16; k++) run[k] = 0.f;
    for (int c = 0; c < NC; c++){
        size_t off = ((size_t)(bb*NC + c)*NH + h)*(HD*DS);
        float e = expf(g_csum[bh*NC + c]);
        #pragma unroll
        for (int k = 0; k < 16; k++){
            int idx = k*256 + tid;
            g_prevh[off + idx] = __float2half(run[k]);
            run[k] = run[k]*e + g_states[off + idx];
        }
    }
}

// ---------------- 8) Y = Y_diag + Y_off (fp16 mma + ldmatrix) --------------
__global__ void ydiag_kernel(){
    int bid = blockIdx.x;            // ((bb*NC+c)*NH+h)*4 + lt
    int lt = bid & 3;
    int h  = (bid >> 2) % NH;
    int c  = (bid / (4*NH)) % NC;
    int bb = bid / (4*NH*NC);
    int b = bb & 1;
    bool rev = bb >= 2;
    int tid = threadIdx.x;
    int lane = tid & 31, warp = tid >> 5;
    int wm = warp >> 2, wn = warp & 3;
    int gid = lane >> 2, qid = lane & 3;
    const int rowsel = lane & 15;
    const int koffA  = (lane >> 4) * 8;
    const int nsel   = (lane & 7) + ((lane >> 4) * 8);
    const int koffB  = ((lane >> 3) & 1) * 8;

    __shared__ __half Ab[64*SMH];
    __shared__ __half Bb[64*SMH];
    __shared__ float acl[64], eacl[64], acs[64], dts[64];

    const float* ac = g_acum + ((size_t)(bb*NH + h)*NC + c)*CHUNK_T;

    if (tid < 64){
        float v = ac[lt*64 + tid];
        acl[tid] = v;
        eacl[tid] = expf(v);
    }
    __syncthreads();

    float acc[2][2][4];
    #pragma unroll
    for (int i=0;i<2;i++)
        #pragma unroll
        for (int j=0;j<2;j++)
            #pragma unroll
            for (int r=0;r<4;r++) acc[i][j][r]=0.f;

    // ---- Y_off
    {
        size_t poff = ((size_t)(bb*NC + c)*NH + h)*(HD*DS);
        for (int i2 = tid; i2 < 2048; i2 += 256){
            int l = i2 >> 5, c2 = (i2 & 31) * 2;
            int tgl = c*CHUNK_T + lt*64 + l;
            int trl = rev ? (SEQLEN-1 - tgl) : tgl;
            __half2 cv = *(const __half2*)&g_xch[(size_t)(b*SEQLEN + trl)*CONVD + DI + DS + c2];
            float2 cf = __half22float2(cv);
            float e = eacl[l];
            *(__half2*)&Ab[l*SMH + c2] = __floats2half2_rn(cf.x*e, cf.y*e);
            *(__half2*)&Bb[l*SMH + c2] = *(const __half2*)&g_prevh[poff + l*64 + c2];
        }
        __syncthreads();
        #pragma unroll
        for (int ks = 0; ks < 64; ks += 16){
            unsigned a[2][4], bf[2][2];
            #pragma unroll
            for (int i=0;i<2;i++)
                ldsm4(a[i], Ab + (wm*32 + i*16 + rowsel)*SMH + ks + koffA);
            {
                unsigned t0[4];
                ldsm4(t0, Bb + (wn*16 + nsel)*SMH + ks + koffB);
                bf[0][0]=t0[0]; bf[0][1]=t0[1]; bf[1][0]=t0[2]; bf[1][1]=t0[3];
            }
            #pragma unroll
            for (int i=0;i<2;i++)
                #pragma unroll
                for (int j=0;j<2;j++) MMA_F16(acc[i][j], a[i], bf[j]);
        }
        __syncthreads();
    }

    // ---- Y_diag over s-tiles <= lt
    for (int st = 0; st <= lt; st++){
        if (tid < 64){
            acs[tid] = ac[st*64 + tid];
            dts[tid] = g_dt[(size_t)(bb*SEQLEN + c*CHUNK_T + st*64 + tid)*NH + h];
        }
        for (int i2 = tid; i2 < 2048; i2 += 256){
            int r = i2 >> 5, c2 = (i2 & 31) * 2;
            int tgl = c*CHUNK_T + lt*64 + r;
            int trl = rev ? (SEQLEN-1 - tgl) : tgl;
            *(__half2*)&Ab[r*SMH + c2] =
                *(const __half2*)&g_xch[(size_t)(b*SEQLEN + trl)*CONVD + DI + DS + c2];
            int tgs = c*CHUNK_T + st*64 + r;
            int trs = rev ? (SEQLEN-1 - tgs) : tgs;
            *(__half2*)&Bb[r*SMH + c2] =
                *(const __half2*)&g_xch[(size_t)(b*SEQLEN + trs)*CONVD + DI + c2];
        }
        __syncthreads();
        float g[2][2][4];
        #pragma unroll
        for (int i=0;i<2;i++)
            #pragma unroll
            for (int j=0;j<2;j++)
                #pragma unroll
                for (int r=0;r<4;r++) g[i][j][r]=0.f;
        #pragma unroll
        for (int ks = 0; ks < 64; ks += 16){
            unsigned a[2][4], bf[2][2];
            #pragma unroll
            for (int i=0;i<2;i++)
                ldsm4(a[i], Ab + (wm*32 + i*16 + rowsel)*SMH + ks + koffA);
            {
                unsigned t0[4];
                ldsm4(t0, Bb + (wn*16 + nsel)*SMH + ks + koffB);
                bf[0][0]=t0[0]; bf[0][1]=t0[1]; bf[1][0]=t0[2]; bf[1][1]=t0[3];
            }
            #pragma unroll
            for (int i=0;i<2;i++)
                #pragma unroll
                for (int j=0;j<2;j++) MMA_F16(g[i][j], a[i], bf[j]);
        }
        __syncthreads();
        bool diag = (st == lt);
        #pragma unroll
        for (int i=0;i<2;i++){
            int l0 = wm*32 + i*16 + gid;
            #pragma unroll
            for (int j=0;j<2;j++){
                int s0 = wn*16 + j*8 + 2*qid;
                float al0 = acl[l0], al1 = acl[l0+8];
                float w00 = (diag && s0   > l0) ? 0.f : expf(al0 - acs[s0]);
                float w01 = (diag && s0+1 > l0) ? 0.f : expf(al0 - acs[s0+1]);
                float w10 = (diag && s0   > l0+8) ? 0.f : expf(al1 - acs[s0]);
                float w11 = (diag && s0+1 > l0+8) ? 0.f : expf(al1 - acs[s0+1]);
                Ab[l0*SMH + s0]       = __float2half(g[i][j][0]*w00);
                Ab[l0*SMH + s0+1]     = __float2half(g[i][j][1]*w01);
                Ab[(l0+8)*SMH + s0]   = __float2half(g[i][j][2]*w10);
                Ab[(l0+8)*SMH + s0+1] = __float2half(g[i][j][3]*w11);
            }
        }
        for (int idx = tid; idx < 64*64; idx += 256){
            int s = idx >> 6, p = idx & 63;
            int tgs = c*CHUNK_T + st*64 + s;
            int trs = rev ? (SEQLEN-1 - tgs) : tgs;
            float xv = __half2float(g_xch[(size_t)(b*SEQLEN + trs)*CONVD + h*HD + p]);
            Bb[p*SMH + s] = __float2half(xv * dts[s]);
        }
        __syncthreads();
        #pragma unroll
        for (int ks = 0; ks < 64; ks += 16){
            unsigned a[2][4], bf[2][2];
            #pragma unroll
            for (int i=0;i<2;i++)
                ldsm4(a[i], Ab + (wm*32 + i*16 + rowsel)*SMH + ks + koffA);
            {
                unsigned t0[4];
                ldsm4(t0, Bb + (wn*16 + nsel)*SMH + ks + koffB);
                bf[0][0]=t0[0]; bf[0][1]=t0[1]; bf[1][0]=t0[2]; bf[1][1]=t0[3];
            }
            #pragma unroll
            for (int i=0;i<2;i++)
                #pragma unroll
                for (int j=0;j<2;j++) MMA_F16(acc[i][j], a[i], bf[j]);
        }
        __syncthreads();
    }

    #pragma unroll
    for (int i=0;i<2;i++){
        int l = wm*32 + i*16 + gid;
        int tg0 = c*CHUNK_T + lt*64 + l;
        #pragma unroll
        for (int j=0;j<2;j++){
            int pc = h*HD + wn*16 + j*8 + 2*qid;
            size_t o0 = (size_t)(bb*SEQLEN + tg0)*DI + pc;
            size_t o1 = (size_t)(bb*SEQLEN + tg0 + 8)*DI + pc;
            *(__half2*)&g_yssdh[o0] = __floats2half2_rn(acc[i][j][0], acc[i][j][1]);
            *(__half2*)&g_yssdh[o1] = __floats2half2_rn(acc[i][j][2], acc[i][j][3]);
        }
    }
}

// ---------------- 9) fc_D (fp16 inputs) ----------------
__global__ void fcd_kernel(const float* __restrict__ fw){
    __shared__ float ws[NH][132];
    int r0 = blockIdx.x * 64;
    int tid = threadIdx.x;
    int rl = tid >> 2;
    int lj = tid & 3;
    float acc[6] = {0.f,0.f,0.f,0.f,0.f,0.f};
    for (int k0 = 0; k0 < DI; k0 += 128){
        for (int i = tid; i < NH*128; i += 256)
            ws[i>>7][i&127] = fw[(size_t)(i>>7)*DI + k0 + (i&127)];
        __syncthreads();
        const __half2* xr = (const __half2*)&g_xch[(size_t)(r0+rl)*CONVD + k0];
        #pragma unroll 16
        for (int kk = 0; kk < 64; kk += 2){
            float2 x0 = __half22float2(xr[kk]);
            float2 x1 = __half22float2(xr[kk+1]);
            #pragma unroll
            for (int hh = 0; hh < 6; hh++){
                int h = lj*6 + hh;
                acc[hh] += x0.x*ws[h][kk*2] + x0.y*ws[h][kk*2+1]
                         + x1.x*ws[h][kk*2+2] + x1.y*ws[h][kk*2+3];
            }
        }
        __syncthreads();
    }
    #pragma unroll
    for (int hh = 0; hh < 6; hh++)
        g_dterm[(size_t)(r0+rl)*NH + lj*6 + hh] = acc[hh];
}

// ---------------- 10) combine + gate + RMSNorm (emits fp16) ----------------
__global__ void combine_kernel(const float* __restrict__ Dv,
                               const float* __restrict__ rms_w){
    __shared__ float ybuf[DI];
    __shared__ float red[256];
    int bl = blockIdx.x;
    int b = bl / SEQLEN, t = bl % SEQLEN;
    int tid = threadIdx.x;
    float ss = 0.f;
    for (int d = tid; d < DI; d += 256){
        float yf = (t > 0) ? __half2float(g_yssdh[(size_t)(b*SEQLEN + t - 1)*DI + d]) : 0.f;
        float yb = (t <= SEQLEN-2)
            ? __half2float(g_yssdh[(size_t)((2+b)*SEQLEN + (SEQLEN-2 - t))*DI + d]) : 0.f;
        float xo = __half2float(g_xch[(size_t)bl*CONVD + d]);
        int h = d >> 6;
        float dterm = g_dterm[(size_t)bl*NH + h] + Dv[h];
        float z = __half2float(g_zxh[(size_t)bl*DIP + d]);
        float y = (yf + yb + xo*dterm) * siluf(z);
        ybuf[d] = y;
        ss += y*y;
    }
    float tot = blockReduce256(ss, red);
    float inv = rsqrtf(tot/DI + EPSV);
    for (int d = tid; d < DI; d += 256)
        g_ynh[(size_t)bl*DI + d] = __float2half(ybuf[d]*inv*rms_w[d]);
}

// ---------------- launch ----------------
extern "C" void kernel_launch(void* const* d_in, const int* in_sizes, int n_in,
                              void* d_out, int out_size){
    const float* x          = (const float*)d_in[0];
    const float* ln_w       = (const float*)d_in[1];
    const float* ln_b       = (const float*)d_in[2];
    const float* in_proj_w  = (const float*)d_in[3];
    const float* conv_w     = (const float*)d_in[4];
    const float* conv_b     = (const float*)d_in[5];
    const float* dt_bias    = (const float*)d_in[6];
    const float* A_log      = (const float*)d_in[7];
    const float* Dv         = (const float*)d_in[8];
    const float* fc_D_w     = (const float*)d_in[9];
    const float* rms_w      = (const float*)d_in[10];
    const float* out_proj_w = (const float*)d_in[11];
    float* out = (float*)d_out;

    __half *uh, *ynh, *wah, *woh, *zxh;
    cudaGetSymbolAddress((void**)&uh,  g_uh);
    cudaGetSymbolAddress((void**)&ynh, g_ynh);
    cudaGetSymbolAddress((void**)&wah, g_wah);
    cudaGetSymbolAddress((void**)&woh, g_woh);
    cudaGetSymbolAddress((void**)&zxh, g_zxh);

    static bool attr_set = false;
    const int gsmem = GSTH*2*128*SMSH*(int)sizeof(__half);   // 61440 B
    if (!attr_set){
        cudaFuncSetAttribute(gemm_h, cudaFuncAttributeMaxDynamicSharedMemorySize, gsmem);
        attr_set = true;
    }

    wconv_kernel<<<(DIP*DM + 255)/256, 256>>>(in_proj_w, out_proj_w);
    ln_kernel<<<BL, 256>>>(x, ln_w, ln_b);

    // in_proj -> fp16 zx
    gemm_h<<<dim3((DIP+127)/128, BL/128), 256, gsmem>>>(uh, DM, wah, DM,
        nullptr, nullptr, zxh, DIP, BL, DIP, DM);

    conv_kernel<<<dim3(CONVD/128, SEQLEN/CTS, BATCH), 256>>>(conv_w, conv_b);
    cumsum_kernel<<<NBB*NH*NC, 256>>>(A_log, dt_bias);
    states_kernel<<<NBB*NC*NH, 256>>>();
    prevscan_kernel<<<NBB*NH, 256>>>();
    ydiag_kernel<<<NBB*NC*NH*4, 256>>>();
    fcd_kernel<<<BL/64, 256>>>(fc_D_w);
    combine_kernel<<<BL, 256>>>(Dv, rms_w);

    // out_proj + residual -> fp32 out
    gemm_h<<<dim3(DM/128, BL/128), 256, gsmem>>>(ynh, DI, woh, DI,
        x, out, nullptr, DM, BL, DM, DI);
}

// round 9
// speedup vs baseline: 4.1508x; 1.0666x over previous
#include <cuda_runtime.h>
#include <cuda_fp16.h>
#include <math.h>
#include <stdint.h>

// ---------------- constants ----------------
#define BATCH   2
#define SEQLEN  4096
#define BL      (BATCH*SEQLEN)          // 8192 rows
#define DM      768
#define DI      1536
#define NH      24
#define HD      64
#define DS      64
#define DCONV   7
#define CONVD   (DI + 2*DS)             // 1664
#define DIP     (2*DI + 2*DS + 2*NH)    // 3248
#define CHUNK_T 256
#define NC      (SEQLEN/CHUNK_T)        // 16
#define NBB     (2*BATCH)               // 4 direction-batches
#define EPSV    1e-5f

// ---------------- scratch ----------------
__device__ __half g_zxh[(size_t)BL*DIP];
__device__ __half g_xch[(size_t)BL*CONVD];
__device__ float g_dt[(size_t)NBB*SEQLEN*NH];
__device__ float g_acum[(size_t)NBB*NH*NC*CHUNK_T];
__device__ float g_csum[(size_t)NBB*NH*NC];
__device__ float g_states[(size_t)NBB*NC*NH*HD*DS];
__device__ __half g_prevh[(size_t)NBB*NC*NH*HD*DS];
__device__ __half g_yssdh[(size_t)NBB*SEQLEN*DI];
__device__ float g_dterm[(size_t)BL*NH];
__device__ __half g_uh[(size_t)BL*DM];
__device__ __half g_ynh[(size_t)BL*DI];
__device__ __half g_wah[(size_t)DIP*DM];
__device__ __half g_woh[(size_t)DM*DI];

// ---------------- helpers ----------------
__device__ __forceinline__ float softplusf(float x){
    return (x > 20.f) ? x : log1pf(expf(x));
}
__device__ __forceinline__ float siluf(float x){
    return x / (1.f + expf(-x));
}
#define MMA_F16(acc, a, b) \
    asm volatile("mma.sync.aligned.m16n8k16.row.col.f32.f16.f16.f32 " \
        "{%0,%1,%2,%3},{%4,%5,%6,%7},{%8,%9},{%0,%1,%2,%3};" \
        : "+f"(acc[0]),"+f"(acc[1]),"+f"(acc[2]),"+f"(acc[3]) \
        : "r"(a[0]),"r"(a[1]),"r"(a[2]),"r"(a[3]),"r"(b[0]),"r"(b[1]))

__device__ __forceinline__ void ldsm4(unsigned* r, const __half* p){
    unsigned a = (unsigned)__cvta_generic_to_shared(p);
    asm volatile("ldmatrix.sync.aligned.m8n8.x4.shared.b16 {%0,%1,%2,%3}, [%4];"
        : "=r"(r[0]),"=r"(r[1]),"=r"(r[2]),"=r"(r[3]) : "r"(a));
}

__device__ __forceinline__ void cp16(void* dst, const void* src, bool p){
    unsigned d = (unsigned)__cvta_generic_to_shared(dst);
    int sz = p ? 16 : 0;
    asm volatile("cp.async.cg.shared.global [%0], [%1], 16, %2;\n"
                 :: "r"(d), "l"(src), "r"(sz));
}
__device__ __forceinline__ void cp_commit(){ asm volatile("cp.async.commit_group;\n"); }
__device__ __forceinline__ void cp_wait2(){ asm volatile("cp.async.wait_group 2;\n"); }

__device__ __forceinline__ float blockReduce256(float v, float* red){
    int tid = threadIdx.x;
    red[tid] = v; __syncthreads();
    #pragma unroll
    for (int o = 128; o > 0; o >>= 1){
        if (tid < o) red[tid] += red[tid + o];
        __syncthreads();
    }
    float r = red[0];
    __syncthreads();
    return r;
}

// ---------------- 0) weight convert to fp16 ----------------
__global__ void wconv_kernel(const float* __restrict__ wi,
                             const float* __restrict__ wo){
    int i = blockIdx.x*256 + threadIdx.x;
    if (i < DIP*DM) g_wah[i] = __float2half(wi[i]);
    if (i < DM*DI)  g_woh[i] = __float2half(wo[i]);
}

// ---------------- 1) LayerNorm (emits fp16) ----------------
__global__ void ln_kernel(const float* __restrict__ x,
                          const float* __restrict__ w,
                          const float* __restrict__ b){
    __shared__ float red[256];
    int row = blockIdx.x;
    const float* xr = x + (size_t)row*DM;
    int tid = threadIdx.x;
    float s = 0.f;
    for (int i = tid; i < DM; i += 256) s += xr[i];
    float mu = blockReduce256(s, red) / DM;
    float v = 0.f;
    for (int i = tid; i < DM; i += 256){ float d = xr[i]-mu; v += d*d; }
    float var = blockReduce256(v, red) / DM;
    float inv = rsqrtf(var + EPSV);
    for (int i = tid; i < DM; i += 256)
        g_uh[(size_t)row*DM + i] = __float2half((xr[i]-mu)*inv*w[i] + b[i]);
}

// ---------------- fp16 GEMM, 4-stage cp.async, m16n8k16, ldmatrix ----------
// C[M,N] = A[M,K] @ B[N,K]^T.  Output: Ch (half) if non-null else C (+R) fp32.
#define SMSH 40
#define GSTH 4
__global__ __launch_bounds__(256, 2)
void gemm_h(const __half* __restrict__ A, int lda,
            const __half* __restrict__ B, int ldb,
            const float* __restrict__ R,
            float* __restrict__ C, __half* __restrict__ Ch, int ldc,
            int M, int N, int K){
    extern __shared__ __half smh[];
    __half* AsB = smh;
    __half* BsB = smh + GSTH*128*SMSH;
    const int tid  = threadIdx.x;
    const int lane = tid & 31;
    const int warp = tid >> 5;
    const int wm = warp >> 2;
    const int wn = warp & 3;
    const int m0 = blockIdx.y * 128;
    const int n0 = blockIdx.x * 128;
    const int rowsel = lane & 15;
    const int koffA  = (lane >> 4) * 8;
    const int nsel   = (lane & 7) + ((lane >> 4) * 8);
    const int koffB  = ((lane >> 3) & 1) * 8;

    float acc[4][4][4];
    #pragma unroll
    for (int i=0;i<4;i++)
        #pragma unroll
        for (int j=0;j<4;j++)
            #pragma unroll
            for (int r=0;r<4;r++) acc[i][j][r]=0.f;

    const int nk = K >> 5;
    const int c0r = tid >> 2,  c0q = tid & 3;
    const int c1r = (tid+256) >> 2, c1q = tid & 3;

    const __half* ApA = A + (size_t)(m0 + c0r)*lda + c0q*8;
    const __half* ApB = A + (size_t)(m0 + c1r)*lda + c1q*8;
    const int bn0 = n0 + c0r, bn1 = n0 + c1r;
    const __half* BpA = B + (size_t)bn0*ldb + c0q*8;
    const __half* BpB = B + (size_t)bn1*ldb + c1q*8;
    const bool bokA = bn0 < N, bokB = bn1 < N;

    #pragma unroll
    for (int s = 0; s < GSTH-1; s++){
        int ko = s << 5;
        __half* as = AsB + s*(128*SMSH);
        __half* bs = BsB + s*(128*SMSH);
        cp16(as + c0r*SMSH + c0q*8, ApA + ko, true);
        cp16(as + c1r*SMSH + c1q*8, ApB + ko, true);
        cp16(bs + c0r*SMSH + c0q*8, BpA + ko, bokA);
        cp16(bs + c1r*SMSH + c1q*8, BpB + ko, bokB);
        cp_commit();
    }

    for (int kt = 0; kt < nk; kt++){
        cp_wait2();
        __syncthreads();
        int kn = kt + GSTH - 1;
        if (kn < nk){
            int ko = kn << 5;
            int stg = kn % GSTH;
            __half* as = AsB + stg*(128*SMSH);
            __half* bs = BsB + stg*(128*SMSH);
            cp16(as + c0r*SMSH + c0q*8, ApA + ko, true);
            cp16(as + c1r*SMSH + c1q*8, ApB + ko, true);
            cp16(bs + c0r*SMSH + c0q*8, BpA + ko, bokA);
            cp16(bs + c1r*SMSH + c1q*8, BpB + ko, bokB);
        }
        cp_commit();

        const __half* As = AsB + (kt % GSTH)*(128*SMSH);
        const __half* Bs = BsB + (kt % GSTH)*(128*SMSH);
        #pragma unroll
        for (int ks = 0; ks < 32; ks += 16){
            unsigned a[4][4], bfr[4][2];
            #pragma unroll
            for (int i=0;i<4;i++)
                ldsm4(a[i], As + (wm*64 + i*16 + rowsel)*SMSH + ks + koffA);
            {
                unsigned t0[4], t1[4];
                ldsm4(t0, Bs + (wn*32 + nsel)*SMSH + ks + koffB);
                ldsm4(t1, Bs + (wn*32 + 16 + nsel)*SMSH + ks + koffB);
                bfr[0][0]=t0[0]; bfr[0][1]=t0[1]; bfr[1][0]=t0[2]; bfr[1][1]=t0[3];
                bfr[2][0]=t1[0]; bfr[2][1]=t1[1]; bfr[3][0]=t1[2]; bfr[3][1]=t1[3];
            }
            #pragma unroll
            for (int i=0;i<4;i++)
                #pragma unroll
                for (int j=0;j<4;j++) MMA_F16(acc[i][j], a[i], bfr[j]);
        }
    }

    #pragma unroll
    for (int i=0;i<4;i++){
        int r0 = m0 + wm*64 + i*16 + (lane>>2);
        #pragma unroll
        for (int j=0;j<4;j++){
            int cb = n0 + wn*32 + j*8;
            if (cb < N){
                int cc = cb + 2*(lane & 3);
                size_t o0 = (size_t)r0*ldc + cc;
                size_t o1 = (size_t)(r0+8)*ldc + cc;
                if (Ch){
                    *(__half2*)&Ch[o0] = __floats2half2_rn(acc[i][j][0], acc[i][j][1]);
                    *(__half2*)&Ch[o1] = __floats2half2_rn(acc[i][j][2], acc[i][j][3]);
                } else {
                    float v0 = acc[i][j][0], v1 = acc[i][j][1];
                    float v2 = acc[i][j][2], v3 = acc[i][j][3];
                    if (R){ v0 += R[o0]; v1 += R[o0+1]; v2 += R[o1]; v3 += R[o1+1]; }
                    C[o0] = v0; C[o0+1] = v1; C[o1] = v2; C[o1+1] = v3;
                }
            }
        }
    }
}

// ---------------- 4) tiled depthwise causal conv + SiLU (fp16 out) ----------
#define CTS 32
__global__ void conv_kernel(const float* __restrict__ cw,
                            const float* __restrict__ cb){
    __shared__ float s[CTS+6][128];
    __shared__ float w[7][128];
    __shared__ float bias[128];
    int ch0 = blockIdx.x * 128;
    int t0  = blockIdx.y * CTS;
    int b   = blockIdx.z;
    int tid = threadIdx.x;
    for (int i = tid; i < 7*128; i += 256){
        int j = i >> 7, ch = i & 127;
        w[j][ch] = cw[(size_t)(ch0+ch)*DCONV + j];
    }
    if (tid < 128) bias[tid] = cb[ch0 + tid];
    for (int i = tid; i < (CTS+6)*128; i += 256){
        int tt = t0 - 6 + (i >> 7);
        int ch = i & 127;
        s[i>>7][ch] = (tt >= 0)
            ? __half2float(g_zxh[(size_t)(b*SEQLEN + tt)*DIP + DI + ch0 + ch]) : 0.f;
    }
    __syncthreads();
    #pragma unroll
    for (int k = 0; k < 16; k++){
        int o = tid + k*256;
        int tl = o >> 7, ch = o & 127;
        float acc = bias[ch];
        #pragma unroll
        for (int j = 0; j < 7; j++) acc += w[j][ch] * s[tl+j][ch];
        g_xch[(size_t)(b*SEQLEN + t0 + tl)*CONVD + ch0 + ch] = __float2half(siluf(acc));
    }
}

// ---------------- 5) dt softplus + per-chunk cumsum fused ----------------
__global__ void cumsum_kernel(const float* __restrict__ A_log,
                              const float* __restrict__ dt_bias){
    int bid = blockIdx.x;            // ((bb*NH)+h)*NC + c
    int c = bid % NC;
    int h = (bid / NC) % NH;
    int bb = bid / (NC*NH);
    int b = bb & 1;
    bool rev = bb >= 2;
    int tid = threadIdx.x;
    float a = -expf(A_log[h]);
    int t = c*CHUNK_T + tid;
    int tg = rev ? (SEQLEN-1-t) : t;
    int col = (DIP - 2*NH) + (rev ? NH + h : h);
    float raw = __half2float(g_zxh[(size_t)(b*SEQLEN + tg)*DIP + col]);
    float dtv = softplusf(raw + dt_bias[h]);
    g_dt[(size_t)(bb*SEQLEN + t)*NH + h] = dtv;
    float v = dtv * a;
    __shared__ float s[CHUNK_T];
    s[tid] = v; __syncthreads();
    for (int off = 1; off < CHUNK_T; off <<= 1){
        float add = (tid >= off) ? s[tid-off] : 0.f;
        __syncthreads();
        s[tid] += add;
        __syncthreads();
    }
    g_acum[(size_t)bid*CHUNK_T + tid] = s[tid];
    if (tid == CHUNK_T-1) g_csum[bid] = s[tid];
}

// ---------------- 6) chunk states (fp16 mma + ldmatrix) ----------------
#define SMH 72
__global__ void states_kernel(){
    int bid = blockIdx.x;            // (bb*NC+c)*NH + h
    int h = bid % NH;
    int c = (bid / NH) % NC;
    int bb = bid / (NH*NC);
    int b = bb & 1;
    bool rev = bb >= 2;
    int tid = threadIdx.x;
    int lane = tid & 31, warp = tid >> 5;
    int wm = warp >> 2, wn = warp & 3;
    int gid = lane >> 2, qid = lane & 3;
    const int rowsel = lane & 15;
    const int koffA  = (lane >> 4) * 8;
    const int nsel   = (lane & 7) + ((lane >> 4) * 8);
    const int koffB  = ((lane >> 3) & 1) * 8;

    __shared__ __half Ab[64*SMH];
    __shared__ __half Bb[64*SMH];
    __shared__ float dtl[64], decl[64];

    const float* ac = g_acum + ((size_t)(bb*NH + h)*NC + c)*CHUNK_T;
    float cs = g_csum[(bb*NH + h)*NC + c];

    float acc[2][2][4];
    #pragma unroll
    for (int i=0;i<2;i++)
        #pragma unroll
        for (int j=0;j<2;j++)
            #pragma unroll
            for (int r=0;r<4;r++) acc[i][j][r]=0.f;

    for (int ltile = 0; ltile < 4; ltile++){
        if (tid < 64){
            int lc2 = ltile*64 + tid;
            int tgl = c*CHUNK_T + lc2;
            dtl[tid] = g_dt[(size_t)(bb*SEQLEN + tgl)*NH + h];
            decl[tid] = expf(cs - ac[lc2]);
        }
        __syncthreads();
        for (int idx = tid; idx < 64*64; idx += 256){
            int l = idx >> 6, q = idx & 63;
            int tgl = c*CHUNK_T + ltile*64 + l;
            int trow = rev ? (SEQLEN-1 - tgl) : tgl;
            size_t roff = (size_t)(b*SEQLEN + trow)*CONVD;
            float xv = __half2float(g_xch[roff + h*HD + q]);
            float bv = __half2float(g_xch[roff + DI + q]);
            Ab[q*SMH + l] = __float2half(xv * dtl[l]);
            Bb[q*SMH + l] = __float2half(bv * decl[l]);
        }
        __syncthreads();
        #pragma unroll
        for (int ks = 0; ks < 64; ks += 16){
            unsigned a[2][4], bf[2][2];
            #pragma unroll
            for (int i=0;i<2;i++)
                ldsm4(a[i], Ab + (wm*32 + i*16 + rowsel)*SMH + ks + koffA);
            {
                unsigned t0[4];
                ldsm4(t0, Bb + (wn*16 + nsel)*SMH + ks + koffB);
                bf[0][0]=t0[0]; bf[0][1]=t0[1]; bf[1][0]=t0[2]; bf[1][1]=t0[3];
            }
            #pragma unroll
            for (int i=0;i<2;i++)
                #pragma unroll
                for (int j=0;j<2;j++) MMA_F16(acc[i][j], a[i], bf[j]);
        }
        __syncthreads();
    }
    float* sp = g_states + (size_t)bid*(HD*DS);
    #pragma unroll
    for (int i=0;i<2;i++){
        int p = wm*32 + i*16 + gid;
        #pragma unroll
        for (int j=0;j<2;j++){
            int n = wn*16 + j*8 + 2*qid;
            sp[p*DS + n]     = acc[i][j][0];
            sp[p*DS + n + 1] = acc[i][j][1];
            sp[(p+8)*DS + n]     = acc[i][j][2];
            sp[(p+8)*DS + n + 1] = acc[i][j][3];
        }
    }
}

// ---------------- 7) inter-chunk scan ----------------
__global__ void prevscan_kernel(){
    int bh = blockIdx.x;
    int bb = bh / NH, h = bh % NH;
    int tid = threadIdx.x;
    float run[16];
    #pragma unroll
    for (int k = 0; k < 16; k++) run[k] = 0.f;
    for (int c = 0; c < NC; c++){
        size_t off = ((size_t)(bb*NC + c)*NH + h)*(HD*DS);
        float e = expf(g_csum[bh*NC + c]);
        #pragma unroll
        for (int k = 0; k < 16; k++){
            int idx = k*256 + tid;
            g_prevh[off + idx] = __float2half(run[k]);
            run[k] = run[k]*e + g_states[off + idx];
        }
    }
}

// ---------------- 8) Y = Y_diag + Y_off (fp16 mma + ldmatrix) --------------
__global__ void ydiag_kernel(){
    int bid = blockIdx.x;            // ((bb*NC+c)*NH+h)*4 + lt
    int lt = bid & 3;
    int h  = (bid >> 2) % NH;
    int c  = (bid / (4*NH)) % NC;
    int bb = bid / (4*NH*NC);
    int b = bb & 1;
    bool rev = bb >= 2;
    int tid = threadIdx.x;
    int lane = tid & 31, warp = tid >> 5;
    int wm = warp >> 2, wn = warp & 3;
    int gid = lane >> 2, qid = lane & 3;
    const int rowsel = lane & 15;
    const int koffA  = (lane >> 4) * 8;
    const int nsel   = (lane & 7) + ((lane >> 4) * 8);
    const int koffB  = ((lane >> 3) & 1) * 8;

    __shared__ __half Ab[64*SMH];
    __shared__ __half Bb[64*SMH];
    __shared__ float acl[64], eacl[64], acs[64], dts[64];

    const float* ac = g_acum + ((size_t)(bb*NH + h)*NC + c)*CHUNK_T;

    if (tid < 64){
        float v = ac[lt*64 + tid];
        acl[tid] = v;
        eacl[tid] = expf(v);
    }
    __syncthreads();

    float acc[2][2][4];
    #pragma unroll
    for (int i=0;i<2;i++)
        #pragma unroll
        for (int j=0;j<2;j++)
            #pragma unroll
            for (int r=0;r<4;r++) acc[i][j][r]=0.f;

    // ---- Y_off
    {
        size_t poff = ((size_t)(bb*NC + c)*NH + h)*(HD*DS);
        for (int i2 = tid; i2 < 2048; i2 += 256){
            int l = i2 >> 5, c2 = (i2 & 31) * 2;
            int tgl = c*CHUNK_T + lt*64 + l;
            int trl = rev ? (SEQLEN-1 - tgl) : tgl;
            __half2 cv = *(const __half2*)&g_xch[(size_t)(b*SEQLEN + trl)*CONVD + DI + DS + c2];
            float2 cf = __half22float2(cv);
            float e = eacl[l];
            *(__half2*)&Ab[l*SMH + c2] = __floats2half2_rn(cf.x*e, cf.y*e);
            *(__half2*)&Bb[l*SMH + c2] = *(const __half2*)&g_prevh[poff + l*64 + c2];
        }
        __syncthreads();
        #pragma unroll
        for (int ks = 0; ks < 64; ks += 16){
            unsigned a[2][4], bf[2][2];
            #pragma unroll
            for (int i=0;i<2;i++)
                ldsm4(a[i], Ab + (wm*32 + i*16 + rowsel)*SMH + ks + koffA);
            {
                unsigned t0[4];
                ldsm4(t0, Bb + (wn*16 + nsel)*SMH + ks + koffB);
                bf[0][0]=t0[0]; bf[0][1]=t0[1]; bf[1][0]=t0[2]; bf[1][1]=t0[3];
            }
            #pragma unroll
            for (int i=0;i<2;i++)
                #pragma unroll
                for (int j=0;j<2;j++) MMA_F16(acc[i][j], a[i], bf[j]);
        }
        __syncthreads();
    }

    // ---- Y_diag over s-tiles <= lt
    for (int st = 0; st <= lt; st++){
        if (tid < 64){
            acs[tid] = ac[st*64 + tid];
            dts[tid] = g_dt[(size_t)(bb*SEQLEN + c*CHUNK_T + st*64 + tid)*NH + h];
        }
        for (int i2 = tid; i2 < 2048; i2 += 256){
            int r = i2 >> 5, c2 = (i2 & 31) * 2;
            int tgl = c*CHUNK_T + lt*64 + r;
            int trl = rev ? (SEQLEN-1 - tgl) : tgl;
            *(__half2*)&Ab[r*SMH + c2] =
                *(const __half2*)&g_xch[(size_t)(b*SEQLEN + trl)*CONVD + DI + DS + c2];
            int tgs = c*CHUNK_T + st*64 + r;
            int trs = rev ? (SEQLEN-1 - tgs) : tgs;
            *(__half2*)&Bb[r*SMH + c2] =
                *(const __half2*)&g_xch[(size_t)(b*SEQLEN + trs)*CONVD + DI + c2];
        }
        __syncthreads();
        float g[2][2][4];
        #pragma unroll
        for (int i=0;i<2;i++)
            #pragma unroll
            for (int j=0;j<2;j++)
                #pragma unroll
                for (int r=0;r<4;r++) g[i][j][r]=0.f;
        #pragma unroll
        for (int ks = 0; ks < 64; ks += 16){
            unsigned a[2][4], bf[2][2];
            #pragma unroll
            for (int i=0;i<2;i++)
                ldsm4(a[i], Ab + (wm*32 + i*16 + rowsel)*SMH + ks + koffA);
            {
                unsigned t0[4];
                ldsm4(t0, Bb + (wn*16 + nsel)*SMH + ks + koffB);
                bf[0][0]=t0[0]; bf[0][1]=t0[1]; bf[1][0]=t0[2]; bf[1][1]=t0[3];
            }
            #pragma unroll
            for (int i=0;i<2;i++)
                #pragma unroll
                for (int j=0;j<2;j++) MMA_F16(g[i][j], a[i], bf[j]);
        }
        __syncthreads();
        bool diag = (st == lt);
        #pragma unroll
        for (int i=0;i<2;i++){
            int l0 = wm*32 + i*16 + gid;
            #pragma unroll
            for (int j=0;j<2;j++){
                int s0 = wn*16 + j*8 + 2*qid;
                float al0 = acl[l0], al1 = acl[l0+8];
                float w00 = (diag && s0   > l0) ? 0.f : expf(al0 - acs[s0]);
                float w01 = (diag && s0+1 > l0) ? 0.f : expf(al0 - acs[s0+1]);
                float w10 = (diag && s0   > l0+8) ? 0.f : expf(al1 - acs[s0]);
                float w11 = (diag && s0+1 > l0+8) ? 0.f : expf(al1 - acs[s0+1]);
                Ab[l0*SMH + s0]       = __float2half(g[i][j][0]*w00);
                Ab[l0*SMH + s0+1]     = __float2half(g[i][j][1]*w01);
                Ab[(l0+8)*SMH + s0]   = __float2half(g[i][j][2]*w10);
                Ab[(l0+8)*SMH + s0+1] = __float2half(g[i][j][3]*w11);
            }
        }
        for (int idx = tid; idx < 64*64; idx += 256){
            int s = idx >> 6, p = idx & 63;
            int tgs = c*CHUNK_T + st*64 + s;
            int trs = rev ? (SEQLEN-1 - tgs) : tgs;
            float xv = __half2float(g_xch[(size_t)(b*SEQLEN + trs)*CONVD + h*HD + p]);
            Bb[p*SMH + s] = __float2half(xv * dts[s]);
        }
        __syncthreads();
        #pragma unroll
        for (int ks = 0; ks < 64; ks += 16){
            unsigned a[2][4], bf[2][2];
            #pragma unroll
            for (int i=0;i<2;i++)
                ldsm4(a[i], Ab + (wm*32 + i*16 + rowsel)*SMH + ks + koffA);
            {
                unsigned t0[4];
                ldsm4(t0, Bb + (wn*16 + nsel)*SMH + ks + koffB);
                bf[0][0]=t0[0]; bf[0][1]=t0[1]; bf[1][0]=t0[2]; bf[1][1]=t0[3];
            }
            #pragma unroll
            for (int i=0;i<2;i++)
                #pragma unroll
                for (int j=0;j<2;j++) MMA_F16(acc[i][j], a[i], bf[j]);
        }
        __syncthreads();
    }

    #pragma unroll
    for (int i=0;i<2;i++){
        int l = wm*32 + i*16 + gid;
        int tg0 = c*CHUNK_T + lt*64 + l;
        #pragma unroll
        for (int j=0;j<2;j++){
            int pc = h*HD + wn*16 + j*8 + 2*qid;
            size_t o0 = (size_t)(bb*SEQLEN + tg0)*DI + pc;
            size_t o1 = (size_t)(bb*SEQLEN + tg0 + 8)*DI + pc;
            *(__half2*)&g_yssdh[o0] = __floats2half2_rn(acc[i][j][0], acc[i][j][1]);
            *(__half2*)&g_yssdh[o1] = __floats2half2_rn(acc[i][j][2], acc[i][j][3]);
        }
    }
}

// ---------------- 9) fc_D (fp16 inputs) ----------------
__global__ void fcd_kernel(const float* __restrict__ fw){
    __shared__ float ws[NH][132];
    int r0 = blockIdx.x * 64;
    int tid = threadIdx.x;
    int rl = tid >> 2;
    int lj = tid & 3;
    float acc[6] = {0.f,0.f,0.f,0.f,0.f,0.f};
    for (int k0 = 0; k0 < DI; k0 += 128){
        for (int i = tid; i < NH*128; i += 256)
            ws[i>>7][i&127] = fw[(size_t)(i>>7)*DI + k0 + (i&127)];
        __syncthreads();
        const __half2* xr = (const __half2*)&g_xch[(size_t)(r0+rl)*CONVD + k0];
        #pragma unroll 16
        for (int kk = 0; kk < 64; kk += 2){
            float2 x0 = __half22float2(xr[kk]);
            float2 x1 = __half22float2(xr[kk+1]);
            #pragma unroll
            for (int hh = 0; hh < 6; hh++){
                int h = lj*6 + hh;
                acc[hh] += x0.x*ws[h][kk*2] + x0.y*ws[h][kk*2+1]
                         + x1.x*ws[h][kk*2+2] + x1.y*ws[h][kk*2+3];
            }
        }
        __syncthreads();
    }
    #pragma unroll
    for (int hh = 0; hh < 6; hh++)
        g_dterm[(size_t)(r0+rl)*NH + lj*6 + hh] = acc[hh];
}

// ---------------- 10) combine + gate + RMSNorm (half2 vectorized) ----------
__global__ void combine_kernel(const float* __restrict__ Dv,
                               const float* __restrict__ rms_w){
    __shared__ float ybuf[DI];
    __shared__ float red[256];
    int bl = blockIdx.x;
    int b = bl / SEQLEN, t = bl % SEQLEN;
    int tid = threadIdx.x;
    float ss = 0.f;
    for (int d = tid*2; d < DI; d += 512){
        float2 yf = make_float2(0.f, 0.f), yb = make_float2(0.f, 0.f);
        if (t > 0)
            yf = __half22float2(*(const __half2*)&g_yssdh[(size_t)(b*SEQLEN + t - 1)*DI + d]);
        if (t <= SEQLEN-2)
            yb = __half22float2(*(const __half2*)&g_yssdh[(size_t)((2+b)*SEQLEN + (SEQLEN-2 - t))*DI + d]);
        float2 xo = __half22float2(*(const __half2*)&g_xch[(size_t)bl*CONVD + d]);
        float2 z  = __half22float2(*(const __half2*)&g_zxh[(size_t)bl*DIP + d]);
        int h = d >> 6;
        float dterm = g_dterm[(size_t)bl*NH + h] + Dv[h];
        float y0 = (yf.x + yb.x + xo.x*dterm) * siluf(z.x);
        float y1 = (yf.y + yb.y + xo.y*dterm) * siluf(z.y);
        ybuf[d] = y0; ybuf[d+1] = y1;
        ss += y0*y0 + y1*y1;
    }
    float tot = blockReduce256(ss, red);
    float inv = rsqrtf(tot/DI + EPSV);
    for (int d = tid*2; d < DI; d += 512){
        float2 rw = *(const float2*)&rms_w[d];
        *(__half2*)&g_ynh[(size_t)bl*DI + d] =
            __floats2half2_rn(ybuf[d]*inv*rw.x, ybuf[d+1]*inv*rw.y);
    }
}

// ---------------- launch ----------------
extern "C" void kernel_launch(void* const* d_in, const int* in_sizes, int n_in,
                              void* d_out, int out_size){
    const float* x          = (const float*)d_in[0];
    const float* ln_w       = (const float*)d_in[1];
    const float* ln_b       = (const float*)d_in[2];
    const float* in_proj_w  = (const float*)d_in[3];
    const float* conv_w     = (const float*)d_in[4];
    const float* conv_b     = (const float*)d_in[5];
    const float* dt_bias    = (const float*)d_in[6];
    const float* A_log      = (const float*)d_in[7];
    const float* Dv         = (const float*)d_in[8];
    const float* fc_D_w     = (const float*)d_in[9];
    const float* rms_w      = (const float*)d_in[10];
    const float* out_proj_w = (const float*)d_in[11];
    float* out = (float*)d_out;

    __half *uh, *ynh, *wah, *woh, *zxh;
    cudaGetSymbolAddress((void**)&uh,  g_uh);
    cudaGetSymbolAddress((void**)&ynh, g_ynh);
    cudaGetSymbolAddress((void**)&wah, g_wah);
    cudaGetSymbolAddress((void**)&woh, g_woh);
    cudaGetSymbolAddress((void**)&zxh, g_zxh);

    static bool attr_set = false;
    const int gsmem = GSTH*2*128*SMSH*(int)sizeof(__half);   // 81920 B
    if (!attr_set){
        cudaFuncSetAttribute(gemm_h, cudaFuncAttributeMaxDynamicSharedMemorySize, gsmem);
        attr_set = true;
    }

    wconv_kernel<<<(DIP*DM + 255)/256, 256>>>(in_proj_w, out_proj_w);
    ln_kernel<<<BL, 256>>>(x, ln_w, ln_b);

    // in_proj -> fp16 zx
    gemm_h<<<dim3((DIP+127)/128, BL/128), 256, gsmem>>>(uh, DM, wah, DM,
        nullptr, nullptr, zxh, DIP, BL, DIP, DM);

    conv_kernel<<<dim3(CONVD/128, SEQLEN/CTS, BATCH), 256>>>(conv_w, conv_b);
    cumsum_kernel<<<NBB*NH*NC, 256>>>(A_log, dt_bias);
    states_kernel<<<NBB*NC*NH, 256>>>();
    prevscan_kernel<<<NBB*NH, 256>>>();
    ydiag_kernel<<<NBB*NC*NH*4, 256>>>();
    fcd_kernel<<<BL/64, 256>>>(fc_D_w);
    combine_kernel<<<BL, 256>>>(Dv, rms_w);

    // out_proj + residual -> fp32 out
    gemm_h<<<dim3(DM/128, BL/128), 256, gsmem>>>(ynh, DI, woh, DI,
        x, out, nullptr, DM, BL, DM, DI);
}

// round 10
// speedup vs baseline: 4.2004x; 1.0120x over previous
#include <cuda_runtime.h>
#include <cuda_fp16.h>
#include <math.h>
#include <stdint.h>

// ---------------- constants ----------------
#define BATCH   2
#define SEQLEN  4096
#define BL      (BATCH*SEQLEN)          // 8192 rows
#define DM      768
#define DI      1536
#define NH      24
#define HD      64
#define DS      64
#define DCONV   7
#define CONVD   (DI + 2*DS)             // 1664
#define DIP     (2*DI + 2*DS + 2*NH)    // 3248
#define CHUNK_T 256
#define NC      (SEQLEN/CHUNK_T)        // 16
#define NBB     (2*BATCH)               // 4 direction-batches
#define EPSV    1e-5f

// ---------------- scratch ----------------
__device__ __half g_zxh[(size_t)BL*DIP];
__device__ __half g_xch[(size_t)BL*CONVD];
__device__ float g_dt[(size_t)NBB*SEQLEN*NH];
__device__ float g_acum[(size_t)NBB*NH*NC*CHUNK_T];
__device__ float g_csum[(size_t)NBB*NH*NC];
__device__ float g_states[(size_t)NBB*NC*NH*HD*DS];
__device__ __half g_prevh[(size_t)NBB*NC*NH*HD*DS];
__device__ __half g_yssdh[(size_t)NBB*SEQLEN*DI];
__device__ float g_dterm[(size_t)BL*NH];
__device__ __half g_uh[(size_t)BL*DM];
__device__ __half g_ynh[(size_t)BL*DI];
__device__ __half g_wah[(size_t)DIP*DM];
__device__ __half g_woh[(size_t)DM*DI];

// ---------------- helpers ----------------
__device__ __forceinline__ float softplusf(float x){
    return (x > 20.f) ? x : log1pf(expf(x));
}
__device__ __forceinline__ float siluf(float x){
    return x / (1.f + expf(-x));
}
#define MMA_F16(acc, a, b) \
    asm volatile("mma.sync.aligned.m16n8k16.row.col.f32.f16.f16.f32 " \
        "{%0,%1,%2,%3},{%4,%5,%6,%7},{%8,%9},{%0,%1,%2,%3};" \
        : "+f"(acc[0]),"+f"(acc[1]),"+f"(acc[2]),"+f"(acc[3]) \
        : "r"(a[0]),"r"(a[1]),"r"(a[2]),"r"(a[3]),"r"(b[0]),"r"(b[1]))

__device__ __forceinline__ void ldsm4(unsigned* r, const __half* p){
    unsigned a = (unsigned)__cvta_generic_to_shared(p);
    asm volatile("ldmatrix.sync.aligned.m8n8.x4.shared.b16 {%0,%1,%2,%3}, [%4];"
        : "=r"(r[0]),"=r"(r[1]),"=r"(r[2]),"=r"(r[3]) : "r"(a));
}

__device__ __forceinline__ void cp16(void* dst, const void* src, bool p){
    unsigned d = (unsigned)__cvta_generic_to_shared(dst);
    int sz = p ? 16 : 0;
    asm volatile("cp.async.cg.shared.global [%0], [%1], 16, %2;\n"
                 :: "r"(d), "l"(src), "r"(sz));
}
__device__ __forceinline__ void cp_commit(){ asm volatile("cp.async.commit_group;\n"); }
__device__ __forceinline__ void cp_wait2(){ asm volatile("cp.async.wait_group 2;\n"); }

__device__ __forceinline__ float blockReduce256(float v, float* red){
    int tid = threadIdx.x;
    int lane = tid & 31, w = tid >> 5;
    #pragma unroll
    for (int o = 16; o > 0; o >>= 1) v += __shfl_xor_sync(0xffffffffu, v, o);
    if (lane == 0) red[w] = v;
    __syncthreads();
    float r = (lane < 8) ? red[lane] : 0.f;
    #pragma unroll
    for (int o = 4; o > 0; o >>= 1) r += __shfl_xor_sync(0xffffffffu, r, o);
    r = __shfl_sync(0xffffffffu, r, 0);
    return r;
}

// ---------------- 0) weight convert to fp16 ----------------
__global__ void wconv_kernel(const float* __restrict__ wi,
                             const float* __restrict__ wo){
    int i = blockIdx.x*256 + threadIdx.x;
    if (i < DIP*DM) g_wah[i] = __float2half(wi[i]);
    if (i < DM*DI)  g_woh[i] = __float2half(wo[i]);
}

// ---------------- 1) LayerNorm (emits fp16) ----------------
__global__ void ln_kernel(const float* __restrict__ x,
                          const float* __restrict__ w,
                          const float* __restrict__ b){
    __shared__ float red[8];
    int row = blockIdx.x;
    const float* xr = x + (size_t)row*DM;
    int tid = threadIdx.x;
    float s = 0.f;
    for (int i = tid; i < DM; i += 256) s += xr[i];
    float mu = blockReduce256(s, red) / DM;
    __syncthreads();
    float v = 0.f;
    for (int i = tid; i < DM; i += 256){ float d = xr[i]-mu; v += d*d; }
    float var = blockReduce256(v, red) / DM;
    float inv = rsqrtf(var + EPSV);
    for (int i = tid; i < DM; i += 256)
        g_uh[(size_t)row*DM + i] = __float2half((xr[i]-mu)*inv*w[i] + b[i]);
}

// ---------------- fp16 GEMM, 4-stage cp.async, m16n8k16, ldmatrix ----------
#define SMSH 40
#define GSTH 4
__global__ __launch_bounds__(256, 2)
void gemm_h(const __half* __restrict__ A, int lda,
            const __half* __restrict__ B, int ldb,
            const float* __restrict__ R,
            float* __restrict__ C, __half* __restrict__ Ch, int ldc,
            int M, int N, int K){
    extern __shared__ __half smh[];
    __half* AsB = smh;
    __half* BsB = smh + GSTH*128*SMSH;
    const int tid  = threadIdx.x;
    const int lane = tid & 31;
    const int warp = tid >> 5;
    const int wm = warp >> 2;
    const int wn = warp & 3;
    const int m0 = blockIdx.y * 128;
    const int n0 = blockIdx.x * 128;
    const int rowsel = lane & 15;
    const int koffA  = (lane >> 4) * 8;
    const int nsel   = (lane & 7) + ((lane >> 4) * 8);
    const int koffB  = ((lane >> 3) & 1) * 8;

    float acc[4][4][4];
    #pragma unroll
    for (int i=0;i<4;i++)
        #pragma unroll
        for (int j=0;j<4;j++)
            #pragma unroll
            for (int r=0;r<4;r++) acc[i][j][r]=0.f;

    const int nk = K >> 5;
    const int c0r = tid >> 2,  c0q = tid & 3;
    const int c1r = (tid+256) >> 2, c1q = tid & 3;

    const __half* ApA = A + (size_t)(m0 + c0r)*lda + c0q*8;
    const __half* ApB = A + (size_t)(m0 + c1r)*lda + c1q*8;
    const int bn0 = n0 + c0r, bn1 = n0 + c1r;
    const __half* BpA = B + (size_t)bn0*ldb + c0q*8;
    const __half* BpB = B + (size_t)bn1*ldb + c1q*8;
    const bool bokA = bn0 < N, bokB = bn1 < N;

    #pragma unroll
    for (int s = 0; s < GSTH-1; s++){
        int ko = s << 5;
        __half* as = AsB + s*(128*SMSH);
        __half* bs = BsB + s*(128*SMSH);
        cp16(as + c0r*SMSH + c0q*8, ApA + ko, true);
        cp16(as + c1r*SMSH + c1q*8, ApB + ko, true);
        cp16(bs + c0r*SMSH + c0q*8, BpA + ko, bokA);
        cp16(bs + c1r*SMSH + c1q*8, BpB + ko, bokB);
        cp_commit();
    }

    for (int kt = 0; kt < nk; kt++){
        cp_wait2();
        __syncthreads();
        int kn = kt + GSTH - 1;
        if (kn < nk){
            int ko = kn << 5;
            int stg = kn % GSTH;
            __half* as = AsB + stg*(128*SMSH);
            __half* bs = BsB + stg*(128*SMSH);
            cp16(as + c0r*SMSH + c0q*8, ApA + ko, true);
            cp16(as + c1r*SMSH + c1q*8, ApB + ko, true);
            cp16(bs + c0r*SMSH + c0q*8, BpA + ko, bokA);
            cp16(bs + c1r*SMSH + c1q*8, BpB + ko, bokB);
        }
        cp_commit();

        const __half* As = AsB + (kt % GSTH)*(128*SMSH);
        const __half* Bs = BsB + (kt % GSTH)*(128*SMSH);
        #pragma unroll
        for (int ks = 0; ks < 32; ks += 16){
            unsigned a[4][4], bfr[4][2];
            #pragma unroll
            for (int i=0;i<4;i++)
                ldsm4(a[i], As + (wm*64 + i*16 + rowsel)*SMSH + ks + koffA);
            {
                unsigned t0[4], t1[4];
                ldsm4(t0, Bs + (wn*32 + nsel)*SMSH + ks + koffB);
                ldsm4(t1, Bs + (wn*32 + 16 + nsel)*SMSH + ks + koffB);
                bfr[0][0]=t0[0]; bfr[0][1]=t0[1]; bfr[1][0]=t0[2]; bfr[1][1]=t0[3];
                bfr[2][0]=t1[0]; bfr[2][1]=t1[1]; bfr[3][0]=t1[2]; bfr[3][1]=t1[3];
            }
            #pragma unroll
            for (int i=0;i<4;i++)
                #pragma unroll
                for (int j=0;j<4;j++) MMA_F16(acc[i][j], a[i], bfr[j]);
        }
    }

    #pragma unroll
    for (int i=0;i<4;i++){
        int r0 = m0 + wm*64 + i*16 + (lane>>2);
        #pragma unroll
        for (int j=0;j<4;j++){
            int cb = n0 + wn*32 + j*8;
            if (cb < N){
                int cc = cb + 2*(lane & 3);
                size_t o0 = (size_t)r0*ldc + cc;
                size_t o1 = (size_t)(r0+8)*ldc + cc;
                if (Ch){
                    *(__half2*)&Ch[o0] = __floats2half2_rn(acc[i][j][0], acc[i][j][1]);
                    *(__half2*)&Ch[o1] = __floats2half2_rn(acc[i][j][2], acc[i][j][3]);
                } else {
                    float v0 = acc[i][j][0], v1 = acc[i][j][1];
                    float v2 = acc[i][j][2], v3 = acc[i][j][3];
                    if (R){ v0 += R[o0]; v1 += R[o0+1]; v2 += R[o1]; v3 += R[o1+1]; }
                    C[o0] = v0; C[o0+1] = v1; C[o1] = v2; C[o1+1] = v3;
                }
            }
        }
    }
}

// ---------------- 4) conv: half2 channel pairs ----------------
#define CTS 32
__global__ void conv_kernel(const float* __restrict__ cw,
                            const float* __restrict__ cb){
    __shared__ __half2 s[CTS+6][64];
    __shared__ __half2 w[7][64];
    __shared__ __half2 bias[64];
    int ch0 = blockIdx.x * 128;          // 64 half2 pairs
    int t0  = blockIdx.y * CTS;
    int b   = blockIdx.z;
    int tid = threadIdx.x;
    for (int i = tid; i < 7*64; i += 256){
        int j = i >> 6, cp = i & 63;
        w[j][cp] = __floats2half2_rn(cw[(size_t)(ch0+cp*2)*DCONV + j],
                                     cw[(size_t)(ch0+cp*2+1)*DCONV + j]);
    }
    if (tid < 64) bias[tid] = __floats2half2_rn(cb[ch0 + tid*2], cb[ch0 + tid*2+1]);
    for (int i = tid; i < (CTS+6)*64; i += 256){
        int tt = t0 - 6 + (i >> 6);
        int cp = i & 63;
        s[i>>6][cp] = (tt >= 0)
            ? *(const __half2*)&g_zxh[(size_t)(b*SEQLEN + tt)*DIP + DI + ch0 + cp*2]
            : __floats2half2_rn(0.f, 0.f);
    }
    __syncthreads();
    #pragma unroll
    for (int k = 0; k < 8; k++){
        int o = tid + k*256;
        int tl = o >> 6, cp = o & 63;
        float2 acc = __half22float2(bias[cp]);
        #pragma unroll
        for (int j = 0; j < 7; j++){
            float2 wv = __half22float2(w[j][cp]);
            float2 sv = __half22float2(s[tl+j][cp]);
            acc.x += wv.x*sv.x; acc.y += wv.y*sv.y;
        }
        *(__half2*)&g_xch[(size_t)(b*SEQLEN + t0 + tl)*CONVD + ch0 + cp*2]
            = __floats2half2_rn(siluf(acc.x), siluf(acc.y));
    }
}

// ---------------- 5) dt softplus + per-chunk cumsum fused ----------------
__global__ void cumsum_kernel(const float* __restrict__ A_log,
                              const float* __restrict__ dt_bias){
    int bid = blockIdx.x;            // ((bb*NH)+h)*NC + c
    int c = bid % NC;
    int h = (bid / NC) % NH;
    int bb = bid / (NC*NH);
    int b = bb & 1;
    bool rev = bb >= 2;
    int tid = threadIdx.x;
    float a = -expf(A_log[h]);
    int t = c*CHUNK_T + tid;
    int tg = rev ? (SEQLEN-1-t) : t;
    int col = (DIP - 2*NH) + (rev ? NH + h : h);
    float raw = __half2float(g_zxh[(size_t)(b*SEQLEN + tg)*DIP + col]);
    float dtv = softplusf(raw + dt_bias[h]);
    g_dt[(size_t)(bb*SEQLEN + t)*NH + h] = dtv;
    float v = dtv * a;
    __shared__ float s[CHUNK_T];
    s[tid] = v; __syncthreads();
    for (int off = 1; off < CHUNK_T; off <<= 1){
        float add = (tid >= off) ? s[tid-off] : 0.f;
        __syncthreads();
        s[tid] += add;
        __syncthreads();
    }
    g_acum[(size_t)bid*CHUNK_T + tid] = s[tid];
    if (tid == CHUNK_T-1) g_csum[bid] = s[tid];
}

// ---------------- 6) chunk states (fp16 mma + ldmatrix) ----------------
#define SMH 88
__global__ void states_kernel(){
    int bid = blockIdx.x;            // (bb*NC+c)*NH + h
    int h = bid % NH;
    int c = (bid / NH) % NC;
    int bb = bid / (NH*NC);
    int b = bb & 1;
    bool rev = bb >= 2;
    int tid = threadIdx.x;
    int lane = tid & 31, warp = tid >> 5;
    int wm = warp >> 2, wn = warp & 3;
    int gid = lane >> 2, qid = lane & 3;
    const int rowsel = lane & 15;
    const int koffA  = (lane >> 4) * 8;
    const int nsel   = (lane & 7) + ((lane >> 4) * 8);
    const int koffB  = ((lane >> 3) & 1) * 8;

    __shared__ __half Ab[64*SMH];
    __shared__ __half Bb[64*SMH];
    __shared__ float dtl[64], decl[64];

    const float* ac = g_acum + ((size_t)(bb*NH + h)*NC + c)*CHUNK_T;
    float cs = g_csum[(bb*NH + h)*NC + c];

    float acc[2][2][4];
    #pragma unroll
    for (int i=0;i<2;i++)
        #pragma unroll
        for (int j=0;j<2;j++)
            #pragma unroll
            for (int r=0;r<4;r++) acc[i][j][r]=0.f;

    for (int ltile = 0; ltile < 4; ltile++){
        if (tid < 64){
            int lc2 = ltile*64 + tid;
            int tgl = c*CHUNK_T + lc2;
            dtl[tid] = g_dt[(size_t)(bb*SEQLEN + tgl)*NH + h];
            decl[tid] = expf(cs - ac[lc2]);
        }
        __syncthreads();
        for (int idx = tid; idx < 64*64; idx += 256){
            int l = idx >> 6, q = idx & 63;
            int tgl = c*CHUNK_T + ltile*64 + l;
            int trow = rev ? (SEQLEN-1 - tgl) : tgl;
            size_t roff = (size_t)(b*SEQLEN + trow)*CONVD;
            float xv = __half2float(g_xch[roff + h*HD + q]);
            float bv = __half2float(g_xch[roff + DI + q]);
            Ab[q*SMH + l] = __float2half(xv * dtl[l]);
            Bb[q*SMH + l] = __float2half(bv * decl[l]);
        }
        __syncthreads();
        #pragma unroll
        for (int ks = 0; ks < 64; ks += 16){
            unsigned a[2][4], bf[2][2];
            #pragma unroll
            for (int i=0;i<2;i++)
                ldsm4(a[i], Ab + (wm*32 + i*16 + rowsel)*SMH + ks + koffA);
            {
                unsigned t0[4];
                ldsm4(t0, Bb + (wn*16 + nsel)*SMH + ks + koffB);
                bf[0][0]=t0[0]; bf[0][1]=t0[1]; bf[1][0]=t0[2]; bf[1][1]=t0[3];
            }
            #pragma unroll
            for (int i=0;i<2;i++)
                #pragma unroll
                for (int j=0;j<2;j++) MMA_F16(acc[i][j], a[i], bf[j]);
        }
        __syncthreads();
    }
    float* sp = g_states + (size_t)bid*(HD*DS);
    #pragma unroll
    for (int i=0;i<2;i++){
        int p = wm*32 + i*16 + gid;
        #pragma unroll
        for (int j=0;j<2;j++){
            int n = wn*16 + j*8 + 2*qid;
            sp[p*DS + n]     = acc[i][j][0];
            sp[p*DS + n + 1] = acc[i][j][1];
            sp[(p+8)*DS + n]     = acc[i][j][2];
            sp[(p+8)*DS + n + 1] = acc[i][j][3];
        }
    }
}

// ---------------- 7) inter-chunk scan ----------------
__global__ void prevscan_kernel(){
    int bh = blockIdx.x;
    int bb = bh / NH, h = bh % NH;
    int tid = threadIdx.x;
    float run[16];
    #pragma unroll
    for (int k = 0; k < 16; k++) run[k] = 0.f;
    for (int c = 0; c < NC; c++){
        size_t off = ((size_t)(bb*NC + c)*NH + h)*(HD*DS);
        float e = expf(g_csum[bh*NC + c]);
        #pragma unroll
        for (int k = 0; k < 16; k++){
            int idx = k*256 + tid;
            g_prevh[off + idx] = __float2half(run[k]);
            run[k] = run[k]*e + g_states[off + idx];
        }
    }
}

// ---------------- 8) Y = Y_diag + Y_off (fp16 mma + ldmatrix) --------------
__global__ void ydiag_kernel(){
    int bid = blockIdx.x;            // ((bb*NC+c)*NH+h)*4 + lt
    int lt = bid & 3;
    int h  = (bid >> 2) % NH;
    int c  = (bid / (4*NH)) % NC;
    int bb = bid / (4*NH*NC);
    int b = bb & 1;
    bool rev = bb >= 2;
    int tid = threadIdx.x;
    int lane = tid & 31, warp = tid >> 5;
    int wm = warp >> 2, wn = warp & 3;
    int gid = lane >> 2, qid = lane & 3;
    const int rowsel = lane & 15;
    const int koffA  = (lane >> 4) * 8;
    const int nsel   = (lane & 7) + ((lane >> 4) * 8);
    const int koffB  = ((lane >> 3) & 1) * 8;

    __shared__ __half Ab[64*SMH];
    __shared__ __half Bb[64*SMH];
    __shared__ float acl[64], eacl[64], acs[64], dts[64];

    const float* ac = g_acum + ((size_t)(bb*NH + h)*NC + c)*CHUNK_T;

    if (tid < 64){
        float v = ac[lt*64 + tid];
        acl[tid] = v;
        eacl[tid] = expf(v);
    }
    __syncthreads();

    float acc[2][2][4];
    #pragma unroll
    for (int i=0;i<2;i++)
        #pragma unroll
        for (int j=0;j<2;j++)
            #pragma unroll
            for (int r=0;r<4;r++) acc[i][j][r]=0.f;

    // ---- Y_off
    {
        size_t poff = ((size_t)(bb*NC + c)*NH + h)*(HD*DS);
        for (int i2 = tid; i2 < 2048; i2 += 256){
            int l = i2 >> 5, c2 = (i2 & 31) * 2;
            int tgl = c*CHUNK_T + lt*64 + l;
            int trl = rev ? (SEQLEN-1 - tgl) : tgl;
            __half2 cv = *(const __half2*)&g_xch[(size_t)(b*SEQLEN + trl)*CONVD + DI + DS + c2];
            float2 cf = __half22float2(cv);
            float e = eacl[l];
            *(__half2*)&Ab[l*SMH + c2] = __floats2half2_rn(cf.x*e, cf.y*e);
            *(__half2*)&Bb[l*SMH + c2] = *(const __half2*)&g_prevh[poff + l*64 + c2];
        }
        __syncthreads();
        #pragma unroll
        for (int ks = 0; ks < 64; ks += 16){
            unsigned a[2][4], bf[2][2];
            #pragma unroll
            for (int i=0;i<2;i++)
                ldsm4(a[i], Ab + (wm*32 + i*16 + rowsel)*SMH + ks + koffA);
            {
                unsigned t0[4];
                ldsm4(t0, Bb + (wn*16 + nsel)*SMH + ks + koffB);
                bf[0][0]=t0[0]; bf[0][1]=t0[1]; bf[1][0]=t0[2]; bf[1][1]=t0[3];
            }
            #pragma unroll
            for (int i=0;i<2;i++)
                #pragma unroll
                for (int j=0;j<2;j++) MMA_F16(acc[i][j], a[i], bf[j]);
        }
        __syncthreads();
    }

    // ---- Y_diag over s-tiles <= lt
    for (int st = 0; st <= lt; st++){
        if (tid < 64){
            acs[tid] = ac[st*64 + tid];
            dts[tid] = g_dt[(size_t)(bb*SEQLEN + c*CHUNK_T + st*64 + tid)*NH + h];
        }
        for (int i2 = tid; i2 < 2048; i2 += 256){
            int r = i2 >> 5, c2 = (i2 & 31) * 2;
            int tgl = c*CHUNK_T + lt*64 + r;
            int trl = rev ? (SEQLEN-1 - tgl) : tgl;
            *(__half2*)&Ab[r*SMH + c2] =
                *(const __half2*)&g_xch[(size_t)(b*SEQLEN + trl)*CONVD + DI + DS + c2];
            int tgs = c*CHUNK_T + st*64 + r;
            int trs = rev ? (SEQLEN-1 - tgs) : tgs;
            *(__half2*)&Bb[r*SMH + c2] =
                *(const __half2*)&g_xch[(size_t)(b*SEQLEN + trs)*CONVD + DI + c2];
        }
        __syncthreads();
        float g[2][2][4];
        #pragma unroll
        for (int i=0;i<2;i++)
            #pragma unroll
            for (int j=0;j<2;j++)
                #pragma unroll
                for (int r=0;r<4;r++) g[i][j][r]=0.f;
        #pragma unroll
        for (int ks = 0; ks < 64; ks += 16){
            unsigned a[2][4], bf[2][2];
            #pragma unroll
            for (int i=0;i<2;i++)
                ldsm4(a[i], Ab + (wm*32 + i*16 + rowsel)*SMH + ks + koffA);
            {
                unsigned t0[4];
                ldsm4(t0, Bb + (wn*16 + nsel)*SMH + ks + koffB);
                bf[0][0]=t0[0]; bf[0][1]=t0[1]; bf[1][0]=t0[2]; bf[1][1]=t0[3];
            }
            #pragma unroll
            for (int i=0;i<2;i++)
                #pragma unroll
                for (int j=0;j<2;j++) MMA_F16(g[i][j], a[i], bf[j]);
        }
        __syncthreads();
        bool diag = (st == lt);
        #pragma unroll
        for (int i=0;i<2;i++){
            int l0 = wm*32 + i*16 + gid;
            #pragma unroll
            for (int j=0;j<2;j++){
                int s0 = wn*16 + j*8 + 2*qid;
                float al0 = acl[l0], al1 = acl[l0+8];
                float w00 = (diag && s0   > l0) ? 0.f : expf(al0 - acs[s0]);
                float w01 = (diag && s0+1 > l0) ? 0.f : expf(al0 - acs[s0+1]);
                float w10 = (diag && s0   > l0+8) ? 0.f : expf(al1 - acs[s0]);
                float w11 = (diag && s0+1 > l0+8) ? 0.f : expf(al1 - acs[s0+1]);
                Ab[l0*SMH + s0]       = __float2half(g[i][j][0]*w00);
                Ab[l0*SMH + s0+1]     = __float2half(g[i][j][1]*w01);
                Ab[(l0+8)*SMH + s0]   = __float2half(g[i][j][2]*w10);
                Ab[(l0+8)*SMH + s0+1] = __float2half(g[i][j][3]*w11);
            }
        }
        for (int idx = tid; idx < 64*64; idx += 256){
            int s = idx >> 6, p = idx & 63;
            int tgs = c*CHUNK_T + st*64 + s;
            int trs = rev ? (SEQLEN-1 - tgs) : tgs;
            float xv = __half2float(g_xch[(size_t)(b*SEQLEN + trs)*CONVD + h*HD + p]);
            Bb[p*SMH + s] = __float2half(xv * dts[s]);
        }
        __syncthreads();
        #pragma unroll
        for (int ks = 0; ks < 64; ks += 16){
            unsigned a[2][4], bf[2][2];
            #pragma unroll
            for (int i=0;i<2;i++)
                ldsm4(a[i], Ab + (wm*32 + i*16 + rowsel)*SMH + ks + koffA);
            {
                unsigned t0[4];
                ldsm4(t0, Bb + (wn*16 + nsel)*SMH + ks + koffB);
                bf[0][0]=t0[0]; bf[0][1]=t0[1]; bf[1][0]=t0[2]; bf[1][1]=t0[3];
            }
            #pragma unroll
            for (int i=0;i<2;i++)
                #pragma unroll
                for (int j=0;j<2;j++) MMA_F16(acc[i][j], a[i], bf[j]);
        }
        __syncthreads();
    }

    #pragma unroll
    for (int i=0;i<2;i++){
        int l = wm*32 + i*16 + gid;
        int tg0 = c*CHUNK_T + lt*64 + l;
        #pragma unroll
        for (int j=0;j<2;j++){
            int pc = h*HD + wn*16 + j*8 + 2*qid;
            size_t o0 = (size_t)(bb*SEQLEN + tg0)*DI + pc;
            size_t o1 = (size_t)(bb*SEQLEN + tg0 + 8)*DI + pc;
            *(__half2*)&g_yssdh[o0] = __floats2half2_rn(acc[i][j][0], acc[i][j][1]);
            *(__half2*)&g_yssdh[o1] = __floats2half2_rn(acc[i][j][2], acc[i][j][3]);
        }
    }
}

// ---------------- 9) fc_D (fp16 inputs) ----------------
__global__ void fcd_kernel(const float* __restrict__ fw){
    __shared__ float ws[NH][132];
    int r0 = blockIdx.x * 64;
    int tid = threadIdx.x;
    int rl = tid >> 2;
    int lj = tid & 3;
    float acc[6] = {0.f,0.f,0.f,0.f,0.f,0.f};
    for (int k0 = 0; k0 < DI; k0 += 128){
        for (int i = tid; i < NH*128; i += 256)
            ws[i>>7][i&127] = fw[(size_t)(i>>7)*DI + k0 + (i&127)];
        __syncthreads();
        const __half2* xr = (const __half2*)&g_xch[(size_t)(r0+rl)*CONVD + k0];
        #pragma unroll 16
        for (int kk = 0; kk < 64; kk += 2){
            float2 x0 = __half22float2(xr[kk]);
            float2 x1 = __half22float2(xr[kk+1]);
            #pragma unroll
            for (int hh = 0; hh < 6; hh++){
                int h = lj*6 + hh;
                acc[hh] += x0.x*ws[h][kk*2] + x0.y*ws[h][kk*2+1]
                         + x1.x*ws[h][kk*2+2] + x1.y*ws[h][kk*2+3];
            }
        }
        __syncthreads();
    }
    #pragma unroll
    for (int hh = 0; hh < 6; hh++)
        g_dterm[(size_t)(r0+rl)*NH + lj*6 + hh] = acc[hh];
}

// ---------------- 10) combine + gate + RMSNorm (half2 vectorized) ----------
__global__ void combine_kernel(const float* __restrict__ Dv,
                               const float* __restrict__ rms_w){
    __shared__ float ybuf[DI];
    __shared__ float red[8];
    int bl = blockIdx.x;
    int b = bl / SEQLEN, t = bl % SEQLEN;
    int tid = threadIdx.x;
    float ss = 0.f;
    for (int d = tid*2; d < DI; d += 512){
        float2 yf = make_float2(0.f, 0.f), yb = make_float2(0.f, 0.f);
        if (t > 0)
            yf = __half22float2(*(const __half2*)&g_yssdh[(size_t)(b*SEQLEN + t - 1)*DI + d]);
        if (t <= SEQLEN-2)
            yb = __half22float2(*(const __half2*)&g_yssdh[(size_t)((2+b)*SEQLEN + (SEQLEN-2 - t))*DI + d]);
        float2 xo = __half22float2(*(const __half2*)&g_xch[(size_t)bl*CONVD + d]);
        float2 z  = __half22float2(*(const __half2*)&g_zxh[(size_t)bl*DIP + d]);
        int h = d >> 6;
        float dterm = g_dterm[(size_t)bl*NH + h] + Dv[h];
        float y0 = (yf.x + yb.x + xo.x*dterm) * siluf(z.x);
        float y1 = (yf.y + yb.y + xo.y*dterm) * siluf(z.y);
        ybuf[d] = y0; ybuf[d+1] = y1;
        ss += y0*y0 + y1*y1;
    }
    float tot = blockReduce256(ss, red);
    float inv = rsqrtf(tot/DI + EPSV);
    __syncthreads();
    for (int d = tid*2; d < DI; d += 512){
        float2 rw = *(const float2*)&rms_w[d];
        *(__half2*)&g_ynh[(size_t)bl*DI + d] =
            __floats2half2_rn(ybuf[d]*inv*rw.x, ybuf[d+1]*inv*rw.y);
    }
}

// ---------------- launch ----------------
extern "C" void kernel_launch(void* const* d_in, const int* in_sizes, int n_in,
                              void* d_out, int out_size){
    const float* x          = (const float*)d_in[0];
    const float* ln_w       = (const float*)d_in[1];
    const float* ln_b       = (const float*)d_in[2];
    const float* in_proj_w  = (const float*)d_in[3];
    const float* conv_w     = (const float*)d_in[4];
    const float* conv_b     = (const float*)d_in[5];
    const float* dt_bias    = (const float*)d_in[6];
    const float* A_log      = (const float*)d_in[7];
    const float* Dv         = (const float*)d_in[8];
    const float* fc_D_w     = (const float*)d_in[9];
    const float* rms_w      = (const float*)d_in[10];
    const float* out_proj_w = (const float*)d_in[11];
    float* out = (float*)d_out;

    __half *uh, *ynh, *wah, *woh, *zxh;
    cudaGetSymbolAddress((void**)&uh,  g_uh);
    cudaGetSymbolAddress((void**)&ynh, g_ynh);
    cudaGetSymbolAddress((void**)&wah, g_wah);
    cudaGetSymbolAddress((void**)&woh, g_woh);
    cudaGetSymbolAddress((void**)&zxh, g_zxh);

    static bool attr_set = false;
    const int gsmem = GSTH*2*128*SMSH*(int)sizeof(__half);   // 81920 B
    if (!attr_set){
        cudaFuncSetAttribute(gemm_h, cudaFuncAttributeMaxDynamicSharedMemorySize, gsmem);
        attr_set = true;
    }

    wconv_kernel<<<(DIP*DM + 255)/256, 256>>>(in_proj_w, out_proj_w);
    ln_kernel<<<BL, 256>>>(x, ln_w, ln_b);

    // in_proj -> fp16 zx
    gemm_h<<<dim3((DIP+127)/128, BL/128), 256, gsmem>>>(uh, DM, wah, DM,
        nullptr, nullptr, zxh, DIP, BL, DIP, DM);

    conv_kernel<<<dim3(CONVD/128, SEQLEN/CTS, BATCH), 256>>>(conv_w, conv_b);
    cumsum_kernel<<<NBB*NH*NC, 256>>>(A_log, dt_bias);
    states_kernel<<<NBB*NC*NH, 256>>>();
    prevscan_kernel<<<NBB*NH, 256>>>();
    ydiag_kernel<<<NBB*NC*NH*4, 256>>>();
    fcd_kernel<<<BL/64, 256>>>(fc_D_w);
    combine_kernel<<<BL, 256>>>(Dv, rms_w);

    // out_proj + residual -> fp32 out
    gemm_h<<<dim3(DM/128, BL/128), 256, gsmem>>>(ynh, DI, woh, DI,
        x, out, nullptr, DM, BL, DM, DI);
}